// round 2
// baseline (speedup 1.0000x reference)
#include <cuda_runtime.h>
#include <math.h>

#define BB 8
#define TT 2048
#define DM 1024
#define NS 512
#define NPROJ 584
#define NPAD 640
#define NHW 520
#define ROWS (BB*TT)   // 16384

// ---------------- scratch (static device globals; no dynamic alloc) ----------------
__device__ float g_P[ROWS * NPAD];      // projection output: cols 0..511 = Bx, 512..583 = raw (diag|off|alpha)
__device__ float g_C[ROWS * 64];        // C matrices (b,t,8,8)
__device__ float g_alpha[ROWS * 8];     // softmax alpha
__device__ float g_hw[ROWS * NHW];      // [h*alpha (512) | alpha (8)] per (b,t)
__device__ float g_Wpack[DM * NPAD];    // packed projection weights (1024 x 640)
__device__ float g_bpack[NPAD];         // packed biases
__device__ float g_W2[NHW * DM];        // packed [Wc_flat; bc] (520 x 1024)
__device__ float g_A[NS];               // A_diag

// ---------------- packing kernels ----------------
__global__ void pack1_kernel(const float* __restrict__ Wb, const float* __restrict__ Wdiag,
                             const float* __restrict__ Woff, const float* __restrict__ Walpha) {
    int idx = blockIdx.x * blockDim.x + threadIdx.x;
    if (idx >= DM * NPAD) return;
    int r = idx / NPAD, c = idx - r * NPAD;
    float v;
    if (c < 512)       v = Wb[r * NS + c];
    else if (c < 520)  v = Wdiag[r * 8 + (c - 512)];
    else if (c < 576)  v = Woff[r * 56 + (c - 520)];
    else if (c < 584)  v = Walpha[r * 8 + (c - 576)];
    else               v = 0.0f;
    g_Wpack[idx] = v;
}

__global__ void pack2_kernel(const float* __restrict__ Wc, const float* __restrict__ bc) {
    int idx = blockIdx.x * blockDim.x + threadIdx.x;
    if (idx >= NHW * DM) return;
    int r = idx >> 10, c = idx & 1023;
    g_W2[idx] = (r < 512) ? Wc[idx] : bc[(r - 512) * DM + c];
}

__global__ void misc_kernel(const float* __restrict__ bb, const float* __restrict__ bdiag,
                            const float* __restrict__ boff, const float* __restrict__ balpha,
                            const float* __restrict__ log_lambda) {
    int tid = threadIdx.x;
    if (tid < NS) {
        int k = tid >> 6;
        double dt = 1e-3 * exp((double)k * log(1000.0) / 7.0);
        double ll = (double)log_lambda[tid];
        double sp = log1p(exp(ll));
        g_A[tid] = (float)exp(-dt * sp);
    }
    if (tid < NPAD) {
        float v;
        if (tid < 512)       v = bb[tid];
        else if (tid < 520)  v = bdiag[tid - 512];
        else if (tid < 576)  v = boff[tid - 520];
        else if (tid < 584)  v = balpha[tid - 576];
        else                 v = 0.0f;
        g_bpack[tid] = v;
    }
}

// ---------------- fp32 SGEMM: C = A(MxK) * B(KxN) + bias, 128x128x8 tiles, double-buffered ----------------
__global__ void __launch_bounds__(256, 1) sgemm128(
    const float* __restrict__ A, const float* __restrict__ B,
    const float* __restrict__ bias, float* __restrict__ Cout,
    int M, int N, int K)
{
    __shared__ float As[2][8][128];
    __shared__ float Bs[2][8][128];
    float acc[8][8];
#pragma unroll
    for (int i = 0; i < 8; i++)
#pragma unroll
        for (int j = 0; j < 8; j++) acc[i][j] = 0.0f;

    const int tid  = threadIdx.x;
    const int tx   = tid & 15;          // 0..15  (N direction)
    const int ty   = tid >> 4;          // 0..15  (M direction)
    const int arow = tid >> 1;          // 0..127
    const int acol = (tid & 1) << 2;    // 0 or 4
    const int brow = tid >> 5;          // 0..7
    const int bcol = (tid & 31) << 2;   // 0..124

    const float* Ap = A + (size_t)(blockIdx.y * 128 + arow) * K + acol;
    const float* Bp = B + (size_t)brow * N + blockIdx.x * 128 + bcol;

    float4 av = *(const float4*)Ap;
    float4 bv = *(const float4*)Bp;
    As[0][acol + 0][arow] = av.x; As[0][acol + 1][arow] = av.y;
    As[0][acol + 2][arow] = av.z; As[0][acol + 3][arow] = av.w;
    *(float4*)&Bs[0][brow][bcol] = bv;
    __syncthreads();

    const int nk = K >> 3;
    for (int kt = 0; kt < nk; ++kt) {
        const int cur = kt & 1;
        if (kt + 1 < nk) {
            av = *(const float4*)(Ap + (kt + 1) * 8);
            bv = *(const float4*)(Bp + (size_t)(kt + 1) * 8 * N);
        }
#pragma unroll
        for (int kk = 0; kk < 8; ++kk) {
            float af[8], bf[8];
            *(float4*)&af[0] = *(const float4*)&As[cur][kk][ty * 8];
            *(float4*)&af[4] = *(const float4*)&As[cur][kk][ty * 8 + 4];
            *(float4*)&bf[0] = *(const float4*)&Bs[cur][kk][tx * 8];
            *(float4*)&bf[4] = *(const float4*)&Bs[cur][kk][tx * 8 + 4];
#pragma unroll
            for (int i = 0; i < 8; i++)
#pragma unroll
                for (int j = 0; j < 8; j++)
                    acc[i][j] = fmaf(af[i], bf[j], acc[i][j]);
        }
        if (kt + 1 < nk) {
            const int nxt = cur ^ 1;
            As[nxt][acol + 0][arow] = av.x; As[nxt][acol + 1][arow] = av.y;
            As[nxt][acol + 2][arow] = av.z; As[nxt][acol + 3][arow] = av.w;
            *(float4*)&Bs[nxt][brow][bcol] = bv;
            __syncthreads();
        }
    }

    float bfrag[8];
    const int col0 = blockIdx.x * 128 + tx * 8;
#pragma unroll
    for (int j = 0; j < 8; j++) bfrag[j] = bias ? bias[col0 + j] : 0.0f;
#pragma unroll
    for (int i = 0; i < 8; i++) {
        size_t row = (size_t)(blockIdx.y * 128 + ty * 8 + i);
        float4 o0 = make_float4(acc[i][0] + bfrag[0], acc[i][1] + bfrag[1],
                                acc[i][2] + bfrag[2], acc[i][3] + bfrag[3]);
        float4 o1 = make_float4(acc[i][4] + bfrag[4], acc[i][5] + bfrag[5],
                                acc[i][6] + bfrag[6], acc[i][7] + bfrag[7]);
        *(float4*)&Cout[row * N + col0]     = o0;
        *(float4*)&Cout[row * N + col0 + 4] = o1;
    }
}

// ---------------- activations: sigmoid / softplus -> C matrix, softmax -> alpha ----------------
__global__ void __launch_bounds__(256) act_kernel(void) {
    __shared__ float s[64 * 72];
    const int row0 = blockIdx.x * 64;
    const int tid = threadIdx.x;
    for (int i = tid; i < 64 * 72; i += 256) {
        int r = i / 72, c = i - r * 72;
        s[i] = g_P[(size_t)(row0 + r) * NPAD + 512 + c];
    }
    __syncthreads();
    if (tid < 64) {
        const int row = row0 + tid;
        const float* v = &s[tid * 72];
        float dg[8];
#pragma unroll
        for (int i = 0; i < 8; i++) dg[i] = 1.0f / (1.0f + expf(-v[i]));
        float Cm[64];
        int m = 0;
#pragma unroll
        for (int i = 0; i < 8; i++) {
#pragma unroll
            for (int j = 0; j < 8; j++) {
                if (i == j) {
                    Cm[i * 8 + j] = dg[i];
                } else {
                    float x = v[8 + m];
                    float sp = (x > 15.0f) ? x : log1pf(expf(x));
                    Cm[i * 8 + j] = -sp;
                    m++;
                }
            }
        }
#pragma unroll
        for (int q = 0; q < 64; q++) g_C[(size_t)row * 64 + q] = Cm[q];
        // softmax over the 8 alpha logits
        float a[8], mx = v[64];
#pragma unroll
        for (int i = 1; i < 8; i++) mx = fmaxf(mx, v[64 + i]);
        float sum = 0.0f;
#pragma unroll
        for (int i = 0; i < 8; i++) { a[i] = expf(v[64 + i] - mx); sum += a[i]; }
        float inv = 1.0f / sum;
#pragma unroll
        for (int k = 0; k < 8; k++) {
            float al = a[k] * inv;
            g_alpha[(size_t)row * 8 + k] = al;
            g_hw[(size_t)row * NHW + 512 + k] = al;
        }
    }
}

// ---------------- sequential scan: h_t = A*h_{t-1} + U (C_t V^T h_{t-1}) + bx_t ----------------
__global__ void __launch_bounds__(512, 1) scan_kernel(const float* __restrict__ Uw,
                                                      const float* __restrict__ Vw) {
    __shared__ float h_s[NS];
    __shared__ float part_s[128];   // 16 warps x 8 partial Vh
    __shared__ float g_s[8];        // coupling vector C_t (V^T h_{t-1})
    __shared__ float cbuf[2][64];   // double-buffered C_t stage

    const int b = blockIdx.x;
    const int n = threadIdx.x;                 // state index (phase A ownership)
    const int kq = n & 7, grp = n >> 3;        // phase R ownership: k=kq over states grp*8..grp*8+7

    float h = 0.0f;
    const float An = g_A[n];
    float Un[8], Vv[8];
#pragma unroll
    for (int k = 0; k < 8; k++) Un[k] = Uw[n * 8 + k];
#pragma unroll
    for (int j = 0; j < 8; j++) Vv[j] = Vw[(grp * 8 + j) * 8 + kq];
    if (n < 8) g_s[n] = 0.0f;

    const float* bxp = g_P + (size_t)b * TT * NPAD + n;
    const float* alp = g_alpha + (size_t)b * TT * 8 + (n >> 6);
    float* hwp = g_hw + (size_t)b * TT * NHW + n;
    const bool cload = (n >= 64 && n < 128);
    const float* cp = cload ? (g_C + (size_t)b * TT * 64 + (n - 64)) : g_C;

    // software prefetch pipeline (2 steps ahead)
    float bx0 = bxp[0];
    float bx1 = bxp[NPAD];
    float av0 = alp[0];
    float av1 = alp[8];
    float creg = cload ? cp[64] : 0.0f;        // C at t=1 (C_0 is never used: h_{-1}=0)
    __syncthreads();

    for (int t = 0; t < TT; ++t) {
        // ---- Phase A: update h, publish h to smem, emit h*alpha ----
        float coup = 0.0f;
#pragma unroll
        for (int k = 0; k < 8; k++) coup = fmaf(Un[k], g_s[k], coup);
        h = fmaf(An, h, coup + bx0);
        h_s[n] = h;
        hwp[(size_t)t * NHW] = h * av0;

        bx0 = bx1; av0 = av1;
        const int tp = (t + 2 < TT) ? (t + 2) : (TT - 1);
        bx1 = bxp[(size_t)tp * NPAD];
        av1 = alp[(size_t)tp * 8];
        if (cload) {
            cbuf[(t + 1) & 1][n - 64] = creg;   // stage C_{t+1} for this step's phase C
            creg = cp[(size_t)tp * 64];          // prefetch C_{t+2}
        }
        __syncthreads();

        // ---- Phase R: per-(k,group) partial of V^T h, warp-level combine ----
        float pv = 0.0f;
        const float* hb = &h_s[grp * 8];
#pragma unroll
        for (int j = 0; j < 8; j++) pv = fmaf(Vv[j], hb[j], pv);
        pv += __shfl_xor_sync(0xffffffffu, pv, 8);
        pv += __shfl_xor_sync(0xffffffffu, pv, 16);
        if ((n & 31) < 8) part_s[(n >> 5) * 8 + (n & 7)] = pv;
        __syncthreads();

        // ---- Phase C: warp 0 finishes reduce and computes g = C_{t+1} * Vh ----
        if (n < 32) {
            float sV = part_s[n] + part_s[n + 32] + part_s[n + 64] + part_s[n + 96];
            sV += __shfl_xor_sync(0xffffffffu, sV, 8);
            sV += __shfl_xor_sync(0xffffffffu, sV, 16);
            float vh[8];
#pragma unroll
            for (int j = 0; j < 8; j++) vh[j] = __shfl_sync(0xffffffffu, sV, j);
            if (n < 8) {
                const float* crow = &cbuf[(t + 1) & 1][n * 8];
                float g = 0.0f;
#pragma unroll
                for (int j = 0; j < 8; j++) g = fmaf(crow[j], vh[j], g);
                g_s[n] = g;
            }
        }
        __syncthreads();
    }
}

// ---------------- launch ----------------
extern "C" void kernel_launch(void* const* d_in, const int* in_sizes, int n_in,
                              void* d_out, int out_size) {
    const float* x      = (const float*)d_in[0];
    const float* Wb     = (const float*)d_in[1];
    const float* bb     = (const float*)d_in[2];
    const float* Wdiag  = (const float*)d_in[3];
    const float* bdiag  = (const float*)d_in[4];
    const float* Woff   = (const float*)d_in[5];
    const float* boff   = (const float*)d_in[6];
    const float* Walpha = (const float*)d_in[7];
    const float* balpha = (const float*)d_in[8];
    const float* Wc     = (const float*)d_in[9];
    const float* bc     = (const float*)d_in[10];
    const float* ll     = (const float*)d_in[11];
    const float* U      = (const float*)d_in[12];
    const float* V      = (const float*)d_in[13];
    float* out = (float*)d_out;

    float *pP, *pWpack, *pbpack, *pW2, *phw;
    cudaGetSymbolAddress((void**)&pP,     g_P);
    cudaGetSymbolAddress((void**)&pWpack, g_Wpack);
    cudaGetSymbolAddress((void**)&pbpack, g_bpack);
    cudaGetSymbolAddress((void**)&pW2,    g_W2);
    cudaGetSymbolAddress((void**)&phw,    g_hw);

    pack1_kernel<<<(DM * NPAD + 255) / 256, 256>>>(Wb, Wdiag, Woff, Walpha);
    pack2_kernel<<<(NHW * DM + 255) / 256, 256>>>(Wc, bc);
    misc_kernel<<<1, 1024>>>(bb, bdiag, boff, balpha, ll);

    // GEMM1: P = x @ Wpack + bpack   (16384 x 640 x 1024)
    sgemm128<<<dim3(NPAD / 128, ROWS / 128), 256>>>(x, pWpack, pbpack, pP, ROWS, NPAD, DM);

    act_kernel<<<ROWS / 64, 256>>>();

    scan_kernel<<<BB, 512>>>(U, V);

    // GEMM2: out = hw @ W2           (16384 x 1024 x 520)
    sgemm128<<<dim3(DM / 128, ROWS / 128), 256>>>(phw, pW2, nullptr, out, ROWS, DM, NHW);
}

// round 3
// speedup vs baseline: 1.0785x; 1.0785x over previous
#include <cuda_runtime.h>
#include <math.h>

#define BB 8
#define TT 2048
#define DM 1024
#define NS 512
#define NPAD 640
#define NHW 520
#define ROWS (BB*TT)   // 16384

// ---------------- scratch (static device globals; no dynamic alloc) ----------------
__device__ float g_P[ROWS * NPAD];      // projection output: cols 0..511 = Bx, 512..583 = raw (diag|off|alpha)
__device__ float g_C[ROWS * 64];        // C matrices (b,t,8,8)
__device__ float g_alpha[ROWS * 8];     // softmax alpha
__device__ float g_hw[ROWS * NHW];      // [h*alpha (512) | alpha (8)] per (b,t)
__device__ float g_Wpack[DM * NPAD];    // packed projection weights (1024 x 640)
__device__ float g_bpack[NPAD];         // packed biases
__device__ float g_W2[NHW * DM];        // packed [Wc_flat; bc] (520 x 1024)
__device__ float g_A[NS];               // A_diag

// ---------------- packing kernels ----------------
__global__ void pack1_kernel(const float* __restrict__ Wb, const float* __restrict__ Wdiag,
                             const float* __restrict__ Woff, const float* __restrict__ Walpha) {
    int idx = blockIdx.x * blockDim.x + threadIdx.x;
    if (idx >= DM * NPAD) return;
    int r = idx / NPAD, c = idx - r * NPAD;
    float v;
    if (c < 512)       v = Wb[r * NS + c];
    else if (c < 520)  v = Wdiag[r * 8 + (c - 512)];
    else if (c < 576)  v = Woff[r * 56 + (c - 520)];
    else if (c < 584)  v = Walpha[r * 8 + (c - 576)];
    else               v = 0.0f;
    g_Wpack[idx] = v;
}

__global__ void pack2_kernel(const float* __restrict__ Wc, const float* __restrict__ bc) {
    int idx = blockIdx.x * blockDim.x + threadIdx.x;
    if (idx >= NHW * DM) return;
    int r = idx >> 10, c = idx & 1023;
    g_W2[idx] = (r < 512) ? Wc[idx] : bc[(r - 512) * DM + c];
}

__global__ void misc_kernel(const float* __restrict__ bb, const float* __restrict__ bdiag,
                            const float* __restrict__ boff, const float* __restrict__ balpha,
                            const float* __restrict__ log_lambda) {
    int tid = threadIdx.x;
    if (tid < NS) {
        int k = tid >> 6;
        double dt = 1e-3 * exp((double)k * log(1000.0) / 7.0);
        double ll = (double)log_lambda[tid];
        double sp = log1p(exp(ll));
        g_A[tid] = (float)exp(-dt * sp);
    }
    if (tid < NPAD) {
        float v;
        if (tid < 512)       v = bb[tid];
        else if (tid < 520)  v = bdiag[tid - 512];
        else if (tid < 576)  v = boff[tid - 520];
        else if (tid < 584)  v = balpha[tid - 576];
        else                 v = 0.0f;
        g_bpack[tid] = v;
    }
}

// ---------------- fp32 SGEMM: C = A(MxK) * B(KxN) + bias, 128x128x8 tiles, double-buffered ----------------
__global__ void __launch_bounds__(256, 1) sgemm128(
    const float* __restrict__ A, const float* __restrict__ B,
    const float* __restrict__ bias, float* __restrict__ Cout,
    int M, int N, int K)
{
    __shared__ float As[2][8][128];
    __shared__ float Bs[2][8][128];
    float acc[8][8];
#pragma unroll
    for (int i = 0; i < 8; i++)
#pragma unroll
        for (int j = 0; j < 8; j++) acc[i][j] = 0.0f;

    const int tid  = threadIdx.x;
    const int tx   = tid & 15;          // 0..15  (N direction)
    const int ty   = tid >> 4;          // 0..15  (M direction)
    const int arow = tid >> 1;          // 0..127
    const int acol = (tid & 1) << 2;    // 0 or 4
    const int brow = tid >> 5;          // 0..7
    const int bcol = (tid & 31) << 2;   // 0..124

    const float* Ap = A + (size_t)(blockIdx.y * 128 + arow) * K + acol;
    const float* Bp = B + (size_t)brow * N + blockIdx.x * 128 + bcol;

    float4 av = *(const float4*)Ap;
    float4 bv = *(const float4*)Bp;
    As[0][acol + 0][arow] = av.x; As[0][acol + 1][arow] = av.y;
    As[0][acol + 2][arow] = av.z; As[0][acol + 3][arow] = av.w;
    *(float4*)&Bs[0][brow][bcol] = bv;
    __syncthreads();

    const int nk = K >> 3;
    for (int kt = 0; kt < nk; ++kt) {
        const int cur = kt & 1;
        if (kt + 1 < nk) {
            av = *(const float4*)(Ap + (kt + 1) * 8);
            bv = *(const float4*)(Bp + (size_t)(kt + 1) * 8 * N);
        }
#pragma unroll
        for (int kk = 0; kk < 8; ++kk) {
            float af[8], bf[8];
            *(float4*)&af[0] = *(const float4*)&As[cur][kk][ty * 8];
            *(float4*)&af[4] = *(const float4*)&As[cur][kk][ty * 8 + 4];
            *(float4*)&bf[0] = *(const float4*)&Bs[cur][kk][tx * 8];
            *(float4*)&bf[4] = *(const float4*)&Bs[cur][kk][tx * 8 + 4];
#pragma unroll
            for (int i = 0; i < 8; i++)
#pragma unroll
                for (int j = 0; j < 8; j++)
                    acc[i][j] = fmaf(af[i], bf[j], acc[i][j]);
        }
        if (kt + 1 < nk) {
            const int nxt = cur ^ 1;
            As[nxt][acol + 0][arow] = av.x; As[nxt][acol + 1][arow] = av.y;
            As[nxt][acol + 2][arow] = av.z; As[nxt][acol + 3][arow] = av.w;
            *(float4*)&Bs[nxt][brow][bcol] = bv;
            __syncthreads();
        }
    }

    float bfrag[8];
    const int col0 = blockIdx.x * 128 + tx * 8;
#pragma unroll
    for (int j = 0; j < 8; j++) bfrag[j] = bias ? bias[col0 + j] : 0.0f;
#pragma unroll
    for (int i = 0; i < 8; i++) {
        size_t row = (size_t)(blockIdx.y * 128 + ty * 8 + i);
        float4 o0 = make_float4(acc[i][0] + bfrag[0], acc[i][1] + bfrag[1],
                                acc[i][2] + bfrag[2], acc[i][3] + bfrag[3]);
        float4 o1 = make_float4(acc[i][4] + bfrag[4], acc[i][5] + bfrag[5],
                                acc[i][6] + bfrag[6], acc[i][7] + bfrag[7]);
        *(float4*)&Cout[row * N + col0]     = o0;
        *(float4*)&Cout[row * N + col0 + 4] = o1;
    }
}

// ---------------- activations: sigmoid / softplus -> C matrix, softmax -> alpha ----------------
__global__ void __launch_bounds__(256) act_kernel(void) {
    __shared__ float s[64 * 72];
    const int row0 = blockIdx.x * 64;
    const int tid = threadIdx.x;
    for (int i = tid; i < 64 * 72; i += 256) {
        int r = i / 72, c = i - r * 72;
        s[i] = g_P[(size_t)(row0 + r) * NPAD + 512 + c];
    }
    __syncthreads();
    if (tid < 64) {
        const int row = row0 + tid;
        const float* v = &s[tid * 72];
        float dg[8];
#pragma unroll
        for (int i = 0; i < 8; i++) dg[i] = 1.0f / (1.0f + expf(-v[i]));
        float Cm[64];
        int m = 0;
#pragma unroll
        for (int i = 0; i < 8; i++) {
#pragma unroll
            for (int j = 0; j < 8; j++) {
                if (i == j) {
                    Cm[i * 8 + j] = dg[i];
                } else {
                    float x = v[8 + m];
                    float sp = (x > 15.0f) ? x : log1pf(expf(x));
                    Cm[i * 8 + j] = -sp;
                    m++;
                }
            }
        }
#pragma unroll
        for (int q = 0; q < 64; q++) g_C[(size_t)row * 64 + q] = Cm[q];
        // softmax over the 8 alpha logits
        float a[8], mx = v[64];
#pragma unroll
        for (int i = 1; i < 8; i++) mx = fmaxf(mx, v[64 + i]);
        float sum = 0.0f;
#pragma unroll
        for (int i = 0; i < 8; i++) { a[i] = expf(v[64 + i] - mx); sum += a[i]; }
        float inv = 1.0f / sum;
#pragma unroll
        for (int k = 0; k < 8; k++) {
            float al = a[k] * inv;
            g_alpha[(size_t)row * 8 + k] = al;
            g_hw[(size_t)row * NHW + 512 + k] = al;
        }
    }
}

// ---------------- sequential scan: h_t = A*h_{t-1} + U (C_t V^T h_{t-1}) + bx_t ----------------
// One __syncthreads per step. Phase R reads only own-warp h (grp*8..grp*8+7 is inside
// the warp's 32-state range), so a __syncwarp suffices after publishing h. Per-warp Vh
// partials go to a k-major double-buffered staging array; after the single barrier,
// EVERY warp redundantly finishes the 16-warp reduce and computes g = C_{t+1}*vh,
// eliminating the warp0-serialized phase C of the previous version.
__global__ void __launch_bounds__(512, 1) scan_kernel(const float* __restrict__ Uw,
                                                      const float* __restrict__ Vw) {
    __shared__ __align__(16) float h_s[NS];
    __shared__ __align__(16) float part_s[2][128];   // [buf][k*16 + warp]
    __shared__ __align__(16) float cbuf[2][64];      // staged C_{t+1}

    const int b = blockIdx.x;
    const int n = threadIdx.x;
    const int lane = n & 31, warp = n >> 5;
    const int kq = n & 7, grp = n >> 3;

    float h = 0.0f;
    const float An = g_A[n];
    float Un[8], Vv[8];
#pragma unroll
    for (int k = 0; k < 8; k++) Un[k] = Uw[n * 8 + k];
#pragma unroll
    for (int j = 0; j < 8; j++) Vv[j] = Vw[(grp * 8 + j) * 8 + kq];

    const float* bxp = g_P + (size_t)b * TT * NPAD + n;
    const float* alp = g_alpha + (size_t)b * TT * 8 + (n >> 6);
    float* hwp = g_hw + (size_t)b * TT * NHW + n;
    const bool cload = (n >= 64 && n < 128);
    const float* cp = cload ? (g_C + (size_t)b * TT * 64 + (n - 64)) : g_C;

    // software prefetch pipeline (2 steps ahead)
    float bx0 = bxp[0];
    float bx1 = bxp[NPAD];
    float av0 = alp[0];
    float av1 = alp[8];
    float creg = cload ? cp[64] : 0.0f;   // C at t=1 (C_0 never used: h_{-1}=0)
    float coup = 0.0f;                    // coupling term for step t (U*C_t*V^T h_{t-1})

    for (int t = 0; t < TT; ++t) {
        // ---- Phase A: update h, publish to smem, emit h*alpha, rotate prefetch ----
        h = fmaf(An, h, coup + bx0);
        h_s[n] = h;
        hwp[(size_t)t * NHW] = h * av0;

        bx0 = bx1; av0 = av1;
        const int tp = (t + 2 < TT) ? (t + 2) : (TT - 1);
        bx1 = bxp[(size_t)tp * NPAD];
        av1 = alp[(size_t)tp * 8];
        if (cload) {
            cbuf[(t + 1) & 1][n - 64] = creg;   // stage C_{t+1}, consumed after the barrier
            creg = cp[(size_t)tp * 64];          // prefetch C_{t+2}
        }
        __syncwarp();

        // ---- Phase R: per-(k,grp) partial of V^T h, warp shfl-combine ----
        float4 hv0 = *(const float4*)&h_s[grp * 8];
        float4 hv1 = *(const float4*)&h_s[grp * 8 + 4];
        float p0 = fmaf(Vv[1], hv0.y, Vv[0] * hv0.x);
        float p1 = fmaf(Vv[3], hv0.w, Vv[2] * hv0.z);
        float p2 = fmaf(Vv[5], hv1.y, Vv[4] * hv1.x);
        float p3 = fmaf(Vv[7], hv1.w, Vv[6] * hv1.z);
        float pv = (p0 + p1) + (p2 + p3);
        pv += __shfl_xor_sync(0xffffffffu, pv, 8);
        pv += __shfl_xor_sync(0xffffffffu, pv, 16);
        if (lane < 8) part_s[t & 1][lane * 16 + warp] = pv;   // k-major
        __syncthreads();

        // ---- Final: every warp redundantly reduces + computes g = C_{t+1} * vh ----
        float vsum = 0.0f, gv = 0.0f;
        float4 c0, c1;
        if (lane < 8) {
            const float* pp = &part_s[t & 1][lane * 16];
            float4 q0 = *(const float4*)&pp[0];
            float4 q1 = *(const float4*)&pp[4];
            float4 q2 = *(const float4*)&pp[8];
            float4 q3 = *(const float4*)&pp[12];
            c0 = *(const float4*)&cbuf[(t + 1) & 1][lane * 8];
            c1 = *(const float4*)&cbuf[(t + 1) & 1][lane * 8 + 4];
            float sx = (q0.x + q1.x) + (q2.x + q3.x);
            float sy = (q0.y + q1.y) + (q2.y + q3.y);
            float sz = (q0.z + q1.z) + (q2.z + q3.z);
            float sw = (q0.w + q1.w) + (q2.w + q3.w);
            vsum = (sx + sy) + (sz + sw);
        }
        float vh[8];
#pragma unroll
        for (int j = 0; j < 8; j++) vh[j] = __shfl_sync(0xffffffffu, vsum, j);
        if (lane < 8) {
            float a0 = fmaf(c0.y, vh[1], c0.x * vh[0]);
            float a1 = fmaf(c0.w, vh[3], c0.z * vh[2]);
            float a2 = fmaf(c1.y, vh[5], c1.x * vh[4]);
            float a3 = fmaf(c1.w, vh[7], c1.z * vh[6]);
            gv = (a0 + a1) + (a2 + a3);
        }
        float gk[8];
#pragma unroll
        for (int k = 0; k < 8; k++) gk[k] = __shfl_sync(0xffffffffu, gv, k);
        float b0 = fmaf(Un[1], gk[1], Un[0] * gk[0]);
        float b1 = fmaf(Un[3], gk[3], Un[2] * gk[2]);
        float b2 = fmaf(Un[5], gk[5], Un[4] * gk[4]);
        float b3 = fmaf(Un[7], gk[7], Un[6] * gk[6]);
        coup = (b0 + b1) + (b2 + b3);
    }
}

// ---------------- launch ----------------
extern "C" void kernel_launch(void* const* d_in, const int* in_sizes, int n_in,
                              void* d_out, int out_size) {
    const float* x      = (const float*)d_in[0];
    const float* Wb     = (const float*)d_in[1];
    const float* bb     = (const float*)d_in[2];
    const float* Wdiag  = (const float*)d_in[3];
    const float* bdiag  = (const float*)d_in[4];
    const float* Woff   = (const float*)d_in[5];
    const float* boff   = (const float*)d_in[6];
    const float* Walpha = (const float*)d_in[7];
    const float* balpha = (const float*)d_in[8];
    const float* Wc     = (const float*)d_in[9];
    const float* bc     = (const float*)d_in[10];
    const float* ll     = (const float*)d_in[11];
    const float* U      = (const float*)d_in[12];
    const float* V      = (const float*)d_in[13];
    float* out = (float*)d_out;

    float *pP, *pWpack, *pbpack, *pW2, *phw;
    cudaGetSymbolAddress((void**)&pP,     g_P);
    cudaGetSymbolAddress((void**)&pWpack, g_Wpack);
    cudaGetSymbolAddress((void**)&pbpack, g_bpack);
    cudaGetSymbolAddress((void**)&pW2,    g_W2);
    cudaGetSymbolAddress((void**)&phw,    g_hw);

    pack1_kernel<<<(DM * NPAD + 255) / 256, 256>>>(Wb, Wdiag, Woff, Walpha);
    pack2_kernel<<<(NHW * DM + 255) / 256, 256>>>(Wc, bc);
    misc_kernel<<<1, 1024>>>(bb, bdiag, boff, balpha, ll);

    // GEMM1: P = x @ Wpack + bpack   (16384 x 640 x 1024)
    sgemm128<<<dim3(NPAD / 128, ROWS / 128), 256>>>(x, pWpack, pbpack, pP, ROWS, NPAD, DM);

    act_kernel<<<ROWS / 64, 256>>>();

    scan_kernel<<<BB, 512>>>(U, V);

    // GEMM2: out = hw @ W2           (16384 x 1024 x 520)
    sgemm128<<<dim3(DM / 128, ROWS / 128), 256>>>(phw, pW2, nullptr, out, ROWS, DM, NHW);
}

// round 6
// speedup vs baseline: 1.4693x; 1.3624x over previous
#include <cuda_runtime.h>
#include <cuda_bf16.h>
#include <cstdint>
#include <math.h>

#define BB 8
#define TT 2048
#define DM 1024
#define NS 512
#define NPAD 640
#define NHW 520
#define KHW 576                 // padded K for GEMM2 (18 x 32)
#define ROWS (BB*TT)            // 16384

// ---------------- scratch (static device globals; no dynamic alloc) ----------------
__device__ float g_P[ROWS * NPAD];              // GEMM1 output fp32
__device__ float g_C[ROWS * 64];                // C matrices (b,t,8,8)
__device__ float g_alpha[ROWS * 8];
__device__ float g_hw[ROWS * NHW];              // scan output fp32: [h*alpha | alpha]
__device__ float g_bpack[NPAD];                 // packed biases
__device__ float g_A[NS];
__device__ __nv_bfloat16 g_xh[ROWS * DM];       // x split hi/lo, [M][K]
__device__ __nv_bfloat16 g_xl[ROWS * DM];
__device__ __nv_bfloat16 g_Wh[DM * NPAD];       // Wpack [K=1024][N=640] hi/lo
__device__ __nv_bfloat16 g_Wl[DM * NPAD];
__device__ __nv_bfloat16 g_hwh[ROWS * KHW];     // hw split hi/lo, [M][576]
__device__ __nv_bfloat16 g_hwl[ROWS * KHW];
__device__ __nv_bfloat16 g_W2h[KHW * DM];       // W2 [K=576][N=1024] hi/lo
__device__ __nv_bfloat16 g_W2l[KHW * DM];

// ---------------- helpers ----------------
__device__ __forceinline__ uint32_t smem_u32(const void* p) {
    uint32_t a;
    asm("{ .reg .u64 t; cvta.to.shared.u64 t, %1; cvt.u32.u64 %0, t; }" : "=r"(a) : "l"(p));
    return a;
}
__device__ __forceinline__ void cp16(uint32_t dst, const void* src) {
    asm volatile("cp.async.cg.shared.global [%0], [%1], 16;" :: "r"(dst), "l"(src));
}
__device__ __forceinline__ void ldsm4(uint32_t* r, uint32_t addr) {
    asm volatile("ldmatrix.sync.aligned.m8n8.x4.shared.b16 {%0,%1,%2,%3}, [%4];"
                 : "=r"(r[0]), "=r"(r[1]), "=r"(r[2]), "=r"(r[3]) : "r"(addr));
}
__device__ __forceinline__ void ldsm4t(uint32_t* r, uint32_t addr) {
    asm volatile("ldmatrix.sync.aligned.m8n8.x4.trans.shared.b16 {%0,%1,%2,%3}, [%4];"
                 : "=r"(r[0]), "=r"(r[1]), "=r"(r[2]), "=r"(r[3]) : "r"(addr));
}
__device__ __forceinline__ void mma16816(float* d, const uint32_t* a, const uint32_t* b) {
    asm volatile(
        "mma.sync.aligned.m16n8k16.row.col.f32.bf16.bf16.f32 "
        "{%0,%1,%2,%3}, {%4,%5,%6,%7}, {%8,%9}, {%0,%1,%2,%3};\n"
        : "+f"(d[0]), "+f"(d[1]), "+f"(d[2]), "+f"(d[3])
        : "r"(a[0]), "r"(a[1]), "r"(a[2]), "r"(a[3]), "r"(b[0]), "r"(b[1]));
}

// smem stage layout (bytes): Ah | Al | Bh | Bl, padded strides for conflict-free ldmatrix
#define ASTR 40                 // halfs per A row (32 + 8 pad)
#define BSTR 136                // halfs per B row (128 + 8 pad)
#define A_BYTES (128 * ASTR * 2)    // 10240
#define B_BYTES (32 * BSTR * 2)     // 8704
#define OFF_AH 0
#define OFF_AL A_BYTES
#define OFF_BH (2 * A_BYTES)
#define OFF_BL (2 * A_BYTES + B_BYTES)
#define STG (2 * A_BYTES + 2 * B_BYTES)   // 37888
#define GSMEM (3 * STG)                   // 113664

// ---------------- bf16x3 mma.sync GEMM: D[M,N] = A[M,K] @ B[K,N] (+bias) ----------------
__global__ void __launch_bounds__(256, 1)
gemm_bf16x3_mma(const __nv_bfloat16* __restrict__ Ah, const __nv_bfloat16* __restrict__ Al,
                const __nv_bfloat16* __restrict__ Bh, const __nv_bfloat16* __restrict__ Bl,
                const float* __restrict__ bias, float* __restrict__ D, int K, int N)
{
    extern __shared__ char smem[];
    const uint32_t sbase = smem_u32(smem);
    const int tid = threadIdx.x;
    const int lane = tid & 31, w = tid >> 5;
    const int wm = w & 1, wn = w >> 1;          // warp grid 2(m) x 4(n)
    const int m0 = blockIdx.y * 128;
    const int n0 = blockIdx.x * 128;
    const int NC = K >> 5;

    float acc[4][4][4];
#pragma unroll
    for (int i = 0; i < 4; i++)
#pragma unroll
        for (int j = 0; j < 4; j++)
#pragma unroll
            for (int q = 0; q < 4; q++) acc[i][j][q] = 0.0f;

    // loader indices
    const int ar = tid >> 2, as = tid & 3;       // A: 2 chunks per matrix
    const int br = tid >> 4, bs = tid & 15;      // B: 2 chunks per matrix

    auto load_stage = [&](int s, int c) {
        const uint32_t st = sbase + s * STG;
        const long kc = (long)c * 32;
        cp16(st + OFF_AH + ar * 80 + as * 16,        Ah + (long)(m0 + ar) * K + kc + as * 8);
        cp16(st + OFF_AH + (ar + 64) * 80 + as * 16, Ah + (long)(m0 + ar + 64) * K + kc + as * 8);
        cp16(st + OFF_AL + ar * 80 + as * 16,        Al + (long)(m0 + ar) * K + kc + as * 8);
        cp16(st + OFF_AL + (ar + 64) * 80 + as * 16, Al + (long)(m0 + ar + 64) * K + kc + as * 8);
        cp16(st + OFF_BH + br * 272 + bs * 16,        Bh + (kc + br) * (long)N + n0 + bs * 8);
        cp16(st + OFF_BH + (br + 16) * 272 + bs * 16, Bh + (kc + br + 16) * (long)N + n0 + bs * 8);
        cp16(st + OFF_BL + br * 272 + bs * 16,        Bl + (kc + br) * (long)N + n0 + bs * 8);
        cp16(st + OFF_BL + (br + 16) * 272 + bs * 16, Bl + (kc + br + 16) * (long)N + n0 + bs * 8);
        asm volatile("cp.async.commit_group;");
    };

    const int pre = (NC < 3) ? NC : 3;
    for (int s = 0; s < pre; s++) load_stage(s, s);

    // per-lane ldmatrix base offsets (within a stage)
    const uint32_t a_off = (uint32_t)(((wm * 64 + (lane & 15)) * ASTR + ((lane >> 4) << 3)) * 2);
    const uint32_t b_off = (uint32_t)((((lane & 15)) * BSTR + wn * 32 + ((lane >> 4) << 3)) * 2);

    int s = 0;
    for (int kt = 0; kt < NC; ++kt) {
        const int pend = ((NC - kt) < 3 ? (NC - kt) : 3);
        if (pend == 3)      asm volatile("cp.async.wait_group 2;");
        else if (pend == 2) asm volatile("cp.async.wait_group 1;");
        else                asm volatile("cp.async.wait_group 0;");
        __syncthreads();

        const uint32_t st = sbase + s * STG;
        const uint32_t ah_b = st + OFF_AH + a_off;
        const uint32_t al_b = st + OFF_AL + a_off;
        const uint32_t bh_b = st + OFF_BH + b_off;
        const uint32_t bl_b = st + OFF_BL + b_off;

#pragma unroll
        for (int kk = 0; kk < 2; ++kk) {
            uint32_t af[4][4], lf[4][4], bf[2][4], gf[2][4];
#pragma unroll
            for (int mt = 0; mt < 4; mt++) {
                ldsm4(af[mt], ah_b + (mt * 16 * ASTR + kk * 16) * 2);
                ldsm4(lf[mt], al_b + (mt * 16 * ASTR + kk * 16) * 2);
            }
#pragma unroll
            for (int np = 0; np < 2; np++) {
                ldsm4t(bf[np], bh_b + (kk * 16 * BSTR + np * 16) * 2);
                ldsm4t(gf[np], bl_b + (kk * 16 * BSTR + np * 16) * 2);
            }
#pragma unroll
            for (int mt = 0; mt < 4; mt++) {
#pragma unroll
                for (int nt = 0; nt < 4; nt++) {
                    const uint32_t* bp = &bf[nt >> 1][(nt & 1) * 2];
                    const uint32_t* lp = &gf[nt >> 1][(nt & 1) * 2];
                    mma16816(acc[mt][nt], af[mt], bp);   // Ah*Bh
                    mma16816(acc[mt][nt], lf[mt], bp);   // Al*Bh
                    mma16816(acc[mt][nt], af[mt], lp);   // Ah*Bl
                }
            }
        }
        __syncthreads();
        const int cn = kt + 3;
        if (cn < NC) load_stage(s, cn);
        if (++s == 3) s = 0;
    }

    // epilogue
    const int rb = m0 + wm * 64 + (lane >> 2);
    const int cb = n0 + wn * 32 + (lane & 3) * 2;
#pragma unroll
    for (int mt = 0; mt < 4; mt++) {
#pragma unroll
        for (int nt = 0; nt < 4; nt++) {
            const int r = rb + mt * 16;
            const int c = cb + nt * 8;
            float b0 = 0.0f, b1 = 0.0f;
            if (bias) { b0 = bias[c]; b1 = bias[c + 1]; }
            float2 o0 = make_float2(acc[mt][nt][0] + b0, acc[mt][nt][1] + b1);
            float2 o1 = make_float2(acc[mt][nt][2] + b0, acc[mt][nt][3] + b1);
            *(float2*)(D + (size_t)r * N + c) = o0;
            *(float2*)(D + (size_t)(r + 8) * N + c) = o1;
        }
    }
}

// ---------------- conversion / packing kernels ----------------
__global__ void conv_x_kernel(const float4* __restrict__ src, uint2* __restrict__ dh,
                              uint2* __restrict__ dl, int n4) {
    int i = blockIdx.x * blockDim.x + threadIdx.x;
    if (i >= n4) return;
    float4 v = src[i];
    __nv_bfloat16 h0 = __float2bfloat16_rn(v.x), h1 = __float2bfloat16_rn(v.y);
    __nv_bfloat16 h2 = __float2bfloat16_rn(v.z), h3 = __float2bfloat16_rn(v.w);
    __nv_bfloat16 l0 = __float2bfloat16_rn(v.x - __bfloat162float(h0));
    __nv_bfloat16 l1 = __float2bfloat16_rn(v.y - __bfloat162float(h1));
    __nv_bfloat16 l2 = __float2bfloat16_rn(v.z - __bfloat162float(h2));
    __nv_bfloat16 l3 = __float2bfloat16_rn(v.w - __bfloat162float(h3));
    __nv_bfloat162 ph0 = __nv_bfloat162(h0, h1), ph1 = __nv_bfloat162(h2, h3);
    __nv_bfloat162 pl0 = __nv_bfloat162(l0, l1), pl1 = __nv_bfloat162(l2, l3);
    uint2 oh, ol;
    oh.x = *(uint32_t*)&ph0; oh.y = *(uint32_t*)&ph1;
    ol.x = *(uint32_t*)&pl0; ol.y = *(uint32_t*)&pl1;
    dh[i] = oh; dl[i] = ol;
}

__global__ void pack1b_kernel(const float* __restrict__ Wb, const float* __restrict__ Wdiag,
                              const float* __restrict__ Woff, const float* __restrict__ Walpha) {
    int idx = blockIdx.x * blockDim.x + threadIdx.x;
    if (idx >= DM * NPAD) return;
    int r = idx / NPAD, c = idx - r * NPAD;   // W[k=r][n=c]
    float v;
    if (c < 512)       v = Wb[r * NS + c];
    else if (c < 520)  v = Wdiag[r * 8 + (c - 512)];
    else if (c < 576)  v = Woff[r * 56 + (c - 520)];
    else if (c < 584)  v = Walpha[r * 8 + (c - 576)];
    else               v = 0.0f;
    __nv_bfloat16 h = __float2bfloat16_rn(v);
    g_Wh[idx] = h;
    g_Wl[idx] = __float2bfloat16_rn(v - __bfloat162float(h));
}

__global__ void pack2b_kernel(const float* __restrict__ Wc, const float* __restrict__ bc) {
    int idx = blockIdx.x * blockDim.x + threadIdx.x;
    if (idx >= KHW * DM) return;
    int k = idx >> 10, n = idx & 1023;   // W2[k][n]
    float v;
    if (k < 512)      v = Wc[idx];
    else if (k < 520) v = bc[(size_t)(k - 512) * DM + n];
    else              v = 0.0f;
    __nv_bfloat16 h = __float2bfloat16_rn(v);
    g_W2h[idx] = h;
    g_W2l[idx] = __float2bfloat16_rn(v - __bfloat162float(h));
}

__global__ void conv_hw_kernel(void) {
    int row = blockIdx.x, k = threadIdx.x;   // block = 576 threads
    float v = (k < NHW) ? g_hw[(size_t)row * NHW + k] : 0.0f;
    __nv_bfloat16 h = __float2bfloat16_rn(v);
    g_hwh[(size_t)row * KHW + k] = h;
    g_hwl[(size_t)row * KHW + k] = __float2bfloat16_rn(v - __bfloat162float(h));
}

__global__ void misc_kernel(const float* __restrict__ bb, const float* __restrict__ bdiag,
                            const float* __restrict__ boff, const float* __restrict__ balpha,
                            const float* __restrict__ log_lambda) {
    int tid = threadIdx.x;
    if (tid < NS) {
        int k = tid >> 6;
        double dt = 1e-3 * exp((double)k * log(1000.0) / 7.0);
        double ll = (double)log_lambda[tid];
        double sp = log1p(exp(ll));
        g_A[tid] = (float)exp(-dt * sp);
    }
    if (tid < NPAD) {
        float v;
        if (tid < 512)       v = bb[tid];
        else if (tid < 520)  v = bdiag[tid - 512];
        else if (tid < 576)  v = boff[tid - 520];
        else if (tid < 584)  v = balpha[tid - 576];
        else                 v = 0.0f;
        g_bpack[tid] = v;
    }
}

// ---------------- activations ----------------
__global__ void __launch_bounds__(256) act_kernel(void) {
    __shared__ float s[64 * 72];
    const int row0 = blockIdx.x * 64;
    const int tid = threadIdx.x;
    for (int i = tid; i < 64 * 72; i += 256) {
        int r = i / 72, c = i - r * 72;
        s[i] = g_P[(size_t)(row0 + r) * NPAD + 512 + c];
    }
    __syncthreads();
    if (tid < 64) {
        const int row = row0 + tid;
        const float* v = &s[tid * 72];
        float dg[8];
#pragma unroll
        for (int i = 0; i < 8; i++) dg[i] = 1.0f / (1.0f + expf(-v[i]));
        float Cm[64];
        int m = 0;
#pragma unroll
        for (int i = 0; i < 8; i++) {
#pragma unroll
            for (int j = 0; j < 8; j++) {
                if (i == j) {
                    Cm[i * 8 + j] = dg[i];
                } else {
                    float x = v[8 + m];
                    float sp = (x > 15.0f) ? x : log1pf(expf(x));
                    Cm[i * 8 + j] = -sp;
                    m++;
                }
            }
        }
#pragma unroll
        for (int q = 0; q < 64; q++) g_C[(size_t)row * 64 + q] = Cm[q];
        float a[8], mx = v[64];
#pragma unroll
        for (int i = 1; i < 8; i++) mx = fmaxf(mx, v[64 + i]);
        float sum = 0.0f;
#pragma unroll
        for (int i = 0; i < 8; i++) { a[i] = expf(v[64 + i] - mx); sum += a[i]; }
        float inv = 1.0f / sum;
#pragma unroll
        for (int k = 0; k < 8; k++) {
            float al = a[k] * inv;
            g_alpha[(size_t)row * 8 + k] = al;
            g_hw[(size_t)row * NHW + 512 + k] = al;
        }
    }
}

// ---------------- sequential scan (unchanged from R3) ----------------
__global__ void __launch_bounds__(512, 1) scan_kernel(const float* __restrict__ Uw,
                                                      const float* __restrict__ Vw) {
    __shared__ __align__(16) float h_s[NS];
    __shared__ __align__(16) float part_s[2][128];
    __shared__ __align__(16) float cbuf[2][64];

    const int b = blockIdx.x;
    const int n = threadIdx.x;
    const int lane = n & 31, warp = n >> 5;
    const int kq = n & 7, grp = n >> 3;

    float h = 0.0f;
    const float An = g_A[n];
    float Un[8], Vv[8];
#pragma unroll
    for (int k = 0; k < 8; k++) Un[k] = Uw[n * 8 + k];
#pragma unroll
    for (int j = 0; j < 8; j++) Vv[j] = Vw[(grp * 8 + j) * 8 + kq];

    const float* bxp = g_P + (size_t)b * TT * NPAD + n;
    const float* alp = g_alpha + (size_t)b * TT * 8 + (n >> 6);
    float* hwp = g_hw + (size_t)b * TT * NHW + n;
    const bool cload = (n >= 64 && n < 128);
    const float* cp = cload ? (g_C + (size_t)b * TT * 64 + (n - 64)) : g_C;

    float bx0 = bxp[0];
    float bx1 = bxp[NPAD];
    float av0 = alp[0];
    float av1 = alp[8];
    float creg = cload ? cp[64] : 0.0f;
    float coup = 0.0f;

    for (int t = 0; t < TT; ++t) {
        h = fmaf(An, h, coup + bx0);
        h_s[n] = h;
        hwp[(size_t)t * NHW] = h * av0;

        bx0 = bx1; av0 = av1;
        const int tp = (t + 2 < TT) ? (t + 2) : (TT - 1);
        bx1 = bxp[(size_t)tp * NPAD];
        av1 = alp[(size_t)tp * 8];
        if (cload) {
            cbuf[(t + 1) & 1][n - 64] = creg;
            creg = cp[(size_t)tp * 64];
        }
        __syncwarp();

        float4 hv0 = *(const float4*)&h_s[grp * 8];
        float4 hv1 = *(const float4*)&h_s[grp * 8 + 4];
        float p0 = fmaf(Vv[1], hv0.y, Vv[0] * hv0.x);
        float p1 = fmaf(Vv[3], hv0.w, Vv[2] * hv0.z);
        float p2 = fmaf(Vv[5], hv1.y, Vv[4] * hv1.x);
        float p3 = fmaf(Vv[7], hv1.w, Vv[6] * hv1.z);
        float pv = (p0 + p1) + (p2 + p3);
        pv += __shfl_xor_sync(0xffffffffu, pv, 8);
        pv += __shfl_xor_sync(0xffffffffu, pv, 16);
        if (lane < 8) part_s[t & 1][lane * 16 + warp] = pv;
        __syncthreads();

        float vsum = 0.0f, gv = 0.0f;
        float4 c0, c1;
        if (lane < 8) {
            const float* pp = &part_s[t & 1][lane * 16];
            float4 q0 = *(const float4*)&pp[0];
            float4 q1 = *(const float4*)&pp[4];
            float4 q2 = *(const float4*)&pp[8];
            float4 q3 = *(const float4*)&pp[12];
            c0 = *(const float4*)&cbuf[(t + 1) & 1][lane * 8];
            c1 = *(const float4*)&cbuf[(t + 1) & 1][lane * 8 + 4];
            float sx = (q0.x + q1.x) + (q2.x + q3.x);
            float sy = (q0.y + q1.y) + (q2.y + q3.y);
            float sz = (q0.z + q1.z) + (q2.z + q3.z);
            float sw = (q0.w + q1.w) + (q2.w + q3.w);
            vsum = (sx + sy) + (sz + sw);
        }
        float vh[8];
#pragma unroll
        for (int j = 0; j < 8; j++) vh[j] = __shfl_sync(0xffffffffu, vsum, j);
        if (lane < 8) {
            float a0 = fmaf(c0.y, vh[1], c0.x * vh[0]);
            float a1 = fmaf(c0.w, vh[3], c0.z * vh[2]);
            float a2 = fmaf(c1.y, vh[5], c1.x * vh[4]);
            float a3 = fmaf(c1.w, vh[7], c1.z * vh[6]);
            gv = (a0 + a1) + (a2 + a3);
        }
        float gk[8];
#pragma unroll
        for (int k = 0; k < 8; k++) gk[k] = __shfl_sync(0xffffffffu, gv, k);
        float b0 = fmaf(Un[1], gk[1], Un[0] * gk[0]);
        float b1 = fmaf(Un[3], gk[3], Un[2] * gk[2]);
        float b2 = fmaf(Un[5], gk[5], Un[4] * gk[4]);
        float b3 = fmaf(Un[7], gk[7], Un[6] * gk[6]);
        coup = (b0 + b1) + (b2 + b3);
    }
}

// ---------------- launch ----------------
extern "C" void kernel_launch(void* const* d_in, const int* in_sizes, int n_in,
                              void* d_out, int out_size) {
    const float* x      = (const float*)d_in[0];
    const float* Wb     = (const float*)d_in[1];
    const float* bb     = (const float*)d_in[2];
    const float* Wdiag  = (const float*)d_in[3];
    const float* bdiag  = (const float*)d_in[4];
    const float* Woff   = (const float*)d_in[5];
    const float* boff   = (const float*)d_in[6];
    const float* Walpha = (const float*)d_in[7];
    const float* balpha = (const float*)d_in[8];
    const float* Wc     = (const float*)d_in[9];
    const float* bc     = (const float*)d_in[10];
    const float* ll     = (const float*)d_in[11];
    const float* U      = (const float*)d_in[12];
    const float* V      = (const float*)d_in[13];
    float* out = (float*)d_out;

    float *pP, *pbpack;
    __nv_bfloat16 *pxh, *pxl, *pWh, *pWl, *phwh, *phwl, *pW2h, *pW2l;
    cudaGetSymbolAddress((void**)&pP,     g_P);
    cudaGetSymbolAddress((void**)&pbpack, g_bpack);
    cudaGetSymbolAddress((void**)&pxh,    g_xh);
    cudaGetSymbolAddress((void**)&pxl,    g_xl);
    cudaGetSymbolAddress((void**)&pWh,    g_Wh);
    cudaGetSymbolAddress((void**)&pWl,    g_Wl);
    cudaGetSymbolAddress((void**)&phwh,   g_hwh);
    cudaGetSymbolAddress((void**)&phwl,   g_hwl);
    cudaGetSymbolAddress((void**)&pW2h,   g_W2h);
    cudaGetSymbolAddress((void**)&pW2l,   g_W2l);

    cudaFuncSetAttribute(gemm_bf16x3_mma, cudaFuncAttributeMaxDynamicSharedMemorySize, GSMEM);

    // conversions + packing
    conv_x_kernel<<<(ROWS * DM / 4 + 255) / 256, 256>>>((const float4*)x, (uint2*)pxh,
                                                        (uint2*)pxl, ROWS * DM / 4);
    pack1b_kernel<<<(DM * NPAD + 255) / 256, 256>>>(Wb, Wdiag, Woff, Walpha);
    pack2b_kernel<<<(KHW * DM + 255) / 256, 256>>>(Wc, bc);
    misc_kernel<<<1, 1024>>>(bb, bdiag, boff, balpha, ll);

    // GEMM1: P = x @ Wpack + bpack   (M=16384, N=640, K=1024)
    gemm_bf16x3_mma<<<dim3(NPAD / 128, ROWS / 128), 256, GSMEM>>>(pxh, pxl, pWh, pWl,
                                                                  pbpack, pP, DM, NPAD);

    act_kernel<<<ROWS / 64, 256>>>();

    scan_kernel<<<BB, 512>>>(U, V);

    conv_hw_kernel<<<ROWS, KHW>>>();

    // GEMM2: out = hw @ W2           (M=16384, N=1024, K=576)
    gemm_bf16x3_mma<<<dim3(DM / 128, ROWS / 128), 256, GSMEM>>>(phwh, phwl, pW2h, pW2l,
                                                                nullptr, out, KHW, DM);
}

// round 7
// speedup vs baseline: 1.5380x; 1.0468x over previous
#include <cuda_runtime.h>
#include <cuda_bf16.h>
#include <cstdint>
#include <math.h>

#define BB 8
#define TT 2048
#define DM 1024
#define NS 512
#define NPAD 640
#define NHW 520
#define KHW 576                 // padded K for GEMM2 (18 x 32)
#define ROWS (BB*TT)            // 16384

// ---------------- scratch (static device globals; no dynamic alloc) ----------------
__device__ float g_P[ROWS * NPAD];              // GEMM1 output fp32
__device__ float g_C[ROWS * 64];                // C matrices (b,t,8,8)
__device__ float g_alpha[ROWS * 8];
__device__ float g_bpack[NPAD];                 // packed biases
__device__ float g_A[NS];
__device__ __nv_bfloat16 g_xh[ROWS * DM];       // x split hi/lo, [M][K]
__device__ __nv_bfloat16 g_xl[ROWS * DM];
__device__ __nv_bfloat16 g_Wh[DM * NPAD];       // Wpack [K=1024][N=640] hi/lo
__device__ __nv_bfloat16 g_Wl[DM * NPAD];
__device__ __nv_bfloat16 g_hwh[ROWS * KHW];     // [h*alpha | alpha | 0pad] hi, bf16
__device__ __nv_bfloat16 g_hwl[ROWS * KHW];     // lo residual
__device__ __nv_bfloat16 g_W2h[KHW * DM];       // W2 [K=576][N=1024] hi/lo
__device__ __nv_bfloat16 g_W2l[KHW * DM];

// ---------------- helpers ----------------
__device__ __forceinline__ uint32_t smem_u32(const void* p) {
    uint32_t a;
    asm("{ .reg .u64 t; cvta.to.shared.u64 t, %1; cvt.u32.u64 %0, t; }" : "=r"(a) : "l"(p));
    return a;
}
__device__ __forceinline__ void cp16(uint32_t dst, const void* src) {
    asm volatile("cp.async.cg.shared.global [%0], [%1], 16;" :: "r"(dst), "l"(src));
}
__device__ __forceinline__ void ldsm4(uint32_t* r, uint32_t addr) {
    asm volatile("ldmatrix.sync.aligned.m8n8.x4.shared.b16 {%0,%1,%2,%3}, [%4];"
                 : "=r"(r[0]), "=r"(r[1]), "=r"(r[2]), "=r"(r[3]) : "r"(addr));
}
__device__ __forceinline__ void ldsm4t(uint32_t* r, uint32_t addr) {
    asm volatile("ldmatrix.sync.aligned.m8n8.x4.trans.shared.b16 {%0,%1,%2,%3}, [%4];"
                 : "=r"(r[0]), "=r"(r[1]), "=r"(r[2]), "=r"(r[3]) : "r"(addr));
}
__device__ __forceinline__ void mma16816(float* d, const uint32_t* a, const uint32_t* b) {
    asm volatile(
        "mma.sync.aligned.m16n8k16.row.col.f32.bf16.bf16.f32 "
        "{%0,%1,%2,%3}, {%4,%5,%6,%7}, {%8,%9}, {%0,%1,%2,%3};\n"
        : "+f"(d[0]), "+f"(d[1]), "+f"(d[2]), "+f"(d[3])
        : "r"(a[0]), "r"(a[1]), "r"(a[2]), "r"(a[3]), "r"(b[0]), "r"(b[1]));
}
__device__ __forceinline__ uint32_t bf16x2_pack(float a, float b) {
    __nv_bfloat162 p = __nv_bfloat162(__float2bfloat16_rn(a), __float2bfloat16_rn(b));
    return *(uint32_t*)&p;
}

// smem stage layout (bytes): Ah | Al | Bh | Bl, padded strides for conflict-free ldmatrix
#define ASTR 40
#define BSTR 136
#define A_BYTES (128 * ASTR * 2)
#define B_BYTES (32 * BSTR * 2)
#define OFF_AH 0
#define OFF_AL A_BYTES
#define OFF_BH (2 * A_BYTES)
#define OFF_BL (2 * A_BYTES + B_BYTES)
#define STG (2 * A_BYTES + 2 * B_BYTES)
#define GSMEM (3 * STG)

// ---------------- bf16x3 mma.sync GEMM: D[M,N] = A[M,K] @ B[K,N] (+bias) ----------------
__global__ void __launch_bounds__(256, 1)
gemm_bf16x3_mma(const __nv_bfloat16* __restrict__ Ah, const __nv_bfloat16* __restrict__ Al,
                const __nv_bfloat16* __restrict__ Bh, const __nv_bfloat16* __restrict__ Bl,
                const float* __restrict__ bias, float* __restrict__ D, int K, int N)
{
    extern __shared__ char smem[];
    const uint32_t sbase = smem_u32(smem);
    const int tid = threadIdx.x;
    const int lane = tid & 31, w = tid >> 5;
    const int wm = w & 1, wn = w >> 1;
    const int m0 = blockIdx.y * 128;
    const int n0 = blockIdx.x * 128;
    const int NC = K >> 5;

    float acc[4][4][4];
#pragma unroll
    for (int i = 0; i < 4; i++)
#pragma unroll
        for (int j = 0; j < 4; j++)
#pragma unroll
            for (int q = 0; q < 4; q++) acc[i][j][q] = 0.0f;

    const int ar = tid >> 2, as = tid & 3;
    const int br = tid >> 4, bs = tid & 15;

    auto load_stage = [&](int s, int c) {
        const uint32_t st = sbase + s * STG;
        const long kc = (long)c * 32;
        cp16(st + OFF_AH + ar * 80 + as * 16,        Ah + (long)(m0 + ar) * K + kc + as * 8);
        cp16(st + OFF_AH + (ar + 64) * 80 + as * 16, Ah + (long)(m0 + ar + 64) * K + kc + as * 8);
        cp16(st + OFF_AL + ar * 80 + as * 16,        Al + (long)(m0 + ar) * K + kc + as * 8);
        cp16(st + OFF_AL + (ar + 64) * 80 + as * 16, Al + (long)(m0 + ar + 64) * K + kc + as * 8);
        cp16(st + OFF_BH + br * 272 + bs * 16,        Bh + (kc + br) * (long)N + n0 + bs * 8);
        cp16(st + OFF_BH + (br + 16) * 272 + bs * 16, Bh + (kc + br + 16) * (long)N + n0 + bs * 8);
        cp16(st + OFF_BL + br * 272 + bs * 16,        Bl + (kc + br) * (long)N + n0 + bs * 8);
        cp16(st + OFF_BL + (br + 16) * 272 + bs * 16, Bl + (kc + br + 16) * (long)N + n0 + bs * 8);
        asm volatile("cp.async.commit_group;");
    };

    const int pre = (NC < 3) ? NC : 3;
    for (int s = 0; s < pre; s++) load_stage(s, s);

    const uint32_t a_off = (uint32_t)(((wm * 64 + (lane & 15)) * ASTR + ((lane >> 4) << 3)) * 2);
    const uint32_t b_off = (uint32_t)((((lane & 15)) * BSTR + wn * 32 + ((lane >> 4) << 3)) * 2);

    int s = 0;
    for (int kt = 0; kt < NC; ++kt) {
        const int pend = ((NC - kt) < 3 ? (NC - kt) : 3);
        if (pend == 3)      asm volatile("cp.async.wait_group 2;");
        else if (pend == 2) asm volatile("cp.async.wait_group 1;");
        else                asm volatile("cp.async.wait_group 0;");
        __syncthreads();

        const uint32_t st = sbase + s * STG;
        const uint32_t ah_b = st + OFF_AH + a_off;
        const uint32_t al_b = st + OFF_AL + a_off;
        const uint32_t bh_b = st + OFF_BH + b_off;
        const uint32_t bl_b = st + OFF_BL + b_off;

#pragma unroll
        for (int kk = 0; kk < 2; ++kk) {
            uint32_t af[4][4], lf[4][4], bf[2][4], gf[2][4];
#pragma unroll
            for (int mt = 0; mt < 4; mt++) {
                ldsm4(af[mt], ah_b + (mt * 16 * ASTR + kk * 16) * 2);
                ldsm4(lf[mt], al_b + (mt * 16 * ASTR + kk * 16) * 2);
            }
#pragma unroll
            for (int np = 0; np < 2; np++) {
                ldsm4t(bf[np], bh_b + (kk * 16 * BSTR + np * 16) * 2);
                ldsm4t(gf[np], bl_b + (kk * 16 * BSTR + np * 16) * 2);
            }
#pragma unroll
            for (int mt = 0; mt < 4; mt++) {
#pragma unroll
                for (int nt = 0; nt < 4; nt++) {
                    const uint32_t* bp = &bf[nt >> 1][(nt & 1) * 2];
                    const uint32_t* lp = &gf[nt >> 1][(nt & 1) * 2];
                    mma16816(acc[mt][nt], af[mt], bp);
                    mma16816(acc[mt][nt], lf[mt], bp);
                    mma16816(acc[mt][nt], af[mt], lp);
                }
            }
        }
        __syncthreads();
        const int cn = kt + 3;
        if (cn < NC) load_stage(s, cn);
        if (++s == 3) s = 0;
    }

    const int rb = m0 + wm * 64 + (lane >> 2);
    const int cb = n0 + wn * 32 + (lane & 3) * 2;
#pragma unroll
    for (int mt = 0; mt < 4; mt++) {
#pragma unroll
        for (int nt = 0; nt < 4; nt++) {
            const int r = rb + mt * 16;
            const int c = cb + nt * 8;
            float b0 = 0.0f, b1 = 0.0f;
            if (bias) { b0 = bias[c]; b1 = bias[c + 1]; }
            float2 o0 = make_float2(acc[mt][nt][0] + b0, acc[mt][nt][1] + b1);
            float2 o1 = make_float2(acc[mt][nt][2] + b0, acc[mt][nt][3] + b1);
            *(float2*)(D + (size_t)r * N + c) = o0;
            *(float2*)(D + (size_t)(r + 8) * N + c) = o1;
        }
    }
}

// ---------------- conversion / packing kernels ----------------
__global__ void conv_x_kernel(const float4* __restrict__ src, uint2* __restrict__ dh,
                              uint2* __restrict__ dl, int n4) {
    int i = blockIdx.x * blockDim.x + threadIdx.x;
    if (i >= n4) return;
    float4 v = src[i];
    float hx = __bfloat162float(__float2bfloat16_rn(v.x));
    float hy = __bfloat162float(__float2bfloat16_rn(v.y));
    float hz = __bfloat162float(__float2bfloat16_rn(v.z));
    float hw = __bfloat162float(__float2bfloat16_rn(v.w));
    uint2 oh, ol;
    oh.x = bf16x2_pack(v.x, v.y); oh.y = bf16x2_pack(v.z, v.w);
    ol.x = bf16x2_pack(v.x - hx, v.y - hy); ol.y = bf16x2_pack(v.z - hz, v.w - hw);
    dh[i] = oh; dl[i] = ol;
}

__global__ void pack1b_kernel(const float* __restrict__ Wb, const float* __restrict__ Wdiag,
                              const float* __restrict__ Woff, const float* __restrict__ Walpha) {
    int idx = blockIdx.x * blockDim.x + threadIdx.x;
    if (idx >= DM * NPAD) return;
    int r = idx / NPAD, c = idx - r * NPAD;
    float v;
    if (c < 512)       v = Wb[r * NS + c];
    else if (c < 520)  v = Wdiag[r * 8 + (c - 512)];
    else if (c < 576)  v = Woff[r * 56 + (c - 520)];
    else if (c < 584)  v = Walpha[r * 8 + (c - 576)];
    else               v = 0.0f;
    __nv_bfloat16 h = __float2bfloat16_rn(v);
    g_Wh[idx] = h;
    g_Wl[idx] = __float2bfloat16_rn(v - __bfloat162float(h));
}

__global__ void pack2b_kernel(const float* __restrict__ Wc, const float* __restrict__ bc) {
    int idx = blockIdx.x * blockDim.x + threadIdx.x;
    if (idx >= KHW * DM) return;
    int k = idx >> 10, n = idx & 1023;
    float v;
    if (k < 512)      v = Wc[idx];
    else if (k < 520) v = bc[(size_t)(k - 512) * DM + n];
    else              v = 0.0f;
    __nv_bfloat16 h = __float2bfloat16_rn(v);
    g_W2h[idx] = h;
    g_W2l[idx] = __float2bfloat16_rn(v - __bfloat162float(h));
}

__global__ void misc_kernel(const float* __restrict__ bb, const float* __restrict__ bdiag,
                            const float* __restrict__ boff, const float* __restrict__ balpha,
                            const float* __restrict__ log_lambda) {
    int tid = threadIdx.x;
    if (tid < NS) {
        int k = tid >> 6;
        double dt = 1e-3 * exp((double)k * log(1000.0) / 7.0);
        double ll = (double)log_lambda[tid];
        double sp = log1p(exp(ll));
        g_A[tid] = (float)exp(-dt * sp);
    }
    if (tid < NPAD) {
        float v;
        if (tid < 512)       v = bb[tid];
        else if (tid < 520)  v = bdiag[tid - 512];
        else if (tid < 576)  v = boff[tid - 520];
        else if (tid < 584)  v = balpha[tid - 576];
        else                 v = 0.0f;
        g_bpack[tid] = v;
    }
}

// ---------------- activations: C, alpha; write alpha tail + zero pad into hwh/hwl ----------------
__global__ void __launch_bounds__(256) act_kernel(void) {
    __shared__ float s[64 * 72];
    const int row0 = blockIdx.x * 64;
    const int tid = threadIdx.x;
    for (int i = tid; i < 64 * 72; i += 256) {
        int r = i / 72, c = i - r * 72;
        s[i] = g_P[(size_t)(row0 + r) * NPAD + 512 + c];
    }
    __syncthreads();
    if (tid < 64) {
        const int row = row0 + tid;
        const float* v = &s[tid * 72];
        float dg[8];
#pragma unroll
        for (int i = 0; i < 8; i++) dg[i] = 1.0f / (1.0f + expf(-v[i]));
        float Cm[64];
        int m = 0;
#pragma unroll
        for (int i = 0; i < 8; i++) {
#pragma unroll
            for (int j = 0; j < 8; j++) {
                if (i == j) {
                    Cm[i * 8 + j] = dg[i];
                } else {
                    float x = v[8 + m];
                    float sp = (x > 15.0f) ? x : log1pf(expf(x));
                    Cm[i * 8 + j] = -sp;
                    m++;
                }
            }
        }
#pragma unroll
        for (int q = 0; q < 64; q++) g_C[(size_t)row * 64 + q] = Cm[q];
        float a[8], mx = v[64];
#pragma unroll
        for (int i = 1; i < 8; i++) mx = fmaxf(mx, v[64 + i]);
        float sum = 0.0f;
#pragma unroll
        for (int i = 0; i < 8; i++) { a[i] = expf(v[64 + i] - mx); sum += a[i]; }
        float inv = 1.0f / sum;
#pragma unroll
        for (int k = 0; k < 8; k++) {
            float al = a[k] * inv;
            g_alpha[(size_t)row * 8 + k] = al;
            __nv_bfloat16 h = __float2bfloat16_rn(al);
            g_hwh[(size_t)row * KHW + 512 + k] = h;
            g_hwl[(size_t)row * KHW + 512 + k] = __float2bfloat16_rn(al - __bfloat162float(h));
        }
    }
    // zero pad cols 520..575 for this block's 64 rows
    const __nv_bfloat16 z = __float2bfloat16_rn(0.0f);
    for (int i = tid; i < 64 * 56; i += 256) {
        int r = i / 56, c = i - r * 56;
        g_hwh[(size_t)(row0 + r) * KHW + 520 + c] = z;
        g_hwl[(size_t)(row0 + r) * KHW + 520 + c] = z;
    }
}

// ---------------- sequential scan: 128 threads/batch, 4 states/thread ----------------
// h_t = A*h_{t-1} + U (C_t V^T h_{t-1}) + bx_t ; emits h*alpha as bf16 hi/lo.
// Warp w owns states 128w..128w+127 AND reduces exactly those states in phase R,
// so phase A -> phase R needs only __syncwarp; one 4-warp __syncthreads per step.
__global__ void __launch_bounds__(128, 1) scan_kernel(const float* __restrict__ Uw,
                                                      const float* __restrict__ Vw) {
    __shared__ __align__(16) float h_s[NS];
    __shared__ __align__(16) float part_s[2][32];   // [buf][k*4 + warp]
    __shared__ __align__(16) float cbuf[2][96];     // staged C_{t+1}, row stride 12
    const int b = blockIdx.x;
    const int i = threadIdx.x;
    const int lane = i & 31, warp = i >> 5;
    const int kq = i & 7, grp = i >> 3;             // 16 groups of 32 states
    const int s0 = 4 * i;

    float h0 = 0.0f, h1 = 0.0f, h2 = 0.0f, h3 = 0.0f;
    const float4 An = *(const float4*)&g_A[s0];
    float Un[4][8];
#pragma unroll
    for (int s = 0; s < 4; s++)
#pragma unroll
        for (int k = 0; k < 8; k++) Un[s][k] = Uw[(s0 + s) * 8 + k];
    float Vv[32];
#pragma unroll
    for (int j = 0; j < 32; j++) Vv[j] = Vw[(grp * 32 + j) * 8 + kq];

    const float* bxp = g_P + (size_t)b * TT * NPAD + s0;
    const float* alp = g_alpha + (size_t)b * TT * 8 + (s0 >> 6);
    uint2* hph = (uint2*)(g_hwh + (size_t)b * TT * KHW + s0);
    uint2* hpl = (uint2*)(g_hwl + (size_t)b * TT * KHW + s0);
    const bool cload = (i >= 64);
    const int crow = (i - 64) >> 3, ccol = (i - 64) & 7;
    const float* cp = cload ? (g_C + (size_t)b * TT * 64 + (i - 64)) : g_C;

    float4 bx0 = *(const float4*)&bxp[0];
    float4 bx1 = *(const float4*)&bxp[NPAD];
    float av0 = alp[0];
    float av1 = alp[8];
    float creg = cload ? cp[64] : 0.0f;             // C at t=1 (C_0 never used)
    float gk[8];
#pragma unroll
    for (int k = 0; k < 8; k++) gk[k] = 0.0f;

    for (int t = 0; t < TT; ++t) {
        // ---- Phase A: coup from gk, update 4 states, publish, emit hw bf16 ----
        float c00 = fmaf(Un[0][1], gk[1], Un[0][0] * gk[0]);
        float c01 = fmaf(Un[0][3], gk[3], Un[0][2] * gk[2]);
        float c02 = fmaf(Un[0][5], gk[5], Un[0][4] * gk[4]);
        float c03 = fmaf(Un[0][7], gk[7], Un[0][6] * gk[6]);
        h0 = fmaf(An.x, h0, ((c00 + c01) + (c02 + c03)) + bx0.x);
        float c10 = fmaf(Un[1][1], gk[1], Un[1][0] * gk[0]);
        float c11 = fmaf(Un[1][3], gk[3], Un[1][2] * gk[2]);
        float c12 = fmaf(Un[1][5], gk[5], Un[1][4] * gk[4]);
        float c13 = fmaf(Un[1][7], gk[7], Un[1][6] * gk[6]);
        h1 = fmaf(An.y, h1, ((c10 + c11) + (c12 + c13)) + bx0.y);
        float c20 = fmaf(Un[2][1], gk[1], Un[2][0] * gk[0]);
        float c21 = fmaf(Un[2][3], gk[3], Un[2][2] * gk[2]);
        float c22 = fmaf(Un[2][5], gk[5], Un[2][4] * gk[4]);
        float c23 = fmaf(Un[2][7], gk[7], Un[2][6] * gk[6]);
        h2 = fmaf(An.z, h2, ((c20 + c21) + (c22 + c23)) + bx0.z);
        float c30 = fmaf(Un[3][1], gk[1], Un[3][0] * gk[0]);
        float c31 = fmaf(Un[3][3], gk[3], Un[3][2] * gk[2]);
        float c32 = fmaf(Un[3][5], gk[5], Un[3][4] * gk[4]);
        float c33 = fmaf(Un[3][7], gk[7], Un[3][6] * gk[6]);
        h3 = fmaf(An.w, h3, ((c30 + c31) + (c32 + c33)) + bx0.w);

        *(float4*)&h_s[s0] = make_float4(h0, h1, h2, h3);
        if (cload) cbuf[(t + 1) & 1][crow * 12 + ccol] = creg;

        // off-path: hw emit + prefetch rotation
        {
            float w0 = h0 * av0, w1 = h1 * av0, w2 = h2 * av0, w3 = h3 * av0;
            float r0 = __bfloat162float(__float2bfloat16_rn(w0));
            float r1 = __bfloat162float(__float2bfloat16_rn(w1));
            float r2 = __bfloat162float(__float2bfloat16_rn(w2));
            float r3 = __bfloat162float(__float2bfloat16_rn(w3));
            uint2 oh, ol;
            oh.x = bf16x2_pack(w0, w1); oh.y = bf16x2_pack(w2, w3);
            ol.x = bf16x2_pack(w0 - r0, w1 - r1); ol.y = bf16x2_pack(w2 - r2, w3 - r3);
            hph[(size_t)t * (KHW / 4)] = oh;
            hpl[(size_t)t * (KHW / 4)] = ol;
        }
        bx0 = bx1; av0 = av1;
        const int tp = (t + 2 < TT) ? (t + 2) : (TT - 1);
        bx1 = *(const float4*)&bxp[(size_t)tp * NPAD];
        av1 = alp[(size_t)tp * 8];
        if (cload) creg = cp[(size_t)tp * 64];
        __syncwarp();

        // ---- Phase R: partial of V^T h for k=kq over own-warp 32 states ----
        const float* hb = &h_s[grp * 32];
        float a0 = 0.0f, a1 = 0.0f, a2 = 0.0f, a3 = 0.0f;
#pragma unroll
        for (int q = 0; q < 8; q++) {
            float4 hv = *(const float4*)&hb[q * 4];
            float* ap = (q & 2) ? ((q & 1) ? &a3 : &a2) : ((q & 1) ? &a1 : &a0);
            float t0 = fmaf(Vv[q * 4 + 1], hv.y, Vv[q * 4] * hv.x);
            float t1 = fmaf(Vv[q * 4 + 3], hv.w, Vv[q * 4 + 2] * hv.z);
            *ap += t0 + t1;
        }
        float pv = (a0 + a1) + (a2 + a3);
        pv += __shfl_xor_sync(0xffffffffu, pv, 8);
        pv += __shfl_xor_sync(0xffffffffu, pv, 16);
        if (lane < 8) part_s[t & 1][lane * 4 + warp] = pv;
        __syncthreads();

        // ---- Final: every warp reduces 4 warp-partials, computes g = C_{t+1} vh ----
        float vsum = 0.0f, gv = 0.0f;
        float4 cc0, cc1;
        if (lane < 8) {
            float4 q = *(const float4*)&part_s[t & 1][lane * 4];
            cc0 = *(const float4*)&cbuf[(t + 1) & 1][lane * 12];
            cc1 = *(const float4*)&cbuf[(t + 1) & 1][lane * 12 + 4];
            vsum = (q.x + q.y) + (q.z + q.w);
        }
        float vh[8];
#pragma unroll
        for (int j = 0; j < 8; j++) vh[j] = __shfl_sync(0xffffffffu, vsum, j);
        if (lane < 8) {
            float d0 = fmaf(cc0.y, vh[1], cc0.x * vh[0]);
            float d1 = fmaf(cc0.w, vh[3], cc0.z * vh[2]);
            float d2 = fmaf(cc1.y, vh[5], cc1.x * vh[4]);
            float d3 = fmaf(cc1.w, vh[7], cc1.z * vh[6]);
            gv = (d0 + d1) + (d2 + d3);
        }
#pragma unroll
        for (int k = 0; k < 8; k++) gk[k] = __shfl_sync(0xffffffffu, gv, k);
    }
}

// ---------------- launch ----------------
extern "C" void kernel_launch(void* const* d_in, const int* in_sizes, int n_in,
                              void* d_out, int out_size) {
    const float* x      = (const float*)d_in[0];
    const float* Wb     = (const float*)d_in[1];
    const float* bb     = (const float*)d_in[2];
    const float* Wdiag  = (const float*)d_in[3];
    const float* bdiag  = (const float*)d_in[4];
    const float* Woff   = (const float*)d_in[5];
    const float* boff   = (const float*)d_in[6];
    const float* Walpha = (const float*)d_in[7];
    const float* balpha = (const float*)d_in[8];
    const float* Wc     = (const float*)d_in[9];
    const float* bc     = (const float*)d_in[10];
    const float* ll     = (const float*)d_in[11];
    const float* U      = (const float*)d_in[12];
    const float* V      = (const float*)d_in[13];
    float* out = (float*)d_out;

    float *pP, *pbpack;
    __nv_bfloat16 *pxh, *pxl, *pWh, *pWl, *phwh, *phwl, *pW2h, *pW2l;
    cudaGetSymbolAddress((void**)&pP,     g_P);
    cudaGetSymbolAddress((void**)&pbpack, g_bpack);
    cudaGetSymbolAddress((void**)&pxh,    g_xh);
    cudaGetSymbolAddress((void**)&pxl,    g_xl);
    cudaGetSymbolAddress((void**)&pWh,    g_Wh);
    cudaGetSymbolAddress((void**)&pWl,    g_Wl);
    cudaGetSymbolAddress((void**)&phwh,   g_hwh);
    cudaGetSymbolAddress((void**)&phwl,   g_hwl);
    cudaGetSymbolAddress((void**)&pW2h,   g_W2h);
    cudaGetSymbolAddress((void**)&pW2l,   g_W2l);

    cudaFuncSetAttribute(gemm_bf16x3_mma, cudaFuncAttributeMaxDynamicSharedMemorySize, GSMEM);

    conv_x_kernel<<<(ROWS * DM / 4 + 255) / 256, 256>>>((const float4*)x, (uint2*)pxh,
                                                        (uint2*)pxl, ROWS * DM / 4);
    pack1b_kernel<<<(DM * NPAD + 255) / 256, 256>>>(Wb, Wdiag, Woff, Walpha);
    pack2b_kernel<<<(KHW * DM + 255) / 256, 256>>>(Wc, bc);
    misc_kernel<<<1, 1024>>>(bb, bdiag, boff, balpha, ll);

    // GEMM1: P = x @ Wpack + bpack   (M=16384, N=640, K=1024)
    gemm_bf16x3_mma<<<dim3(NPAD / 128, ROWS / 128), 256, GSMEM>>>(pxh, pxl, pWh, pWl,
                                                                  pbpack, pP, DM, NPAD);

    act_kernel<<<ROWS / 64, 256>>>();

    scan_kernel<<<BB, 128>>>(U, V);

    // GEMM2: out = hw @ W2           (M=16384, N=1024, K=576)
    gemm_bf16x3_mma<<<dim3(DM / 128, ROWS / 128), 256, GSMEM>>>(phwh, phwl, pW2h, pW2l,
                                                                nullptr, out, KHW, DM);
}

// round 8
// speedup vs baseline: 1.6502x; 1.0730x over previous
#include <cuda_runtime.h>
#include <cuda_bf16.h>
#include <cstdint>
#include <math.h>

#define BB 8
#define TT 2048
#define DM 1024
#define NS 512
#define NPAD 640
#define NHW 520
#define KHW 576                 // padded K for GEMM2 (18 x 32)
#define ROWS (BB*TT)            // 16384

// ---------------- scratch (static device globals; no dynamic alloc) ----------------
__device__ float g_P[ROWS * NPAD];              // GEMM1 output fp32
__device__ float g_C[ROWS * 64];                // C matrices (b,t,8,8)
__device__ float g_alpha[ROWS * 8];
__device__ float g_bpack[NPAD];                 // packed biases
__device__ float g_A[NS];
__device__ __nv_bfloat16 g_xh[ROWS * DM];       // x split hi/lo, [M][K]
__device__ __nv_bfloat16 g_xl[ROWS * DM];
__device__ __nv_bfloat16 g_Wh[DM * NPAD];       // Wpack [K=1024][N=640] hi/lo
__device__ __nv_bfloat16 g_Wl[DM * NPAD];
__device__ __nv_bfloat16 g_hwh[ROWS * KHW];     // [h*alpha | alpha | 0pad] hi, bf16
__device__ __nv_bfloat16 g_hwl[ROWS * KHW];     // lo residual
__device__ __nv_bfloat16 g_W2h[KHW * DM];       // W2 [K=576][N=1024] hi/lo
__device__ __nv_bfloat16 g_W2l[KHW * DM];

// ---------------- helpers ----------------
__device__ __forceinline__ uint32_t smem_u32(const void* p) {
    uint32_t a;
    asm("{ .reg .u64 t; cvta.to.shared.u64 t, %1; cvt.u32.u64 %0, t; }" : "=r"(a) : "l"(p));
    return a;
}
__device__ __forceinline__ void cp16(uint32_t dst, const void* src) {
    asm volatile("cp.async.cg.shared.global [%0], [%1], 16;" :: "r"(dst), "l"(src));
}
__device__ __forceinline__ void ldsm4(uint32_t* r, uint32_t addr) {
    asm volatile("ldmatrix.sync.aligned.m8n8.x4.shared.b16 {%0,%1,%2,%3}, [%4];"
                 : "=r"(r[0]), "=r"(r[1]), "=r"(r[2]), "=r"(r[3]) : "r"(addr));
}
__device__ __forceinline__ void ldsm4t(uint32_t* r, uint32_t addr) {
    asm volatile("ldmatrix.sync.aligned.m8n8.x4.trans.shared.b16 {%0,%1,%2,%3}, [%4];"
                 : "=r"(r[0]), "=r"(r[1]), "=r"(r[2]), "=r"(r[3]) : "r"(addr));
}
__device__ __forceinline__ void mma16816(float* d, const uint32_t* a, const uint32_t* b) {
    asm volatile(
        "mma.sync.aligned.m16n8k16.row.col.f32.bf16.bf16.f32 "
        "{%0,%1,%2,%3}, {%4,%5,%6,%7}, {%8,%9}, {%0,%1,%2,%3};\n"
        : "+f"(d[0]), "+f"(d[1]), "+f"(d[2]), "+f"(d[3])
        : "r"(a[0]), "r"(a[1]), "r"(a[2]), "r"(a[3]), "r"(b[0]), "r"(b[1]));
}
__device__ __forceinline__ uint32_t bf16x2_pack(float a, float b) {
    __nv_bfloat162 p = __nv_bfloat162(__float2bfloat16_rn(a), __float2bfloat16_rn(b));
    return *(uint32_t*)&p;
}

// smem stage layout (bytes): Ah | Al | Bh | Bl, padded strides for conflict-free ldmatrix
#define ASTR 40
#define BSTR 136
#define A_BYTES (128 * ASTR * 2)
#define B_BYTES (32 * BSTR * 2)
#define OFF_AH 0
#define OFF_AL A_BYTES
#define OFF_BH (2 * A_BYTES)
#define OFF_BL (2 * A_BYTES + B_BYTES)
#define STG (2 * A_BYTES + 2 * B_BYTES)
#define GSMEM (3 * STG)

// ---------------- bf16x3 mma.sync GEMM: D[M,N] = A[M,K] @ B[K,N] (+bias) ----------------
__global__ void __launch_bounds__(256, 1)
gemm_bf16x3_mma(const __nv_bfloat16* __restrict__ Ah, const __nv_bfloat16* __restrict__ Al,
                const __nv_bfloat16* __restrict__ Bh, const __nv_bfloat16* __restrict__ Bl,
                const float* __restrict__ bias, float* __restrict__ D, int K, int N)
{
    extern __shared__ char smem[];
    const uint32_t sbase = smem_u32(smem);
    const int tid = threadIdx.x;
    const int lane = tid & 31, w = tid >> 5;
    const int wm = w & 1, wn = w >> 1;
    const int m0 = blockIdx.y * 128;
    const int n0 = blockIdx.x * 128;
    const int NC = K >> 5;

    float acc[4][4][4];
#pragma unroll
    for (int i = 0; i < 4; i++)
#pragma unroll
        for (int j = 0; j < 4; j++)
#pragma unroll
            for (int q = 0; q < 4; q++) acc[i][j][q] = 0.0f;

    const int ar = tid >> 2, as = tid & 3;
    const int br = tid >> 4, bs = tid & 15;

    auto load_stage = [&](int s, int c) {
        const uint32_t st = sbase + s * STG;
        const long kc = (long)c * 32;
        cp16(st + OFF_AH + ar * 80 + as * 16,        Ah + (long)(m0 + ar) * K + kc + as * 8);
        cp16(st + OFF_AH + (ar + 64) * 80 + as * 16, Ah + (long)(m0 + ar + 64) * K + kc + as * 8);
        cp16(st + OFF_AL + ar * 80 + as * 16,        Al + (long)(m0 + ar) * K + kc + as * 8);
        cp16(st + OFF_AL + (ar + 64) * 80 + as * 16, Al + (long)(m0 + ar + 64) * K + kc + as * 8);
        cp16(st + OFF_BH + br * 272 + bs * 16,        Bh + (kc + br) * (long)N + n0 + bs * 8);
        cp16(st + OFF_BH + (br + 16) * 272 + bs * 16, Bh + (kc + br + 16) * (long)N + n0 + bs * 8);
        cp16(st + OFF_BL + br * 272 + bs * 16,        Bl + (kc + br) * (long)N + n0 + bs * 8);
        cp16(st + OFF_BL + (br + 16) * 272 + bs * 16, Bl + (kc + br + 16) * (long)N + n0 + bs * 8);
        asm volatile("cp.async.commit_group;");
    };

    const int pre = (NC < 3) ? NC : 3;
    for (int s = 0; s < pre; s++) load_stage(s, s);

    const uint32_t a_off = (uint32_t)(((wm * 64 + (lane & 15)) * ASTR + ((lane >> 4) << 3)) * 2);
    const uint32_t b_off = (uint32_t)((((lane & 15)) * BSTR + wn * 32 + ((lane >> 4) << 3)) * 2);

    int s = 0;
    for (int kt = 0; kt < NC; ++kt) {
        const int pend = ((NC - kt) < 3 ? (NC - kt) : 3);
        if (pend == 3)      asm volatile("cp.async.wait_group 2;");
        else if (pend == 2) asm volatile("cp.async.wait_group 1;");
        else                asm volatile("cp.async.wait_group 0;");
        __syncthreads();

        const uint32_t st = sbase + s * STG;
        const uint32_t ah_b = st + OFF_AH + a_off;
        const uint32_t al_b = st + OFF_AL + a_off;
        const uint32_t bh_b = st + OFF_BH + b_off;
        const uint32_t bl_b = st + OFF_BL + b_off;

#pragma unroll
        for (int kk = 0; kk < 2; ++kk) {
            uint32_t af[4][4], lf[4][4], bf[2][4], gf[2][4];
#pragma unroll
            for (int mt = 0; mt < 4; mt++) {
                ldsm4(af[mt], ah_b + (mt * 16 * ASTR + kk * 16) * 2);
                ldsm4(lf[mt], al_b + (mt * 16 * ASTR + kk * 16) * 2);
            }
#pragma unroll
            for (int np = 0; np < 2; np++) {
                ldsm4t(bf[np], bh_b + (kk * 16 * BSTR + np * 16) * 2);
                ldsm4t(gf[np], bl_b + (kk * 16 * BSTR + np * 16) * 2);
            }
#pragma unroll
            for (int mt = 0; mt < 4; mt++) {
#pragma unroll
                for (int nt = 0; nt < 4; nt++) {
                    const uint32_t* bp = &bf[nt >> 1][(nt & 1) * 2];
                    const uint32_t* lp = &gf[nt >> 1][(nt & 1) * 2];
                    mma16816(acc[mt][nt], af[mt], bp);
                    mma16816(acc[mt][nt], lf[mt], bp);
                    mma16816(acc[mt][nt], af[mt], lp);
                }
            }
        }
        __syncthreads();
        const int cn = kt + 3;
        if (cn < NC) load_stage(s, cn);
        if (++s == 3) s = 0;
    }

    const int rb = m0 + wm * 64 + (lane >> 2);
    const int cb = n0 + wn * 32 + (lane & 3) * 2;
#pragma unroll
    for (int mt = 0; mt < 4; mt++) {
#pragma unroll
        for (int nt = 0; nt < 4; nt++) {
            const int r = rb + mt * 16;
            const int c = cb + nt * 8;
            float b0 = 0.0f, b1 = 0.0f;
            if (bias) { b0 = bias[c]; b1 = bias[c + 1]; }
            float2 o0 = make_float2(acc[mt][nt][0] + b0, acc[mt][nt][1] + b1);
            float2 o1 = make_float2(acc[mt][nt][2] + b0, acc[mt][nt][3] + b1);
            *(float2*)(D + (size_t)r * N + c) = o0;
            *(float2*)(D + (size_t)(r + 8) * N + c) = o1;
        }
    }
}

// ---------------- conversion / packing kernels ----------------
__global__ void conv_x_kernel(const float4* __restrict__ src, uint2* __restrict__ dh,
                              uint2* __restrict__ dl, int n4) {
    int i = blockIdx.x * blockDim.x + threadIdx.x;
    if (i >= n4) return;
    float4 v = src[i];
    float hx = __bfloat162float(__float2bfloat16_rn(v.x));
    float hy = __bfloat162float(__float2bfloat16_rn(v.y));
    float hz = __bfloat162float(__float2bfloat16_rn(v.z));
    float hw = __bfloat162float(__float2bfloat16_rn(v.w));
    uint2 oh, ol;
    oh.x = bf16x2_pack(v.x, v.y); oh.y = bf16x2_pack(v.z, v.w);
    ol.x = bf16x2_pack(v.x - hx, v.y - hy); ol.y = bf16x2_pack(v.z - hz, v.w - hw);
    dh[i] = oh; dl[i] = ol;
}

__global__ void pack1b_kernel(const float* __restrict__ Wb, const float* __restrict__ Wdiag,
                              const float* __restrict__ Woff, const float* __restrict__ Walpha) {
    int idx = blockIdx.x * blockDim.x + threadIdx.x;
    if (idx >= DM * NPAD) return;
    int r = idx / NPAD, c = idx - r * NPAD;
    float v;
    if (c < 512)       v = Wb[r * NS + c];
    else if (c < 520)  v = Wdiag[r * 8 + (c - 512)];
    else if (c < 576)  v = Woff[r * 56 + (c - 520)];
    else if (c < 584)  v = Walpha[r * 8 + (c - 576)];
    else               v = 0.0f;
    __nv_bfloat16 h = __float2bfloat16_rn(v);
    g_Wh[idx] = h;
    g_Wl[idx] = __float2bfloat16_rn(v - __bfloat162float(h));
}

__global__ void pack2b_kernel(const float* __restrict__ Wc, const float* __restrict__ bc) {
    int idx = blockIdx.x * blockDim.x + threadIdx.x;
    if (idx >= KHW * DM) return;
    int k = idx >> 10, n = idx & 1023;
    float v;
    if (k < 512)      v = Wc[idx];
    else if (k < 520) v = bc[(size_t)(k - 512) * DM + n];
    else              v = 0.0f;
    __nv_bfloat16 h = __float2bfloat16_rn(v);
    g_W2h[idx] = h;
    g_W2l[idx] = __float2bfloat16_rn(v - __bfloat162float(h));
}

__global__ void misc_kernel(const float* __restrict__ bb, const float* __restrict__ bdiag,
                            const float* __restrict__ boff, const float* __restrict__ balpha,
                            const float* __restrict__ log_lambda) {
    int tid = threadIdx.x;
    if (tid < NS) {
        int k = tid >> 6;
        double dt = 1e-3 * exp((double)k * log(1000.0) / 7.0);
        double ll = (double)log_lambda[tid];
        double sp = log1p(exp(ll));
        g_A[tid] = (float)exp(-dt * sp);
    }
    if (tid < NPAD) {
        float v;
        if (tid < 512)       v = bb[tid];
        else if (tid < 520)  v = bdiag[tid - 512];
        else if (tid < 576)  v = boff[tid - 520];
        else if (tid < 584)  v = balpha[tid - 576];
        else                 v = 0.0f;
        g_bpack[tid] = v;
    }
}

// ---------------- activations: C, alpha; write alpha tail + zero pad into hwh/hwl ----------------
__global__ void __launch_bounds__(256) act_kernel(void) {
    __shared__ float s[64 * 72];
    const int row0 = blockIdx.x * 64;
    const int tid = threadIdx.x;
    for (int i = tid; i < 64 * 72; i += 256) {
        int r = i / 72, c = i - r * 72;
        s[i] = g_P[(size_t)(row0 + r) * NPAD + 512 + c];
    }
    __syncthreads();
    if (tid < 64) {
        const int row = row0 + tid;
        const float* v = &s[tid * 72];
        float dg[8];
#pragma unroll
        for (int i = 0; i < 8; i++) dg[i] = 1.0f / (1.0f + expf(-v[i]));
        float Cm[64];
        int m = 0;
#pragma unroll
        for (int i = 0; i < 8; i++) {
#pragma unroll
            for (int j = 0; j < 8; j++) {
                if (i == j) {
                    Cm[i * 8 + j] = dg[i];
                } else {
                    float x = v[8 + m];
                    float sp = (x > 15.0f) ? x : log1pf(expf(x));
                    Cm[i * 8 + j] = -sp;
                    m++;
                }
            }
        }
#pragma unroll
        for (int q = 0; q < 64; q++) g_C[(size_t)row * 64 + q] = Cm[q];
        float a[8], mx = v[64];
#pragma unroll
        for (int i = 1; i < 8; i++) mx = fmaxf(mx, v[64 + i]);
        float sum = 0.0f;
#pragma unroll
        for (int i = 0; i < 8; i++) { a[i] = expf(v[64 + i] - mx); sum += a[i]; }
        float inv = 1.0f / sum;
#pragma unroll
        for (int k = 0; k < 8; k++) {
            float al = a[k] * inv;
            g_alpha[(size_t)row * 8 + k] = al;
            __nv_bfloat16 h = __float2bfloat16_rn(al);
            g_hwh[(size_t)row * KHW + 512 + k] = h;
            g_hwl[(size_t)row * KHW + 512 + k] = __float2bfloat16_rn(al - __bfloat162float(h));
        }
    }
    const __nv_bfloat16 z = __float2bfloat16_rn(0.0f);
    for (int i = tid; i < 64 * 56; i += 256) {
        int r = i / 56, c = i - r * 56;
        g_hwh[(size_t)(row0 + r) * KHW + 520 + c] = z;
        g_hwl[(size_t)(row0 + r) * KHW + 520 + c] = z;
    }
}

// ---------------- warp-specialized scan: 4 compute warps + 4 emitter warps ----------------
// Compute warps (tid<128, 4 states/thread): pure recurrence, zero gmem traffic.
// Emitter warps (tid>=128): emit hw bf16 from h_s, stage bx into bxbuf (2 ahead) and
// C into cstage (3 ahead) via their own register prefetch (1 step earlier).
// One __syncthreads per step for all 8 warps; h_s double-buffered.
__global__ void __launch_bounds__(256, 1) scan_kernel(const float* __restrict__ Uw,
                                                      const float* __restrict__ Vw) {
    __shared__ __align__(16) float h_s[2][NS];
    __shared__ __align__(16) float part_s[2][32];    // [buf][k*4 + warp]
    __shared__ __align__(16) float cstage[4][96];    // C rows, stride 12
    __shared__ __align__(16) float bxbuf[4][NS];

    const int b = blockIdx.x;
    const int i = threadIdx.x;

    // ---- prefill: bx_0, bx_1; C_1, C_2 ----
    {
        const float* bx0p = g_P + (size_t)b * TT * NPAD;
        for (int j = i; j < NS; j += 256) {
            bxbuf[0][j] = bx0p[j];
            bxbuf[1][j] = bx0p[NPAD + j];
        }
        if (i < 64) {
            const float* cb = g_C + (size_t)b * TT * 64;
            cstage[1][(i >> 3) * 12 + (i & 7)] = cb[64 + i];
            cstage[2][(i >> 3) * 12 + (i & 7)] = cb[128 + i];
        }
    }
    __syncthreads();

    if (i < 128) {
        // ================= compute warps =================
        const int lane = i & 31, warp = i >> 5;
        const int kq = i & 7, grp = i >> 3;
        const int s0 = 4 * i;

        float h0 = 0.0f, h1 = 0.0f, h2 = 0.0f, h3 = 0.0f;
        const float4 An = *(const float4*)&g_A[s0];
        float Un[4][8];
#pragma unroll
        for (int s = 0; s < 4; s++)
#pragma unroll
            for (int k = 0; k < 8; k++) Un[s][k] = Uw[(s0 + s) * 8 + k];
        float Vv[32];
#pragma unroll
        for (int j = 0; j < 32; j++) Vv[j] = Vw[(grp * 32 + j) * 8 + kq];

        float gk[8];
#pragma unroll
        for (int k = 0; k < 8; k++) gk[k] = 0.0f;

        for (int t = 0; t < TT; ++t) {
            const float4 bx = *(const float4*)&bxbuf[t & 3][s0];
            float c00 = fmaf(Un[0][1], gk[1], Un[0][0] * gk[0]);
            float c01 = fmaf(Un[0][3], gk[3], Un[0][2] * gk[2]);
            float c02 = fmaf(Un[0][5], gk[5], Un[0][4] * gk[4]);
            float c03 = fmaf(Un[0][7], gk[7], Un[0][6] * gk[6]);
            h0 = fmaf(An.x, h0, ((c00 + c01) + (c02 + c03)) + bx.x);
            float c10 = fmaf(Un[1][1], gk[1], Un[1][0] * gk[0]);
            float c11 = fmaf(Un[1][3], gk[3], Un[1][2] * gk[2]);
            float c12 = fmaf(Un[1][5], gk[5], Un[1][4] * gk[4]);
            float c13 = fmaf(Un[1][7], gk[7], Un[1][6] * gk[6]);
            h1 = fmaf(An.y, h1, ((c10 + c11) + (c12 + c13)) + bx.y);
            float c20 = fmaf(Un[2][1], gk[1], Un[2][0] * gk[0]);
            float c21 = fmaf(Un[2][3], gk[3], Un[2][2] * gk[2]);
            float c22 = fmaf(Un[2][5], gk[5], Un[2][4] * gk[4]);
            float c23 = fmaf(Un[2][7], gk[7], Un[2][6] * gk[6]);
            h2 = fmaf(An.z, h2, ((c20 + c21) + (c22 + c23)) + bx.z);
            float c30 = fmaf(Un[3][1], gk[1], Un[3][0] * gk[0]);
            float c31 = fmaf(Un[3][3], gk[3], Un[3][2] * gk[2]);
            float c32 = fmaf(Un[3][5], gk[5], Un[3][4] * gk[4]);
            float c33 = fmaf(Un[3][7], gk[7], Un[3][6] * gk[6]);
            h3 = fmaf(An.w, h3, ((c30 + c31) + (c32 + c33)) + bx.w);

            *(float4*)&h_s[t & 1][s0] = make_float4(h0, h1, h2, h3);
            __syncwarp();

            // phase R: V^T h partial for k=kq over own-warp 32 states
            const float* hb = &h_s[t & 1][grp * 32];
            float a0 = 0.0f, a1 = 0.0f, a2 = 0.0f, a3 = 0.0f;
#pragma unroll
            for (int q = 0; q < 8; q++) {
                float4 hv = *(const float4*)&hb[q * 4];
                float t0 = fmaf(Vv[q * 4 + 1], hv.y, Vv[q * 4] * hv.x);
                float t1 = fmaf(Vv[q * 4 + 3], hv.w, Vv[q * 4 + 2] * hv.z);
                float tq = t0 + t1;
                if (q == 0) a0 += tq; else if (q == 1) a1 += tq;
                else if (q == 2) a2 += tq; else if (q == 3) a3 += tq;
                else if (q == 4) a0 += tq; else if (q == 5) a1 += tq;
                else if (q == 6) a2 += tq; else a3 += tq;
            }
            float pv = (a0 + a1) + (a2 + a3);
            pv += __shfl_xor_sync(0xffffffffu, pv, 8);
            pv += __shfl_xor_sync(0xffffffffu, pv, 16);
            if (lane < 8) part_s[t & 1][lane * 4 + warp] = pv;
            __syncthreads();

            // final: reduce partials, g = C_{t+1} * vh
            float vsum = 0.0f, gv = 0.0f;
            float4 cc0, cc1;
            if (lane < 8) {
                float4 q = *(const float4*)&part_s[t & 1][lane * 4];
                cc0 = *(const float4*)&cstage[(t + 1) & 3][lane * 12];
                cc1 = *(const float4*)&cstage[(t + 1) & 3][lane * 12 + 4];
                vsum = (q.x + q.y) + (q.z + q.w);
            }
            float vh[8];
#pragma unroll
            for (int j = 0; j < 8; j++) vh[j] = __shfl_sync(0xffffffffu, vsum, j);
            if (lane < 8) {
                float d0 = fmaf(cc0.y, vh[1], cc0.x * vh[0]);
                float d1 = fmaf(cc0.w, vh[3], cc0.z * vh[2]);
                float d2 = fmaf(cc1.y, vh[5], cc1.x * vh[4]);
                float d3 = fmaf(cc1.w, vh[7], cc1.z * vh[6]);
                gv = (d0 + d1) + (d2 + d3);
            }
#pragma unroll
            for (int k = 0; k < 8; k++) gk[k] = __shfl_sync(0xffffffffu, gv, k);
        }
    } else {
        // ================= emitter warps =================
        const int i2 = i - 128;                  // 0..127
        const int e0 = 4 * i2;
        const float* alp = g_alpha + (size_t)b * TT * 8 + (e0 >> 6);
        uint2* eph = (uint2*)(g_hwh + (size_t)b * TT * KHW + e0);
        uint2* epl = (uint2*)(g_hwl + (size_t)b * TT * KHW + e0);
        const float* bxp = g_P + (size_t)b * TT * NPAD + e0;
        const bool cload = (i2 < 64);
        const float* cp = g_C + (size_t)b * TT * 64 + (cload ? i2 : 0);
        const int crow = (i2 >> 3) & 7, ccol = i2 & 7;

        float4 bxreg = *(const float4*)&bxp[(size_t)2 * NPAD];    // bx_2
        float creg = cload ? cp[3 * 64] : 0.0f;                   // C_3
        float av0 = alp[0];
        float av1 = alp[8];

        for (int t = 0; t < TT; ++t) {
            __syncthreads();
            // emit hw_t from h_s[t&1]
            float4 hv = *(const float4*)&h_s[t & 1][e0];
            float w0 = hv.x * av0, w1 = hv.y * av0, w2 = hv.z * av0, w3 = hv.w * av0;
            float r0 = __bfloat162float(__float2bfloat16_rn(w0));
            float r1 = __bfloat162float(__float2bfloat16_rn(w1));
            float r2 = __bfloat162float(__float2bfloat16_rn(w2));
            float r3 = __bfloat162float(__float2bfloat16_rn(w3));
            uint2 oh, ol;
            oh.x = bf16x2_pack(w0, w1); oh.y = bf16x2_pack(w2, w3);
            ol.x = bf16x2_pack(w0 - r0, w1 - r1); ol.y = bf16x2_pack(w2 - r2, w3 - r3);
            eph[(size_t)t * (KHW / 4)] = oh;
            epl[(size_t)t * (KHW / 4)] = ol;

            // stage prefetched data for compute warps
            *(float4*)&bxbuf[(t + 2) & 3][e0] = bxreg;
            if (cload) cstage[(t + 3) & 3][crow * 12 + ccol] = creg;

            // issue next prefetches (consumed next step)
            const int tb = (t + 3 < TT) ? (t + 3) : (TT - 1);
            bxreg = *(const float4*)&bxp[(size_t)tb * NPAD];
            if (cload) {
                const int tc = (t + 4 < TT) ? (t + 4) : (TT - 1);
                creg = cp[(size_t)tc * 64];
            }
            av0 = av1;
            const int ta = (t + 2 < TT) ? (t + 2) : (TT - 1);
            av1 = alp[(size_t)ta * 8];
        }
    }
}

// ---------------- launch ----------------
extern "C" void kernel_launch(void* const* d_in, const int* in_sizes, int n_in,
                              void* d_out, int out_size) {
    const float* x      = (const float*)d_in[0];
    const float* Wb     = (const float*)d_in[1];
    const float* bb     = (const float*)d_in[2];
    const float* Wdiag  = (const float*)d_in[3];
    const float* bdiag  = (const float*)d_in[4];
    const float* Woff   = (const float*)d_in[5];
    const float* boff   = (const float*)d_in[6];
    const float* Walpha = (const float*)d_in[7];
    const float* balpha = (const float*)d_in[8];
    const float* Wc     = (const float*)d_in[9];
    const float* bc     = (const float*)d_in[10];
    const float* ll     = (const float*)d_in[11];
    const float* U      = (const float*)d_in[12];
    const float* V      = (const float*)d_in[13];
    float* out = (float*)d_out;

    float *pP, *pbpack;
    __nv_bfloat16 *pxh, *pxl, *pWh, *pWl, *phwh, *phwl, *pW2h, *pW2l;
    cudaGetSymbolAddress((void**)&pP,     g_P);
    cudaGetSymbolAddress((void**)&pbpack, g_bpack);
    cudaGetSymbolAddress((void**)&pxh,    g_xh);
    cudaGetSymbolAddress((void**)&pxl,    g_xl);
    cudaGetSymbolAddress((void**)&pWh,    g_Wh);
    cudaGetSymbolAddress((void**)&pWl,    g_Wl);
    cudaGetSymbolAddress((void**)&phwh,   g_hwh);
    cudaGetSymbolAddress((void**)&phwl,   g_hwl);
    cudaGetSymbolAddress((void**)&pW2h,   g_W2h);
    cudaGetSymbolAddress((void**)&pW2l,   g_W2l);

    cudaFuncSetAttribute(gemm_bf16x3_mma, cudaFuncAttributeMaxDynamicSharedMemorySize, GSMEM);

    conv_x_kernel<<<(ROWS * DM / 4 + 255) / 256, 256>>>((const float4*)x, (uint2*)pxh,
                                                        (uint2*)pxl, ROWS * DM / 4);
    pack1b_kernel<<<(DM * NPAD + 255) / 256, 256>>>(Wb, Wdiag, Woff, Walpha);
    pack2b_kernel<<<(KHW * DM + 255) / 256, 256>>>(Wc, bc);
    misc_kernel<<<1, 1024>>>(bb, bdiag, boff, balpha, ll);

    // GEMM1: P = x @ Wpack + bpack   (M=16384, N=640, K=1024)
    gemm_bf16x3_mma<<<dim3(NPAD / 128, ROWS / 128), 256, GSMEM>>>(pxh, pxl, pWh, pWl,
                                                                  pbpack, pP, DM, NPAD);

    act_kernel<<<ROWS / 64, 256>>>();

    scan_kernel<<<BB, 256>>>(U, V);

    // GEMM2: out = hw @ W2           (M=16384, N=1024, K=576)
    gemm_bf16x3_mma<<<dim3(DM / 128, ROWS / 128), 256, GSMEM>>>(phwh, phwl, pW2h, pW2l,
                                                                nullptr, out, KHW, DM);
}

// round 9
// speedup vs baseline: 1.7887x; 1.0839x over previous
#include <cuda_runtime.h>
#include <cuda_bf16.h>
#include <cstdint>
#include <math.h>

#define BB 8
#define TT 2048
#define DM 1024
#define NS 512
#define NPAD 640
#define NHW 520
#define KHW 576                 // padded K for GEMM2 (18 x 32)
#define ROWS (BB*TT)            // 16384
#define NCH 256                 // chunks of 8 steps

// ---------------- scratch (static device globals; no dynamic alloc) ----------------
__device__ float g_P[ROWS * NPAD];              // GEMM1 output fp32
__device__ float g_C[ROWS * 64];                // C matrices (b,t,8,8)
__device__ float g_alpha[ROWS * 8];
__device__ float g_bpack[NPAD];                 // packed biases
__device__ float g_A[NS];
__device__ float g_W8[512];                     // W_d = V^T diag(a^d) U, d=0..7, [d][r][c]
__device__ __nv_bfloat16 g_xh[ROWS * DM];       // x split hi/lo, [M][K]
__device__ __nv_bfloat16 g_xl[ROWS * DM];
__device__ __nv_bfloat16 g_Wh[DM * NPAD];       // Wpack [K=1024][N=640] hi/lo
__device__ __nv_bfloat16 g_Wl[DM * NPAD];
__device__ __nv_bfloat16 g_hwh[ROWS * KHW];     // [h*alpha | alpha | 0pad] hi, bf16
__device__ __nv_bfloat16 g_hwl[ROWS * KHW];     // lo residual
__device__ __nv_bfloat16 g_W2h[KHW * DM];       // W2 [K=576][N=1024] hi/lo
__device__ __nv_bfloat16 g_W2l[KHW * DM];

// ---------------- helpers ----------------
__device__ __forceinline__ uint32_t smem_u32(const void* p) {
    uint32_t a;
    asm("{ .reg .u64 t; cvta.to.shared.u64 t, %1; cvt.u32.u64 %0, t; }" : "=r"(a) : "l"(p));
    return a;
}
__device__ __forceinline__ void cp16(uint32_t dst, const void* src) {
    asm volatile("cp.async.cg.shared.global [%0], [%1], 16;" :: "r"(dst), "l"(src));
}
__device__ __forceinline__ void ldsm4(uint32_t* r, uint32_t addr) {
    asm volatile("ldmatrix.sync.aligned.m8n8.x4.shared.b16 {%0,%1,%2,%3}, [%4];"
                 : "=r"(r[0]), "=r"(r[1]), "=r"(r[2]), "=r"(r[3]) : "r"(addr));
}
__device__ __forceinline__ void ldsm4t(uint32_t* r, uint32_t addr) {
    asm volatile("ldmatrix.sync.aligned.m8n8.x4.trans.shared.b16 {%0,%1,%2,%3}, [%4];"
                 : "=r"(r[0]), "=r"(r[1]), "=r"(r[2]), "=r"(r[3]) : "r"(addr));
}
__device__ __forceinline__ void mma16816(float* d, const uint32_t* a, const uint32_t* b) {
    asm volatile(
        "mma.sync.aligned.m16n8k16.row.col.f32.bf16.bf16.f32 "
        "{%0,%1,%2,%3}, {%4,%5,%6,%7}, {%8,%9}, {%0,%1,%2,%3};\n"
        : "+f"(d[0]), "+f"(d[1]), "+f"(d[2]), "+f"(d[3])
        : "r"(a[0]), "r"(a[1]), "r"(a[2]), "r"(a[3]), "r"(b[0]), "r"(b[1]));
}
__device__ __forceinline__ uint32_t bf16x2_pack(float a, float b) {
    __nv_bfloat162 p = __nv_bfloat162(__float2bfloat16_rn(a), __float2bfloat16_rn(b));
    return *(uint32_t*)&p;
}
__device__ __forceinline__ float dot8v(float4 a0, float4 a1, const float* m) {
    float t0 = fmaf(a0.y, m[1], a0.x * m[0]);
    float t1 = fmaf(a0.w, m[3], a0.z * m[2]);
    float t2 = fmaf(a1.y, m[5], a1.x * m[4]);
    float t3 = fmaf(a1.w, m[7], a1.z * m[6]);
    return (t0 + t1) + (t2 + t3);
}

// smem stage layout (bytes): Ah | Al | Bh | Bl, padded strides for conflict-free ldmatrix
#define ASTR 40
#define BSTR 136
#define A_BYTES (128 * ASTR * 2)
#define B_BYTES (32 * BSTR * 2)
#define OFF_AH 0
#define OFF_AL A_BYTES
#define OFF_BH (2 * A_BYTES)
#define OFF_BL (2 * A_BYTES + B_BYTES)
#define STG (2 * A_BYTES + 2 * B_BYTES)
#define GSMEM (3 * STG)

// ---------------- bf16x3 mma.sync GEMM: D[M,N] = A[M,K] @ B[K,N] (+bias) ----------------
__global__ void __launch_bounds__(256, 1)
gemm_bf16x3_mma(const __nv_bfloat16* __restrict__ Ah, const __nv_bfloat16* __restrict__ Al,
                const __nv_bfloat16* __restrict__ Bh, const __nv_bfloat16* __restrict__ Bl,
                const float* __restrict__ bias, float* __restrict__ D, int K, int N)
{
    extern __shared__ char smem[];
    const uint32_t sbase = smem_u32(smem);
    const int tid = threadIdx.x;
    const int lane = tid & 31, w = tid >> 5;
    const int wm = w & 1, wn = w >> 1;
    const int m0 = blockIdx.y * 128;
    const int n0 = blockIdx.x * 128;
    const int NC = K >> 5;

    float acc[4][4][4];
#pragma unroll
    for (int i = 0; i < 4; i++)
#pragma unroll
        for (int j = 0; j < 4; j++)
#pragma unroll
            for (int q = 0; q < 4; q++) acc[i][j][q] = 0.0f;

    const int ar = tid >> 2, as = tid & 3;
    const int br = tid >> 4, bs = tid & 15;

    auto load_stage = [&](int s, int c) {
        const uint32_t st = sbase + s * STG;
        const long kc = (long)c * 32;
        cp16(st + OFF_AH + ar * 80 + as * 16,        Ah + (long)(m0 + ar) * K + kc + as * 8);
        cp16(st + OFF_AH + (ar + 64) * 80 + as * 16, Ah + (long)(m0 + ar + 64) * K + kc + as * 8);
        cp16(st + OFF_AL + ar * 80 + as * 16,        Al + (long)(m0 + ar) * K + kc + as * 8);
        cp16(st + OFF_AL + (ar + 64) * 80 + as * 16, Al + (long)(m0 + ar + 64) * K + kc + as * 8);
        cp16(st + OFF_BH + br * 272 + bs * 16,        Bh + (kc + br) * (long)N + n0 + bs * 8);
        cp16(st + OFF_BH + (br + 16) * 272 + bs * 16, Bh + (kc + br + 16) * (long)N + n0 + bs * 8);
        cp16(st + OFF_BL + br * 272 + bs * 16,        Bl + (kc + br) * (long)N + n0 + bs * 8);
        cp16(st + OFF_BL + (br + 16) * 272 + bs * 16, Bl + (kc + br + 16) * (long)N + n0 + bs * 8);
        asm volatile("cp.async.commit_group;");
    };

    const int pre = (NC < 3) ? NC : 3;
    for (int s = 0; s < pre; s++) load_stage(s, s);

    const uint32_t a_off = (uint32_t)(((wm * 64 + (lane & 15)) * ASTR + ((lane >> 4) << 3)) * 2);
    const uint32_t b_off = (uint32_t)((((lane & 15)) * BSTR + wn * 32 + ((lane >> 4) << 3)) * 2);

    int s = 0;
    for (int kt = 0; kt < NC; ++kt) {
        const int pend = ((NC - kt) < 3 ? (NC - kt) : 3);
        if (pend == 3)      asm volatile("cp.async.wait_group 2;");
        else if (pend == 2) asm volatile("cp.async.wait_group 1;");
        else                asm volatile("cp.async.wait_group 0;");
        __syncthreads();

        const uint32_t st = sbase + s * STG;
        const uint32_t ah_b = st + OFF_AH + a_off;
        const uint32_t al_b = st + OFF_AL + a_off;
        const uint32_t bh_b = st + OFF_BH + b_off;
        const uint32_t bl_b = st + OFF_BL + b_off;

#pragma unroll
        for (int kk = 0; kk < 2; ++kk) {
            uint32_t af[4][4], lf[4][4], bf[2][4], gf[2][4];
#pragma unroll
            for (int mt = 0; mt < 4; mt++) {
                ldsm4(af[mt], ah_b + (mt * 16 * ASTR + kk * 16) * 2);
                ldsm4(lf[mt], al_b + (mt * 16 * ASTR + kk * 16) * 2);
            }
#pragma unroll
            for (int np = 0; np < 2; np++) {
                ldsm4t(bf[np], bh_b + (kk * 16 * BSTR + np * 16) * 2);
                ldsm4t(gf[np], bl_b + (kk * 16 * BSTR + np * 16) * 2);
            }
#pragma unroll
            for (int mt = 0; mt < 4; mt++) {
#pragma unroll
                for (int nt = 0; nt < 4; nt++) {
                    const uint32_t* bp = &bf[nt >> 1][(nt & 1) * 2];
                    const uint32_t* lp = &gf[nt >> 1][(nt & 1) * 2];
                    mma16816(acc[mt][nt], af[mt], bp);
                    mma16816(acc[mt][nt], lf[mt], bp);
                    mma16816(acc[mt][nt], af[mt], lp);
                }
            }
        }
        __syncthreads();
        const int cn = kt + 3;
        if (cn < NC) load_stage(s, cn);
        if (++s == 3) s = 0;
    }

    const int rb = m0 + wm * 64 + (lane >> 2);
    const int cb = n0 + wn * 32 + (lane & 3) * 2;
#pragma unroll
    for (int mt = 0; mt < 4; mt++) {
#pragma unroll
        for (int nt = 0; nt < 4; nt++) {
            const int r = rb + mt * 16;
            const int c = cb + nt * 8;
            float b0 = 0.0f, b1 = 0.0f;
            if (bias) { b0 = bias[c]; b1 = bias[c + 1]; }
            float2 o0 = make_float2(acc[mt][nt][0] + b0, acc[mt][nt][1] + b1);
            float2 o1 = make_float2(acc[mt][nt][2] + b0, acc[mt][nt][3] + b1);
            *(float2*)(D + (size_t)r * N + c) = o0;
            *(float2*)(D + (size_t)(r + 8) * N + c) = o1;
        }
    }
}

// ---------------- conversion / packing kernels ----------------
__global__ void conv_x_kernel(const float4* __restrict__ src, uint2* __restrict__ dh,
                              uint2* __restrict__ dl, int n4) {
    int i = blockIdx.x * blockDim.x + threadIdx.x;
    if (i >= n4) return;
    float4 v = src[i];
    float hx = __bfloat162float(__float2bfloat16_rn(v.x));
    float hy = __bfloat162float(__float2bfloat16_rn(v.y));
    float hz = __bfloat162float(__float2bfloat16_rn(v.z));
    float hw = __bfloat162float(__float2bfloat16_rn(v.w));
    uint2 oh, ol;
    oh.x = bf16x2_pack(v.x, v.y); oh.y = bf16x2_pack(v.z, v.w);
    ol.x = bf16x2_pack(v.x - hx, v.y - hy); ol.y = bf16x2_pack(v.z - hz, v.w - hw);
    dh[i] = oh; dl[i] = ol;
}

__global__ void pack1b_kernel(const float* __restrict__ Wb, const float* __restrict__ Wdiag,
                              const float* __restrict__ Woff, const float* __restrict__ Walpha) {
    int idx = blockIdx.x * blockDim.x + threadIdx.x;
    if (idx >= DM * NPAD) return;
    int r = idx / NPAD, c = idx - r * NPAD;
    float v;
    if (c < 512)       v = Wb[r * NS + c];
    else if (c < 520)  v = Wdiag[r * 8 + (c - 512)];
    else if (c < 576)  v = Woff[r * 56 + (c - 520)];
    else if (c < 584)  v = Walpha[r * 8 + (c - 576)];
    else               v = 0.0f;
    __nv_bfloat16 h = __float2bfloat16_rn(v);
    g_Wh[idx] = h;
    g_Wl[idx] = __float2bfloat16_rn(v - __bfloat162float(h));
}

__global__ void pack2b_kernel(const float* __restrict__ Wc, const float* __restrict__ bc) {
    int idx = blockIdx.x * blockDim.x + threadIdx.x;
    if (idx >= KHW * DM) return;
    int k = idx >> 10, n = idx & 1023;
    float v;
    if (k < 512)      v = Wc[idx];
    else if (k < 520) v = bc[(size_t)(k - 512) * DM + n];
    else              v = 0.0f;
    __nv_bfloat16 h = __float2bfloat16_rn(v);
    g_W2h[idx] = h;
    g_W2l[idx] = __float2bfloat16_rn(v - __bfloat162float(h));
}

__global__ void misc_kernel(const float* __restrict__ bb, const float* __restrict__ bdiag,
                            const float* __restrict__ boff, const float* __restrict__ balpha,
                            const float* __restrict__ log_lambda) {
    int tid = threadIdx.x;
    if (tid < NS) {
        int k = tid >> 6;
        double dt = 1e-3 * exp((double)k * log(1000.0) / 7.0);
        double ll = (double)log_lambda[tid];
        double sp = log1p(exp(ll));
        g_A[tid] = (float)exp(-dt * sp);
    }
    if (tid < NPAD) {
        float v;
        if (tid < 512)       v = bb[tid];
        else if (tid < 520)  v = bdiag[tid - 512];
        else if (tid < 576)  v = boff[tid - 520];
        else if (tid < 584)  v = balpha[tid - 576];
        else                 v = 0.0f;
        g_bpack[tid] = v;
    }
}

// W_d[r][c] = sum_n V[n,r] * a_n^d * U[n,c], d=0..7  (runs after misc_kernel)
__global__ void wtab_kernel(const float* __restrict__ Uw, const float* __restrict__ Vw) {
    int i = threadIdx.x;
    if (i >= 512) return;
    int d = i >> 6, r = (i >> 3) & 7, c = i & 7;
    float s = 0.0f;
    for (int n = 0; n < NS; n++) {
        float a = g_A[n];
        float p = 1.0f;
        for (int t = 0; t < d; t++) p *= a;
        s += Vw[n * 8 + r] * p * Uw[n * 8 + c];
    }
    g_W8[i] = s;
}

// ---------------- activations: C, alpha; write alpha tail + zero pad into hwh/hwl ----------------
__global__ void __launch_bounds__(256) act_kernel(void) {
    __shared__ float s[64 * 72];
    const int row0 = blockIdx.x * 64;
    const int tid = threadIdx.x;
    for (int i = tid; i < 64 * 72; i += 256) {
        int r = i / 72, c = i - r * 72;
        s[i] = g_P[(size_t)(row0 + r) * NPAD + 512 + c];
    }
    __syncthreads();
    if (tid < 64) {
        const int row = row0 + tid;
        const float* v = &s[tid * 72];
        float dg[8];
#pragma unroll
        for (int i = 0; i < 8; i++) dg[i] = 1.0f / (1.0f + expf(-v[i]));
        float Cm[64];
        int m = 0;
#pragma unroll
        for (int i = 0; i < 8; i++) {
#pragma unroll
            for (int j = 0; j < 8; j++) {
                if (i == j) {
                    Cm[i * 8 + j] = dg[i];
                } else {
                    float x = v[8 + m];
                    float sp = (x > 15.0f) ? x : log1pf(expf(x));
                    Cm[i * 8 + j] = -sp;
                    m++;
                }
            }
        }
#pragma unroll
        for (int q = 0; q < 64; q++) g_C[(size_t)row * 64 + q] = Cm[q];
        float a[8], mx = v[64];
#pragma unroll
        for (int i = 1; i < 8; i++) mx = fmaxf(mx, v[64 + i]);
        float sum = 0.0f;
#pragma unroll
        for (int i = 0; i < 8; i++) { a[i] = expf(v[64 + i] - mx); sum += a[i]; }
        float inv = 1.0f / sum;
#pragma unroll
        for (int k = 0; k < 8; k++) {
            float al = a[k] * inv;
            g_alpha[(size_t)row * 8 + k] = al;
            __nv_bfloat16 h = __float2bfloat16_rn(al);
            g_hwh[(size_t)row * KHW + 512 + k] = h;
            g_hwl[(size_t)row * KHW + 512 + k] = __float2bfloat16_rn(al - __bfloat162float(h));
        }
    }
    const __nv_bfloat16 z = __float2bfloat16_rn(0.0f);
    for (int i = tid; i < 64 * 56; i += 256) {
        int r = i / 56, c = i - r * 56;
        g_hwh[(size_t)(row0 + r) * KHW + 520 + c] = z;
        g_hwl[(size_t)(row0 + r) * KHW + 520 + c] = z;
    }
}

// ---------------- chunked scan: 8 steps per chunk, rank-8 serial chain ----------------
// Per chunk (h_start = h at chunk start, w carried in warp0 regs):
//  A: f_j = a*f_{j-1} + bx_j, f_{-1}=h_start  (thread-local, diagonal)
//  B: PF_j = V^T f_j  (batched reduction over all 8 steps)
//  C: serial 8-dim chain (warp 0): m_j = C_j w_{j-1};  w_j = PF_j + sum_{s<=j} W_{j-s} m_s
//  D: g_j = a*g_{j-1} + U m_j;  h_j = f_j + g_j;  emit hw bf16;  h_start' = h_7
// smem (floats): bxs[2][8][512] | fbuf[8][512] | hst[512] | cst[2][8][64] | ast[2][8][8]
//                | wt[512] | red[8][8][16] | pf[64] | mb[64]
#define SCAN_SMEM (15616 * 4)
__global__ void __launch_bounds__(512, 1) scan_kernel(const float* __restrict__ Uw,
                                                      const float* __restrict__ Vw) {
    extern __shared__ float sm[];
    float* bxs  = sm;             // 8192
    float* fbuf = sm + 8192;      // 4096
    float* hst  = sm + 12288;     // 512
    float* cst  = sm + 12800;     // 1024
    float* ast  = sm + 13824;     // 128
    float* wt   = sm + 13952;     // 512
    float* red  = sm + 14464;     // 1024
    float* pf   = sm + 15488;     // 64
    float* mb   = sm + 15552;     // 64

    const int b = blockIdx.x;
    const int i = threadIdx.x;
    const int wid = i >> 5, lane = i & 31;
    const uint32_t sbase = smem_u32(sm);

    // init
    hst[i] = 0.0f;
    wt[i] = g_W8[i];
    const int k = i & 7, g8 = i >> 3;
    float Vv[8], Urow[8];
#pragma unroll
    for (int q = 0; q < 8; q++) Vv[q] = Vw[(g8 * 8 + q) * 8 + k];
#pragma unroll
    for (int q = 0; q < 8; q++) Urow[q] = Uw[i * 8 + q];
    const float an = g_A[i];
    float wreg[8];
#pragma unroll
    for (int q = 0; q < 8; q++) wreg[q] = 0.0f;

    const float* bxg = g_P + (size_t)b * TT * NPAD;
    const float* cg  = g_C + (size_t)b * TT * 64;
    const float* ag  = g_alpha + (size_t)b * TT * 8;

    // prefill stage for chunk 0 (buf 0)
    for (int idx = i; idx < 1024; idx += 512) {
        int t = idx >> 7, sg = idx & 127;
        cp16(sbase + (uint32_t)(t * 512 + sg * 4) * 4, bxg + t * NPAD + sg * 4);
    }
    for (int idx = i; idx < 128; idx += 512) {
        int t = idx >> 4, sg = idx & 15;
        cp16(sbase + (uint32_t)(12800 + t * 64 + sg * 4) * 4, cg + t * 64 + sg * 4);
    }
    if (i < 16) {
        int t = i >> 1, sg = i & 1;
        cp16(sbase + (uint32_t)(13824 + t * 8 + sg * 4) * 4, ag + t * 8 + sg * 4);
    }
    asm volatile("cp.async.commit_group;");
    asm volatile("cp.async.wait_group 0;");
    __syncthreads();

    float ff[8];
    for (int c = 0; c < NCH; ++c) {
        const int buf = c & 1;
        // ---- Phase A: thread-local f recurrence ----
        float fp = hst[i];
#pragma unroll
        for (int j = 0; j < 8; j++) {
            fp = fmaf(an, fp, bxs[buf * 4096 + j * 512 + i]);
            ff[j] = fp;
            fbuf[j * 512 + i] = fp;
        }
        __syncthreads();

        // ---- Phase B: PF_j = V^T f_j ----
        float pv[8];
        {
            const float* fb = fbuf + g8 * 8;
#pragma unroll
            for (int j = 0; j < 8; j++) {
                float4 f0 = *(const float4*)(fb + j * 512);
                float4 f1 = *(const float4*)(fb + j * 512 + 4);
                pv[j] = dot8v(f0, f1, Vv);
            }
        }
#pragma unroll
        for (int j = 0; j < 8; j++) {
            pv[j] += __shfl_xor_sync(0xffffffffu, pv[j], 8);
            pv[j] += __shfl_xor_sync(0xffffffffu, pv[j], 16);
        }
        if (lane < 8) {
#pragma unroll
            for (int j = 0; j < 8; j++) red[(j * 8 + lane) * 16 + wid] = pv[j];
        }
        __syncthreads();
        if (i < 64) {
            const float* rb = red + i * 16;
            float4 r0 = *(const float4*)rb,       r1 = *(const float4*)(rb + 4);
            float4 r2 = *(const float4*)(rb + 8), r3 = *(const float4*)(rb + 12);
            pf[i] = ((r0.x + r0.y) + (r0.z + r0.w)) + ((r1.x + r1.y) + (r1.z + r1.w))
                  + ((r2.x + r2.y) + (r2.z + r2.w)) + ((r3.x + r3.y) + (r3.z + r3.w));
        } else if (i >= 128 && c + 1 < NCH) {
            // stage next chunk
            const int nb = buf ^ 1;
            const size_t tb = (size_t)(c + 1) * 8;
            const int tt = i - 128;
            for (int idx = tt; idx < 1024; idx += 384) {
                int t = idx >> 7, sg = idx & 127;
                cp16(sbase + (uint32_t)(nb * 4096 + t * 512 + sg * 4) * 4,
                     bxg + (tb + t) * NPAD + sg * 4);
            }
            for (int idx = tt; idx < 128; idx += 384) {
                int t = idx >> 4, sg = idx & 15;
                cp16(sbase + (uint32_t)(12800 + nb * 512 + t * 64 + sg * 4) * 4,
                     cg + (tb + t) * 64 + sg * 4);
            }
            if (tt < 16) {
                int t = tt >> 1, sg = tt & 1;
                cp16(sbase + (uint32_t)(13824 + nb * 64 + t * 8 + sg * 4) * 4,
                     ag + (tb + t) * 8 + sg * 4);
            }
            asm volatile("cp.async.commit_group;");
        }
        __syncthreads();

        // ---- Phase C: serial 8-dim chain (warp 0) ----
        if (wid == 0) {
            const int r = lane & 7, dup = lane >> 3;
            const int j1 = dup, j2 = dup + 4;
            float PFr[8];
#pragma unroll
            for (int s = 0; s < 8; s++) PFr[s] = pf[s * 8 + r];
            float accA = 0.0f, accB = 0.0f;
            const float* cb = cst + buf * 512;
#pragma unroll
            for (int s = 0; s < 8; s++) {
                float4 c0 = *(const float4*)(cb + s * 64 + r * 8);
                float4 c1 = *(const float4*)(cb + s * 64 + r * 8 + 4);
                float mr = dot8v(c0, c1, wreg);
                float mf[8];
#pragma unroll
                for (int q = 0; q < 8; q++) mf[q] = __shfl_sync(0xffffffffu, mr, q + (dup << 3));
                if (j1 >= s) {
                    const float* wr = wt + ((j1 - s) * 8 + r) * 8;
                    accA += dot8v(*(const float4*)wr, *(const float4*)(wr + 4), mf);
                }
                if (j2 >= s) {
                    const float* wr = wt + ((j2 - s) * 8 + r) * 8;
                    accB += dot8v(*(const float4*)wr, *(const float4*)(wr + 4), mf);
                }
                float wv = (j1 == s) ? (PFr[s] + accA) : ((j2 == s) ? (PFr[s] + accB) : 0.0f);
#pragma unroll
                for (int q = 0; q < 8; q++) wreg[q] = __shfl_sync(0xffffffffu, wv, q + ((s & 3) << 3));
                if (dup == 0) mb[s * 8 + r] = mr;
            }
        } else {
            asm volatile("cp.async.wait_group 0;");
        }
        __syncthreads();

        // ---- Phase D: reconstruct h + emit hw ----
        {
            float g = 0.0f;
            const size_t row0 = (size_t)b * TT + (size_t)c * 8;
            __nv_bfloat16* oh = g_hwh + row0 * KHW + i;
            __nv_bfloat16* ol = g_hwl + row0 * KHW + i;
            const float* as_ = ast + buf * 64;
            const int ab = i >> 6;
            float hlast = 0.0f;
#pragma unroll
            for (int j = 0; j < 8; j++) {
                float4 m0 = *(const float4*)(mb + j * 8);
                float4 m1 = *(const float4*)(mb + j * 8 + 4);
                float um = dot8v(m0, m1, Urow);
                g = fmaf(an, g, um);
                float h = ff[j] + g;
                float wv = h * as_[j * 8 + ab];
                __nv_bfloat16 hi = __float2bfloat16_rn(wv);
                oh[(size_t)j * KHW] = hi;
                ol[(size_t)j * KHW] = __float2bfloat16_rn(wv - __bfloat162float(hi));
                hlast = h;
            }
            hst[i] = hlast;
        }
        __syncthreads();
    }
}

// ---------------- launch ----------------
extern "C" void kernel_launch(void* const* d_in, const int* in_sizes, int n_in,
                              void* d_out, int out_size) {
    const float* x      = (const float*)d_in[0];
    const float* Wb     = (const float*)d_in[1];
    const float* bb     = (const float*)d_in[2];
    const float* Wdiag  = (const float*)d_in[3];
    const float* bdiag  = (const float*)d_in[4];
    const float* Woff   = (const float*)d_in[5];
    const float* boff   = (const float*)d_in[6];
    const float* Walpha = (const float*)d_in[7];
    const float* balpha = (const float*)d_in[8];
    const float* Wc     = (const float*)d_in[9];
    const float* bc     = (const float*)d_in[10];
    const float* ll     = (const float*)d_in[11];
    const float* U      = (const float*)d_in[12];
    const float* V      = (const float*)d_in[13];
    float* out = (float*)d_out;

    float *pP, *pbpack;
    __nv_bfloat16 *pxh, *pxl, *pWh, *pWl, *phwh, *phwl, *pW2h, *pW2l;
    cudaGetSymbolAddress((void**)&pP,     g_P);
    cudaGetSymbolAddress((void**)&pbpack, g_bpack);
    cudaGetSymbolAddress((void**)&pxh,    g_xh);
    cudaGetSymbolAddress((void**)&pxl,    g_xl);
    cudaGetSymbolAddress((void**)&pWh,    g_Wh);
    cudaGetSymbolAddress((void**)&pWl,    g_Wl);
    cudaGetSymbolAddress((void**)&phwh,   g_hwh);
    cudaGetSymbolAddress((void**)&phwl,   g_hwl);
    cudaGetSymbolAddress((void**)&pW2h,   g_W2h);
    cudaGetSymbolAddress((void**)&pW2l,   g_W2l);

    cudaFuncSetAttribute(gemm_bf16x3_mma, cudaFuncAttributeMaxDynamicSharedMemorySize, GSMEM);
    cudaFuncSetAttribute(scan_kernel, cudaFuncAttributeMaxDynamicSharedMemorySize, SCAN_SMEM);

    conv_x_kernel<<<(ROWS * DM / 4 + 255) / 256, 256>>>((const float4*)x, (uint2*)pxh,
                                                        (uint2*)pxl, ROWS * DM / 4);
    pack1b_kernel<<<(DM * NPAD + 255) / 256, 256>>>(Wb, Wdiag, Woff, Walpha);
    pack2b_kernel<<<(KHW * DM + 255) / 256, 256>>>(Wc, bc);
    misc_kernel<<<1, 1024>>>(bb, bdiag, boff, balpha, ll);
    wtab_kernel<<<1, 512>>>(U, V);

    // GEMM1: P = x @ Wpack + bpack   (M=16384, N=640, K=1024)
    gemm_bf16x3_mma<<<dim3(NPAD / 128, ROWS / 128), 256, GSMEM>>>(pxh, pxl, pWh, pWl,
                                                                  pbpack, pP, DM, NPAD);

    act_kernel<<<ROWS / 64, 256>>>();

    scan_kernel<<<BB, 512, SCAN_SMEM>>>(U, V);

    // GEMM2: out = hw @ W2           (M=16384, N=1024, K=576)
    gemm_bf16x3_mma<<<dim3(DM / 128, ROWS / 128), 256, GSMEM>>>(phwh, phwl, pW2h, pW2l,
                                                                nullptr, out, KHW, DM);
}

// round 10
// speedup vs baseline: 2.0545x; 1.1486x over previous
#include <cuda_runtime.h>
#include <cuda_bf16.h>
#include <cstdint>
#include <math.h>

#define BB 8
#define TT 2048
#define DM 1024
#define NS 512
#define NPAD 640
#define NHW 520
#define KHW 576                 // padded K for GEMM2 (18 x 32)
#define ROWS (BB*TT)            // 16384
#define NCH 256                 // chunks of 8 steps
#define NSEG 4
#define CH_PER_SEG (NCH / NSEG) // 64

// ---------------- scratch (static device globals; no dynamic alloc) ----------------
__device__ float g_P[ROWS * NPAD];              // GEMM1 output fp32
__device__ float g_C[ROWS * 64];                // C matrices (b,t,8,8)
__device__ float g_alpha[ROWS * 8];
__device__ float g_bpack[NPAD];                 // packed biases
__device__ float g_A[NS];
__device__ float g_W8[512];                     // W_d = V^T diag(a^d) U, d=0..7, [d][r][c]
__device__ float g_hcarry[BB * NS];             // h carry between scan segments
__device__ float g_wcarry[BB * 8];              // w carry between scan segments
__device__ __nv_bfloat16 g_xh[ROWS * DM];       // x split hi/lo, [M][K]
__device__ __nv_bfloat16 g_xl[ROWS * DM];
__device__ __nv_bfloat16 g_Wh[DM * NPAD];       // Wpack [K=1024][N=640] hi/lo
__device__ __nv_bfloat16 g_Wl[DM * NPAD];
__device__ __nv_bfloat16 g_hwh[ROWS * KHW];     // [h*alpha | alpha | 0pad] hi, bf16
__device__ __nv_bfloat16 g_hwl[ROWS * KHW];     // lo residual
__device__ __nv_bfloat16 g_W2h[KHW * DM];       // W2 [K=576][N=1024] hi/lo
__device__ __nv_bfloat16 g_W2l[KHW * DM];

// ---------------- helpers ----------------
__device__ __forceinline__ uint32_t smem_u32(const void* p) {
    uint32_t a;
    asm("{ .reg .u64 t; cvta.to.shared.u64 t, %1; cvt.u32.u64 %0, t; }" : "=r"(a) : "l"(p));
    return a;
}
__device__ __forceinline__ void cp16(uint32_t dst, const void* src) {
    asm volatile("cp.async.cg.shared.global [%0], [%1], 16;" :: "r"(dst), "l"(src));
}
__device__ __forceinline__ void ldsm4(uint32_t* r, uint32_t addr) {
    asm volatile("ldmatrix.sync.aligned.m8n8.x4.shared.b16 {%0,%1,%2,%3}, [%4];"
                 : "=r"(r[0]), "=r"(r[1]), "=r"(r[2]), "=r"(r[3]) : "r"(addr));
}
__device__ __forceinline__ void ldsm4t(uint32_t* r, uint32_t addr) {
    asm volatile("ldmatrix.sync.aligned.m8n8.x4.trans.shared.b16 {%0,%1,%2,%3}, [%4];"
                 : "=r"(r[0]), "=r"(r[1]), "=r"(r[2]), "=r"(r[3]) : "r"(addr));
}
__device__ __forceinline__ void mma16816(float* d, const uint32_t* a, const uint32_t* b) {
    asm volatile(
        "mma.sync.aligned.m16n8k16.row.col.f32.bf16.bf16.f32 "
        "{%0,%1,%2,%3}, {%4,%5,%6,%7}, {%8,%9}, {%0,%1,%2,%3};\n"
        : "+f"(d[0]), "+f"(d[1]), "+f"(d[2]), "+f"(d[3])
        : "r"(a[0]), "r"(a[1]), "r"(a[2]), "r"(a[3]), "r"(b[0]), "r"(b[1]));
}
__device__ __forceinline__ uint32_t bf16x2_pack(float a, float b) {
    __nv_bfloat162 p = __nv_bfloat162(__float2bfloat16_rn(a), __float2bfloat16_rn(b));
    return *(uint32_t*)&p;
}
__device__ __forceinline__ float dot8v(float4 a0, float4 a1, const float* m) {
    float t0 = fmaf(a0.y, m[1], a0.x * m[0]);
    float t1 = fmaf(a0.w, m[3], a0.z * m[2]);
    float t2 = fmaf(a1.y, m[5], a1.x * m[4]);
    float t3 = fmaf(a1.w, m[7], a1.z * m[6]);
    return (t0 + t1) + (t2 + t3);
}

// smem stage layout (bytes): Ah | Al | Bh | Bl, padded strides for conflict-free ldmatrix
#define ASTR 40
#define BSTR 136
#define A_BYTES (128 * ASTR * 2)
#define B_BYTES (32 * BSTR * 2)
#define OFF_AH 0
#define OFF_AL A_BYTES
#define OFF_BH (2 * A_BYTES)
#define OFF_BL (2 * A_BYTES + B_BYTES)
#define STG (2 * A_BYTES + 2 * B_BYTES)
#define GSMEM (3 * STG)

// ---------------- bf16x3 mma.sync GEMM over one T-segment ----------------
// Rows remapped: blockIdx.y in [0,32): batch = by>>2, quarter = by&3,
// m0 = batch*2048 + seg*512 + quarter*128.
__global__ void __launch_bounds__(256, 1)
gemm_bf16x3_mma(const __nv_bfloat16* __restrict__ Ah, const __nv_bfloat16* __restrict__ Al,
                const __nv_bfloat16* __restrict__ Bh, const __nv_bfloat16* __restrict__ Bl,
                const float* __restrict__ bias, float* __restrict__ D, int K, int N, int seg)
{
    extern __shared__ char smem[];
    const uint32_t sbase = smem_u32(smem);
    const int tid = threadIdx.x;
    const int lane = tid & 31, w = tid >> 5;
    const int wm = w & 1, wn = w >> 1;
    const int m0 = (blockIdx.y >> 2) * 2048 + seg * 512 + (blockIdx.y & 3) * 128;
    const int n0 = blockIdx.x * 128;
    const int NC = K >> 5;

    float acc[4][4][4];
#pragma unroll
    for (int i = 0; i < 4; i++)
#pragma unroll
        for (int j = 0; j < 4; j++)
#pragma unroll
            for (int q = 0; q < 4; q++) acc[i][j][q] = 0.0f;

    const int ar = tid >> 2, as = tid & 3;
    const int br = tid >> 4, bs = tid & 15;

    auto load_stage = [&](int s, int c) {
        const uint32_t st = sbase + s * STG;
        const long kc = (long)c * 32;
        cp16(st + OFF_AH + ar * 80 + as * 16,        Ah + (long)(m0 + ar) * K + kc + as * 8);
        cp16(st + OFF_AH + (ar + 64) * 80 + as * 16, Ah + (long)(m0 + ar + 64) * K + kc + as * 8);
        cp16(st + OFF_AL + ar * 80 + as * 16,        Al + (long)(m0 + ar) * K + kc + as * 8);
        cp16(st + OFF_AL + (ar + 64) * 80 + as * 16, Al + (long)(m0 + ar + 64) * K + kc + as * 8);
        cp16(st + OFF_BH + br * 272 + bs * 16,        Bh + (kc + br) * (long)N + n0 + bs * 8);
        cp16(st + OFF_BH + (br + 16) * 272 + bs * 16, Bh + (kc + br + 16) * (long)N + n0 + bs * 8);
        cp16(st + OFF_BL + br * 272 + bs * 16,        Bl + (kc + br) * (long)N + n0 + bs * 8);
        cp16(st + OFF_BL + (br + 16) * 272 + bs * 16, Bl + (kc + br + 16) * (long)N + n0 + bs * 8);
        asm volatile("cp.async.commit_group;");
    };

    const int pre = (NC < 3) ? NC : 3;
    for (int s = 0; s < pre; s++) load_stage(s, s);

    const uint32_t a_off = (uint32_t)(((wm * 64 + (lane & 15)) * ASTR + ((lane >> 4) << 3)) * 2);
    const uint32_t b_off = (uint32_t)((((lane & 15)) * BSTR + wn * 32 + ((lane >> 4) << 3)) * 2);

    int s = 0;
    for (int kt = 0; kt < NC; ++kt) {
        const int pend = ((NC - kt) < 3 ? (NC - kt) : 3);
        if (pend == 3)      asm volatile("cp.async.wait_group 2;");
        else if (pend == 2) asm volatile("cp.async.wait_group 1;");
        else                asm volatile("cp.async.wait_group 0;");
        __syncthreads();

        const uint32_t st = sbase + s * STG;
        const uint32_t ah_b = st + OFF_AH + a_off;
        const uint32_t al_b = st + OFF_AL + a_off;
        const uint32_t bh_b = st + OFF_BH + b_off;
        const uint32_t bl_b = st + OFF_BL + b_off;

#pragma unroll
        for (int kk = 0; kk < 2; ++kk) {
            uint32_t af[4][4], lf[4][4], bf[2][4], gf[2][4];
#pragma unroll
            for (int mt = 0; mt < 4; mt++) {
                ldsm4(af[mt], ah_b + (mt * 16 * ASTR + kk * 16) * 2);
                ldsm4(lf[mt], al_b + (mt * 16 * ASTR + kk * 16) * 2);
            }
#pragma unroll
            for (int np = 0; np < 2; np++) {
                ldsm4t(bf[np], bh_b + (kk * 16 * BSTR + np * 16) * 2);
                ldsm4t(gf[np], bl_b + (kk * 16 * BSTR + np * 16) * 2);
            }
#pragma unroll
            for (int mt = 0; mt < 4; mt++) {
#pragma unroll
                for (int nt = 0; nt < 4; nt++) {
                    const uint32_t* bp = &bf[nt >> 1][(nt & 1) * 2];
                    const uint32_t* lp = &gf[nt >> 1][(nt & 1) * 2];
                    mma16816(acc[mt][nt], af[mt], bp);
                    mma16816(acc[mt][nt], lf[mt], bp);
                    mma16816(acc[mt][nt], af[mt], lp);
                }
            }
        }
        __syncthreads();
        const int cn = kt + 3;
        if (cn < NC) load_stage(s, cn);
        if (++s == 3) s = 0;
    }

    const int rb = m0 + wm * 64 + (lane >> 2);
    const int cb = n0 + wn * 32 + (lane & 3) * 2;
#pragma unroll
    for (int mt = 0; mt < 4; mt++) {
#pragma unroll
        for (int nt = 0; nt < 4; nt++) {
            const int r = rb + mt * 16;
            const int c = cb + nt * 8;
            float b0 = 0.0f, b1 = 0.0f;
            if (bias) { b0 = bias[c]; b1 = bias[c + 1]; }
            float2 o0 = make_float2(acc[mt][nt][0] + b0, acc[mt][nt][1] + b1);
            float2 o1 = make_float2(acc[mt][nt][2] + b0, acc[mt][nt][3] + b1);
            *(float2*)(D + (size_t)r * N + c) = o0;
            *(float2*)(D + (size_t)(r + 8) * N + c) = o1;
        }
    }
}

// ---------------- conversion / packing kernels ----------------
__global__ void conv_x_kernel(const float4* __restrict__ src, uint2* __restrict__ dh,
                              uint2* __restrict__ dl, int n4) {
    int i = blockIdx.x * blockDim.x + threadIdx.x;
    if (i >= n4) return;
    float4 v = src[i];
    float hx = __bfloat162float(__float2bfloat16_rn(v.x));
    float hy = __bfloat162float(__float2bfloat16_rn(v.y));
    float hz = __bfloat162float(__float2bfloat16_rn(v.z));
    float hw = __bfloat162float(__float2bfloat16_rn(v.w));
    uint2 oh, ol;
    oh.x = bf16x2_pack(v.x, v.y); oh.y = bf16x2_pack(v.z, v.w);
    ol.x = bf16x2_pack(v.x - hx, v.y - hy); ol.y = bf16x2_pack(v.z - hz, v.w - hw);
    dh[i] = oh; dl[i] = ol;
}

__global__ void pack1b_kernel(const float* __restrict__ Wb, const float* __restrict__ Wdiag,
                              const float* __restrict__ Woff, const float* __restrict__ Walpha) {
    int idx = blockIdx.x * blockDim.x + threadIdx.x;
    if (idx >= DM * NPAD) return;
    int r = idx / NPAD, c = idx - r * NPAD;
    float v;
    if (c < 512)       v = Wb[r * NS + c];
    else if (c < 520)  v = Wdiag[r * 8 + (c - 512)];
    else if (c < 576)  v = Woff[r * 56 + (c - 520)];
    else if (c < 584)  v = Walpha[r * 8 + (c - 576)];
    else               v = 0.0f;
    __nv_bfloat16 h = __float2bfloat16_rn(v);
    g_Wh[idx] = h;
    g_Wl[idx] = __float2bfloat16_rn(v - __bfloat162float(h));
}

__global__ void pack2b_kernel(const float* __restrict__ Wc, const float* __restrict__ bc) {
    int idx = blockIdx.x * blockDim.x + threadIdx.x;
    if (idx >= KHW * DM) return;
    int k = idx >> 10, n = idx & 1023;
    float v;
    if (k < 512)      v = Wc[idx];
    else if (k < 520) v = bc[(size_t)(k - 512) * DM + n];
    else              v = 0.0f;
    __nv_bfloat16 h = __float2bfloat16_rn(v);
    g_W2h[idx] = h;
    g_W2l[idx] = __float2bfloat16_rn(v - __bfloat162float(h));
}

__global__ void misc_kernel(const float* __restrict__ bb, const float* __restrict__ bdiag,
                            const float* __restrict__ boff, const float* __restrict__ balpha,
                            const float* __restrict__ log_lambda) {
    int tid = threadIdx.x;
    if (tid < NS) {
        int k = tid >> 6;
        double dt = 1e-3 * exp((double)k * log(1000.0) / 7.0);
        double ll = (double)log_lambda[tid];
        double sp = log1p(exp(ll));
        g_A[tid] = (float)exp(-dt * sp);
    }
    if (tid < NPAD) {
        float v;
        if (tid < 512)       v = bb[tid];
        else if (tid < 520)  v = bdiag[tid - 512];
        else if (tid < 576)  v = boff[tid - 520];
        else if (tid < 584)  v = balpha[tid - 576];
        else                 v = 0.0f;
        g_bpack[tid] = v;
    }
}

// W_d[r][c] = sum_n V[n,r] * a_n^d * U[n,c], d=0..7  (runs after misc_kernel)
__global__ void wtab_kernel(const float* __restrict__ Uw, const float* __restrict__ Vw) {
    int i = threadIdx.x;
    if (i >= 512) return;
    int d = i >> 6, r = (i >> 3) & 7, c = i & 7;
    float s = 0.0f;
    for (int n = 0; n < NS; n++) {
        float a = g_A[n];
        float p = 1.0f;
        for (int t = 0; t < d; t++) p *= a;
        s += Vw[n * 8 + r] * p * Uw[n * 8 + c];
    }
    g_W8[i] = s;
}

// ---------------- activations for one T-segment ----------------
// grid = 64 blocks; row0 = (bx>>3)*2048 + seg*512 + (bx&7)*64
__global__ void __launch_bounds__(256) act_kernel(int seg) {
    __shared__ float s[64 * 72];
    const int row0 = (blockIdx.x >> 3) * 2048 + seg * 512 + (blockIdx.x & 7) * 64;
    const int tid = threadIdx.x;
    for (int i = tid; i < 64 * 72; i += 256) {
        int r = i / 72, c = i - r * 72;
        s[i] = g_P[(size_t)(row0 + r) * NPAD + 512 + c];
    }
    __syncthreads();
    if (tid < 64) {
        const int row = row0 + tid;
        const float* v = &s[tid * 72];
        float dg[8];
#pragma unroll
        for (int i = 0; i < 8; i++) dg[i] = 1.0f / (1.0f + expf(-v[i]));
        float Cm[64];
        int m = 0;
#pragma unroll
        for (int i = 0; i < 8; i++) {
#pragma unroll
            for (int j = 0; j < 8; j++) {
                if (i == j) {
                    Cm[i * 8 + j] = dg[i];
                } else {
                    float x = v[8 + m];
                    float sp = (x > 15.0f) ? x : log1pf(expf(x));
                    Cm[i * 8 + j] = -sp;
                    m++;
                }
            }
        }
#pragma unroll
        for (int q = 0; q < 64; q++) g_C[(size_t)row * 64 + q] = Cm[q];
        float a[8], mx = v[64];
#pragma unroll
        for (int i = 1; i < 8; i++) mx = fmaxf(mx, v[64 + i]);
        float sum = 0.0f;
#pragma unroll
        for (int i = 0; i < 8; i++) { a[i] = expf(v[64 + i] - mx); sum += a[i]; }
        float inv = 1.0f / sum;
#pragma unroll
        for (int k = 0; k < 8; k++) {
            float al = a[k] * inv;
            g_alpha[(size_t)row * 8 + k] = al;
            __nv_bfloat16 h = __float2bfloat16_rn(al);
            g_hwh[(size_t)row * KHW + 512 + k] = h;
            g_hwl[(size_t)row * KHW + 512 + k] = __float2bfloat16_rn(al - __bfloat162float(h));
        }
    }
    const __nv_bfloat16 z = __float2bfloat16_rn(0.0f);
    for (int i = tid; i < 64 * 56; i += 256) {
        int r = i / 56, c = i - r * 56;
        g_hwh[(size_t)(row0 + r) * KHW + 520 + c] = z;
        g_hwl[(size_t)(row0 + r) * KHW + 520 + c] = z;
    }
}

// ---------------- chunked scan over one T-segment (64 chunks of 8 steps) ----------------
// h carry via g_hcarry, w carry via g_wcarry between segment launches.
#define SCAN_SMEM (15616 * 4)
__global__ void __launch_bounds__(512, 1) scan_kernel(const float* __restrict__ Uw,
                                                      const float* __restrict__ Vw, int seg) {
    extern __shared__ float sm[];
    float* bxs  = sm;             // 8192
    float* fbuf = sm + 8192;      // 4096
    float* hst  = sm + 12288;     // 512
    float* cst  = sm + 12800;     // 1024
    float* ast  = sm + 13824;     // 128
    float* wt   = sm + 13952;     // 512
    float* red  = sm + 14464;     // 1024
    float* pf   = sm + 15488;     // 64
    float* mb   = sm + 15552;     // 64

    const int b = blockIdx.x;
    const int i = threadIdx.x;
    const int wid = i >> 5, lane = i & 31;
    const uint32_t sbase = smem_u32(sm);
    const int cbeg = seg * CH_PER_SEG, cend = cbeg + CH_PER_SEG;

    // init
    hst[i] = (seg == 0) ? 0.0f : g_hcarry[b * NS + i];
    wt[i] = g_W8[i];
    const int k = i & 7, g8 = i >> 3;
    float Vv[8], Urow[8];
#pragma unroll
    for (int q = 0; q < 8; q++) Vv[q] = Vw[(g8 * 8 + q) * 8 + k];
#pragma unroll
    for (int q = 0; q < 8; q++) Urow[q] = Uw[i * 8 + q];
    const float an = g_A[i];
    float wreg[8];
    if (seg == 0) {
#pragma unroll
        for (int q = 0; q < 8; q++) wreg[q] = 0.0f;
    } else {
#pragma unroll
        for (int q = 0; q < 8; q++) wreg[q] = g_wcarry[b * 8 + q];
    }

    const float* bxg = g_P + (size_t)b * TT * NPAD;
    const float* cg  = g_C + (size_t)b * TT * 64;
    const float* ag  = g_alpha + (size_t)b * TT * 8;
    const size_t t0 = (size_t)cbeg * 8;

    // prefill stage for first chunk (cbeg is even -> buf 0)
    for (int idx = i; idx < 1024; idx += 512) {
        int t = idx >> 7, sg = idx & 127;
        cp16(sbase + (uint32_t)(t * 512 + sg * 4) * 4, bxg + (t0 + t) * NPAD + sg * 4);
    }
    for (int idx = i; idx < 128; idx += 512) {
        int t = idx >> 4, sg = idx & 15;
        cp16(sbase + (uint32_t)(12800 + t * 64 + sg * 4) * 4, cg + (t0 + t) * 64 + sg * 4);
    }
    if (i < 16) {
        int t = i >> 1, sg = i & 1;
        cp16(sbase + (uint32_t)(13824 + t * 8 + sg * 4) * 4, ag + (t0 + t) * 8 + sg * 4);
    }
    asm volatile("cp.async.commit_group;");
    asm volatile("cp.async.wait_group 0;");
    __syncthreads();

    float ff[8];
    for (int c = cbeg; c < cend; ++c) {
        const int buf = c & 1;
        // ---- Phase A: thread-local f recurrence ----
        float fp = hst[i];
#pragma unroll
        for (int j = 0; j < 8; j++) {
            fp = fmaf(an, fp, bxs[buf * 4096 + j * 512 + i]);
            ff[j] = fp;
            fbuf[j * 512 + i] = fp;
        }
        __syncthreads();

        // ---- Phase B: PF_j = V^T f_j ----
        float pv[8];
        {
            const float* fb = fbuf + g8 * 8;
#pragma unroll
            for (int j = 0; j < 8; j++) {
                float4 f0 = *(const float4*)(fb + j * 512);
                float4 f1 = *(const float4*)(fb + j * 512 + 4);
                pv[j] = dot8v(f0, f1, Vv);
            }
        }
#pragma unroll
        for (int j = 0; j < 8; j++) {
            pv[j] += __shfl_xor_sync(0xffffffffu, pv[j], 8);
            pv[j] += __shfl_xor_sync(0xffffffffu, pv[j], 16);
        }
        if (lane < 8) {
#pragma unroll
            for (int j = 0; j < 8; j++) red[(j * 8 + lane) * 16 + wid] = pv[j];
        }
        __syncthreads();
        if (i < 64) {
            const float* rb = red + i * 16;
            float4 r0 = *(const float4*)rb,       r1 = *(const float4*)(rb + 4);
            float4 r2 = *(const float4*)(rb + 8), r3 = *(const float4*)(rb + 12);
            pf[i] = ((r0.x + r0.y) + (r0.z + r0.w)) + ((r1.x + r1.y) + (r1.z + r1.w))
                  + ((r2.x + r2.y) + (r2.z + r2.w)) + ((r3.x + r3.y) + (r3.z + r3.w));
        } else if (i >= 128 && c + 1 < cend) {
            // stage next chunk (stays inside this segment's act/gemm1 output)
            const int nb = buf ^ 1;
            const size_t tb = (size_t)(c + 1) * 8;
            const int tt = i - 128;
            for (int idx = tt; idx < 1024; idx += 384) {
                int t = idx >> 7, sg = idx & 127;
                cp16(sbase + (uint32_t)(nb * 4096 + t * 512 + sg * 4) * 4,
                     bxg + (tb + t) * NPAD + sg * 4);
            }
            for (int idx = tt; idx < 128; idx += 384) {
                int t = idx >> 4, sg = idx & 15;
                cp16(sbase + (uint32_t)(12800 + nb * 512 + t * 64 + sg * 4) * 4,
                     cg + (tb + t) * 64 + sg * 4);
            }
            if (tt < 16) {
                int t = tt >> 1, sg = tt & 1;
                cp16(sbase + (uint32_t)(13824 + nb * 64 + t * 8 + sg * 4) * 4,
                     ag + (tb + t) * 8 + sg * 4);
            }
            asm volatile("cp.async.commit_group;");
        }
        __syncthreads();

        // ---- Phase C: serial 8-dim chain (warp 0) ----
        if (wid == 0) {
            const int r = lane & 7, dup = lane >> 3;
            const int j1 = dup, j2 = dup + 4;
            float PFr[8];
#pragma unroll
            for (int s = 0; s < 8; s++) PFr[s] = pf[s * 8 + r];
            float accA = 0.0f, accB = 0.0f;
            const float* cb = cst + buf * 512;
#pragma unroll
            for (int s = 0; s < 8; s++) {
                float4 c0 = *(const float4*)(cb + s * 64 + r * 8);
                float4 c1 = *(const float4*)(cb + s * 64 + r * 8 + 4);
                float mr = dot8v(c0, c1, wreg);
                float mf[8];
#pragma unroll
                for (int q = 0; q < 8; q++) mf[q] = __shfl_sync(0xffffffffu, mr, q + (dup << 3));
                if (j1 >= s) {
                    const float* wr = wt + ((j1 - s) * 8 + r) * 8;
                    accA += dot8v(*(const float4*)wr, *(const float4*)(wr + 4), mf);
                }
                if (j2 >= s) {
                    const float* wr = wt + ((j2 - s) * 8 + r) * 8;
                    accB += dot8v(*(const float4*)wr, *(const float4*)(wr + 4), mf);
                }
                float wv = (j1 == s) ? (PFr[s] + accA) : ((j2 == s) ? (PFr[s] + accB) : 0.0f);
#pragma unroll
                for (int q = 0; q < 8; q++) wreg[q] = __shfl_sync(0xffffffffu, wv, q + ((s & 3) << 3));
                if (dup == 0) mb[s * 8 + r] = mr;
            }
        } else {
            asm volatile("cp.async.wait_group 0;");
        }
        __syncthreads();

        // ---- Phase D: reconstruct h + emit hw ----
        {
            float g = 0.0f;
            const size_t row0 = (size_t)b * TT + (size_t)c * 8;
            __nv_bfloat16* oh = g_hwh + row0 * KHW + i;
            __nv_bfloat16* ol = g_hwl + row0 * KHW + i;
            const float* as_ = ast + buf * 64;
            const int ab = i >> 6;
            float hlast = 0.0f;
#pragma unroll
            for (int j = 0; j < 8; j++) {
                float4 m0 = *(const float4*)(mb + j * 8);
                float4 m1 = *(const float4*)(mb + j * 8 + 4);
                float um = dot8v(m0, m1, Urow);
                g = fmaf(an, g, um);
                float h = ff[j] + g;
                float wv = h * as_[j * 8 + ab];
                __nv_bfloat16 hi = __float2bfloat16_rn(wv);
                oh[(size_t)j * KHW] = hi;
                ol[(size_t)j * KHW] = __float2bfloat16_rn(wv - __bfloat162float(hi));
                hlast = h;
            }
            hst[i] = hlast;
        }
        __syncthreads();
    }

    // write carries for next segment
    g_hcarry[b * NS + i] = hst[i];
    if (wid == 0 && lane == 0) {
#pragma unroll
        for (int q = 0; q < 8; q++) g_wcarry[b * 8 + q] = wreg[q];
    }
}

// ---------------- launch: 4-segment software pipeline across 3 streams ----------------
extern "C" void kernel_launch(void* const* d_in, const int* in_sizes, int n_in,
                              void* d_out, int out_size) {
    const float* x      = (const float*)d_in[0];
    const float* Wb     = (const float*)d_in[1];
    const float* bb     = (const float*)d_in[2];
    const float* Wdiag  = (const float*)d_in[3];
    const float* bdiag  = (const float*)d_in[4];
    const float* Woff   = (const float*)d_in[5];
    const float* boff   = (const float*)d_in[6];
    const float* Walpha = (const float*)d_in[7];
    const float* balpha = (const float*)d_in[8];
    const float* Wc     = (const float*)d_in[9];
    const float* bc     = (const float*)d_in[10];
    const float* ll     = (const float*)d_in[11];
    const float* U      = (const float*)d_in[12];
    const float* V      = (const float*)d_in[13];
    float* out = (float*)d_out;

    float *pP, *pbpack;
    __nv_bfloat16 *pxh, *pxl, *pWh, *pWl, *phwh, *phwl, *pW2h, *pW2l;
    cudaGetSymbolAddress((void**)&pP,     g_P);
    cudaGetSymbolAddress((void**)&pbpack, g_bpack);
    cudaGetSymbolAddress((void**)&pxh,    g_xh);
    cudaGetSymbolAddress((void**)&pxl,    g_xl);
    cudaGetSymbolAddress((void**)&pWh,    g_Wh);
    cudaGetSymbolAddress((void**)&pWl,    g_Wl);
    cudaGetSymbolAddress((void**)&phwh,   g_hwh);
    cudaGetSymbolAddress((void**)&phwl,   g_hwl);
    cudaGetSymbolAddress((void**)&pW2h,   g_W2h);
    cudaGetSymbolAddress((void**)&pW2l,   g_W2l);

    cudaFuncSetAttribute(gemm_bf16x3_mma, cudaFuncAttributeMaxDynamicSharedMemorySize, GSMEM);
    cudaFuncSetAttribute(scan_kernel, cudaFuncAttributeMaxDynamicSharedMemorySize, SCAN_SMEM);

    // lazily-created side streams/events (resource handles only; per-call work identical)
    static cudaStream_t sB = nullptr, sC = nullptr;
    static cudaEvent_t evA[NSEG], evS[NSEG], evEnd = nullptr;
    static int streams_ok = -1;
    if (streams_ok < 0) {
        bool ok = (cudaStreamCreateWithFlags(&sB, cudaStreamNonBlocking) == cudaSuccess) &&
                  (cudaStreamCreateWithFlags(&sC, cudaStreamNonBlocking) == cudaSuccess);
        for (int s = 0; s < NSEG && ok; s++) {
            ok = (cudaEventCreateWithFlags(&evA[s], cudaEventDisableTiming) == cudaSuccess) &&
                 (cudaEventCreateWithFlags(&evS[s], cudaEventDisableTiming) == cudaSuccess);
        }
        ok = ok && (cudaEventCreateWithFlags(&evEnd, cudaEventDisableTiming) == cudaSuccess);
        streams_ok = ok ? 1 : 0;
    }

    // head: conversions + packing (stream 0)
    conv_x_kernel<<<(ROWS * DM / 4 + 255) / 256, 256>>>((const float4*)x, (uint2*)pxh,
                                                        (uint2*)pxl, ROWS * DM / 4);
    pack1b_kernel<<<(DM * NPAD + 255) / 256, 256>>>(Wb, Wdiag, Woff, Walpha);
    pack2b_kernel<<<(KHW * DM + 255) / 256, 256>>>(Wc, bc);
    misc_kernel<<<1, 1024>>>(bb, bdiag, boff, balpha, ll);
    wtab_kernel<<<1, 512>>>(U, V);

    if (streams_ok == 1) {
        // producer chain on stream 0: GEMM1 seg + act seg
        for (int s = 0; s < NSEG; s++) {
            gemm_bf16x3_mma<<<dim3(NPAD / 128, 32), 256, GSMEM>>>(pxh, pxl, pWh, pWl,
                                                                  pbpack, pP, DM, NPAD, s);
            act_kernel<<<64, 256>>>(s);
            cudaEventRecord(evA[s], 0);
        }
        // scan chain on stream B
        for (int s = 0; s < NSEG; s++) {
            cudaStreamWaitEvent(sB, evA[s], 0);
            scan_kernel<<<BB, 512, SCAN_SMEM, sB>>>(U, V, s);
            cudaEventRecord(evS[s], sB);
        }
        // GEMM2 chain on stream C
        for (int s = 0; s < NSEG; s++) {
            cudaStreamWaitEvent(sC, evS[s], 0);
            gemm_bf16x3_mma<<<dim3(DM / 128, 32), 256, GSMEM, sC>>>(phwh, phwl, pW2h, pW2l,
                                                                    nullptr, out, KHW, DM, s);
        }
        cudaEventRecord(evEnd, sC);
        cudaStreamWaitEvent(0, evEnd, 0);
    } else {
        // sequential fallback on stream 0
        for (int s = 0; s < NSEG; s++) {
            gemm_bf16x3_mma<<<dim3(NPAD / 128, 32), 256, GSMEM>>>(pxh, pxl, pWh, pWl,
                                                                  pbpack, pP, DM, NPAD, s);
            act_kernel<<<64, 256>>>(s);
        }
        for (int s = 0; s < NSEG; s++) scan_kernel<<<BB, 512, SCAN_SMEM>>>(U, V, s);
        for (int s = 0; s < NSEG; s++)
            gemm_bf16x3_mma<<<dim3(DM / 128, 32), 256, GSMEM>>>(phwh, phwl, pW2h, pW2l,
                                                                nullptr, out, KHW, DM, s);
    }
}

// round 11
// speedup vs baseline: 2.3984x; 1.1674x over previous
#include <cuda_runtime.h>
#include <cuda_bf16.h>
#include <cstdint>
#include <math.h>

#define BB 8
#define TT 2048
#define DM 1024
#define NS 512
#define NPAD 640
#define NHW 520
#define KHW 576                 // padded K for GEMM2 (18 x 32)
#define ROWS (BB*TT)            // 16384
#define NCH 256                 // chunks of 8 steps
#define NSEG 8
#define CH_PER_SEG (NCH / NSEG) // 32
#define TSEG (TT / NSEG)        // 256 rows per batch per segment

// ---------------- scratch (static device globals; no dynamic alloc) ----------------
__device__ float g_P[ROWS * NPAD];              // GEMM1 output fp32
__device__ float g_C[ROWS * 64];                // C matrices (b,t,8,8)
__device__ float g_alpha[ROWS * 8];
__device__ float g_bpack[NPAD];                 // packed biases
__device__ float g_A[NS];
__device__ float g_W8[512];                     // W_d = V^T diag(a^d) U, d=0..7, [d][r][c]
__device__ float g_hcarry[BB * NS];             // h carry between scan segments
__device__ float g_wcarry[BB * 8];              // w carry between scan segments
__device__ __nv_bfloat16 g_xh[ROWS * DM];       // x split hi/lo, [M][K]
__device__ __nv_bfloat16 g_xl[ROWS * DM];
__device__ __nv_bfloat16 g_Wh[DM * NPAD];       // Wpack [K=1024][N=640] hi/lo
__device__ __nv_bfloat16 g_Wl[DM * NPAD];
__device__ __nv_bfloat16 g_hwh[ROWS * KHW];     // [h*alpha | alpha | 0pad] hi, bf16
__device__ __nv_bfloat16 g_hwl[ROWS * KHW];     // lo residual
__device__ __nv_bfloat16 g_W2h[KHW * DM];       // W2 [K=576][N=1024] hi/lo
__device__ __nv_bfloat16 g_W2l[KHW * DM];

// ---------------- helpers ----------------
__device__ __forceinline__ uint32_t smem_u32(const void* p) {
    uint32_t a;
    asm("{ .reg .u64 t; cvta.to.shared.u64 t, %1; cvt.u32.u64 %0, t; }" : "=r"(a) : "l"(p));
    return a;
}
__device__ __forceinline__ void cp16(uint32_t dst, const void* src) {
    asm volatile("cp.async.cg.shared.global [%0], [%1], 16;" :: "r"(dst), "l"(src));
}
__device__ __forceinline__ void ldsm4(uint32_t* r, uint32_t addr) {
    asm volatile("ldmatrix.sync.aligned.m8n8.x4.shared.b16 {%0,%1,%2,%3}, [%4];"
                 : "=r"(r[0]), "=r"(r[1]), "=r"(r[2]), "=r"(r[3]) : "r"(addr));
}
__device__ __forceinline__ void ldsm4t(uint32_t* r, uint32_t addr) {
    asm volatile("ldmatrix.sync.aligned.m8n8.x4.trans.shared.b16 {%0,%1,%2,%3}, [%4];"
                 : "=r"(r[0]), "=r"(r[1]), "=r"(r[2]), "=r"(r[3]) : "r"(addr));
}
__device__ __forceinline__ void mma16816(float* d, const uint32_t* a, const uint32_t* b) {
    asm volatile(
        "mma.sync.aligned.m16n8k16.row.col.f32.bf16.bf16.f32 "
        "{%0,%1,%2,%3}, {%4,%5,%6,%7}, {%8,%9}, {%0,%1,%2,%3};\n"
        : "+f"(d[0]), "+f"(d[1]), "+f"(d[2]), "+f"(d[3])
        : "r"(a[0]), "r"(a[1]), "r"(a[2]), "r"(a[3]), "r"(b[0]), "r"(b[1]));
}
__device__ __forceinline__ uint32_t bf16x2_pack(float a, float b) {
    __nv_bfloat162 p = __nv_bfloat162(__float2bfloat16_rn(a), __float2bfloat16_rn(b));
    return *(uint32_t*)&p;
}
__device__ __forceinline__ float dot8v(float4 a0, float4 a1, const float* m) {
    float t0 = fmaf(a0.y, m[1], a0.x * m[0]);
    float t1 = fmaf(a0.w, m[3], a0.z * m[2]);
    float t2 = fmaf(a1.y, m[5], a1.x * m[4]);
    float t3 = fmaf(a1.w, m[7], a1.z * m[6]);
    return (t0 + t1) + (t2 + t3);
}

// smem stage layout (bytes): Ah | Al | Bh | Bl, padded strides for conflict-free ldmatrix
#define ASTR 40
#define BSTR 136
#define A_BYTES (128 * ASTR * 2)
#define B_BYTES (32 * BSTR * 2)
#define OFF_AH 0
#define OFF_AL A_BYTES
#define OFF_BH (2 * A_BYTES)
#define OFF_BL (2 * A_BYTES + B_BYTES)
#define STG (2 * A_BYTES + 2 * B_BYTES)
#define GSMEM (3 * STG)

// ---------------- bf16x3 mma.sync GEMM over one T-segment ----------------
// blockIdx.y in [0,16): batch = by>>1, tile = by&1; m0 = batch*2048 + seg*256 + tile*128.
__global__ void __launch_bounds__(256, 1)
gemm_bf16x3_mma(const __nv_bfloat16* __restrict__ Ah, const __nv_bfloat16* __restrict__ Al,
                const __nv_bfloat16* __restrict__ Bh, const __nv_bfloat16* __restrict__ Bl,
                const float* __restrict__ bias, float* __restrict__ D, int K, int N, int seg)
{
    extern __shared__ char smem[];
    const uint32_t sbase = smem_u32(smem);
    const int tid = threadIdx.x;
    const int lane = tid & 31, w = tid >> 5;
    const int wm = w & 1, wn = w >> 1;
    const int m0 = (blockIdx.y >> 1) * TT + seg * TSEG + (blockIdx.y & 1) * 128;
    const int n0 = blockIdx.x * 128;
    const int NC = K >> 5;

    float acc[4][4][4];
#pragma unroll
    for (int i = 0; i < 4; i++)
#pragma unroll
        for (int j = 0; j < 4; j++)
#pragma unroll
            for (int q = 0; q < 4; q++) acc[i][j][q] = 0.0f;

    const int ar = tid >> 2, as = tid & 3;
    const int br = tid >> 4, bs = tid & 15;

    auto load_stage = [&](int s, int c) {
        const uint32_t st = sbase + s * STG;
        const long kc = (long)c * 32;
        cp16(st + OFF_AH + ar * 80 + as * 16,        Ah + (long)(m0 + ar) * K + kc + as * 8);
        cp16(st + OFF_AH + (ar + 64) * 80 + as * 16, Ah + (long)(m0 + ar + 64) * K + kc + as * 8);
        cp16(st + OFF_AL + ar * 80 + as * 16,        Al + (long)(m0 + ar) * K + kc + as * 8);
        cp16(st + OFF_AL + (ar + 64) * 80 + as * 16, Al + (long)(m0 + ar + 64) * K + kc + as * 8);
        cp16(st + OFF_BH + br * 272 + bs * 16,        Bh + (kc + br) * (long)N + n0 + bs * 8);
        cp16(st + OFF_BH + (br + 16) * 272 + bs * 16, Bh + (kc + br + 16) * (long)N + n0 + bs * 8);
        cp16(st + OFF_BL + br * 272 + bs * 16,        Bl + (kc + br) * (long)N + n0 + bs * 8);
        cp16(st + OFF_BL + (br + 16) * 272 + bs * 16, Bl + (kc + br + 16) * (long)N + n0 + bs * 8);
        asm volatile("cp.async.commit_group;");
    };

    const int pre = (NC < 3) ? NC : 3;
    for (int s = 0; s < pre; s++) load_stage(s, s);

    const uint32_t a_off = (uint32_t)(((wm * 64 + (lane & 15)) * ASTR + ((lane >> 4) << 3)) * 2);
    const uint32_t b_off = (uint32_t)((((lane & 15)) * BSTR + wn * 32 + ((lane >> 4) << 3)) * 2);

    int s = 0;
    for (int kt = 0; kt < NC; ++kt) {
        const int pend = ((NC - kt) < 3 ? (NC - kt) : 3);
        if (pend == 3)      asm volatile("cp.async.wait_group 2;");
        else if (pend == 2) asm volatile("cp.async.wait_group 1;");
        else                asm volatile("cp.async.wait_group 0;");
        __syncthreads();

        const uint32_t st = sbase + s * STG;
        const uint32_t ah_b = st + OFF_AH + a_off;
        const uint32_t al_b = st + OFF_AL + a_off;
        const uint32_t bh_b = st + OFF_BH + b_off;
        const uint32_t bl_b = st + OFF_BL + b_off;

#pragma unroll
        for (int kk = 0; kk < 2; ++kk) {
            uint32_t af[4][4], lf[4][4], bf[2][4], gf[2][4];
#pragma unroll
            for (int mt = 0; mt < 4; mt++) {
                ldsm4(af[mt], ah_b + (mt * 16 * ASTR + kk * 16) * 2);
                ldsm4(lf[mt], al_b + (mt * 16 * ASTR + kk * 16) * 2);
            }
#pragma unroll
            for (int np = 0; np < 2; np++) {
                ldsm4t(bf[np], bh_b + (kk * 16 * BSTR + np * 16) * 2);
                ldsm4t(gf[np], bl_b + (kk * 16 * BSTR + np * 16) * 2);
            }
#pragma unroll
            for (int mt = 0; mt < 4; mt++) {
#pragma unroll
                for (int nt = 0; nt < 4; nt++) {
                    const uint32_t* bp = &bf[nt >> 1][(nt & 1) * 2];
                    const uint32_t* lp = &gf[nt >> 1][(nt & 1) * 2];
                    mma16816(acc[mt][nt], af[mt], bp);
                    mma16816(acc[mt][nt], lf[mt], bp);
                    mma16816(acc[mt][nt], af[mt], lp);
                }
            }
        }
        __syncthreads();
        const int cn = kt + 3;
        if (cn < NC) load_stage(s, cn);
        if (++s == 3) s = 0;
    }

    const int rb = m0 + wm * 64 + (lane >> 2);
    const int cb = n0 + wn * 32 + (lane & 3) * 2;
#pragma unroll
    for (int mt = 0; mt < 4; mt++) {
#pragma unroll
        for (int nt = 0; nt < 4; nt++) {
            const int r = rb + mt * 16;
            const int c = cb + nt * 8;
            float b0 = 0.0f, b1 = 0.0f;
            if (bias) { b0 = bias[c]; b1 = bias[c + 1]; }
            float2 o0 = make_float2(acc[mt][nt][0] + b0, acc[mt][nt][1] + b1);
            float2 o1 = make_float2(acc[mt][nt][2] + b0, acc[mt][nt][3] + b1);
            *(float2*)(D + (size_t)r * N + c) = o0;
            *(float2*)(D + (size_t)(r + 8) * N + c) = o1;
        }
    }
}

// ---------------- conversion / packing kernels ----------------
// per-segment x conversion: seg rows [b*2048 + seg*256, +256) for all b
#define CONV_F4_PER_BATCH (TSEG * DM / 4)       // 65536
__global__ void conv_x_kernel(const float4* __restrict__ src, uint2* __restrict__ dh,
                              uint2* __restrict__ dl, int seg) {
    int i = blockIdx.x * blockDim.x + threadIdx.x;
    if (i >= BB * CONV_F4_PER_BATCH) return;
    int b = i / CONV_F4_PER_BATCH;
    int rem = i - b * CONV_F4_PER_BATCH;
    size_t gi = (size_t)b * (TT * DM / 4) + (size_t)seg * CONV_F4_PER_BATCH + rem;
    float4 v = src[gi];
    float hx = __bfloat162float(__float2bfloat16_rn(v.x));
    float hy = __bfloat162float(__float2bfloat16_rn(v.y));
    float hz = __bfloat162float(__float2bfloat16_rn(v.z));
    float hw = __bfloat162float(__float2bfloat16_rn(v.w));
    uint2 oh, ol;
    oh.x = bf16x2_pack(v.x, v.y); oh.y = bf16x2_pack(v.z, v.w);
    ol.x = bf16x2_pack(v.x - hx, v.y - hy); ol.y = bf16x2_pack(v.z - hz, v.w - hw);
    dh[gi] = oh; dl[gi] = ol;
}

__global__ void pack1b_kernel(const float* __restrict__ Wb, const float* __restrict__ Wdiag,
                              const float* __restrict__ Woff, const float* __restrict__ Walpha) {
    int idx = blockIdx.x * blockDim.x + threadIdx.x;
    if (idx >= DM * NPAD) return;
    int r = idx / NPAD, c = idx - r * NPAD;
    float v;
    if (c < 512)       v = Wb[r * NS + c];
    else if (c < 520)  v = Wdiag[r * 8 + (c - 512)];
    else if (c < 576)  v = Woff[r * 56 + (c - 520)];
    else if (c < 584)  v = Walpha[r * 8 + (c - 576)];
    else               v = 0.0f;
    __nv_bfloat16 h = __float2bfloat16_rn(v);
    g_Wh[idx] = h;
    g_Wl[idx] = __float2bfloat16_rn(v - __bfloat162float(h));
}

__global__ void pack2b_kernel(const float* __restrict__ Wc, const float* __restrict__ bc) {
    int idx = blockIdx.x * blockDim.x + threadIdx.x;
    if (idx >= KHW * DM) return;
    int k = idx >> 10, n = idx & 1023;
    float v;
    if (k < 512)      v = Wc[idx];
    else if (k < 520) v = bc[(size_t)(k - 512) * DM + n];
    else              v = 0.0f;
    __nv_bfloat16 h = __float2bfloat16_rn(v);
    g_W2h[idx] = h;
    g_W2l[idx] = __float2bfloat16_rn(v - __bfloat162float(h));
}

__global__ void misc_kernel(const float* __restrict__ bb, const float* __restrict__ bdiag,
                            const float* __restrict__ boff, const float* __restrict__ balpha,
                            const float* __restrict__ log_lambda) {
    int tid = threadIdx.x;
    if (tid < NS) {
        int k = tid >> 6;
        double dt = 1e-3 * exp((double)k * log(1000.0) / 7.0);
        double ll = (double)log_lambda[tid];
        double sp = log1p(exp(ll));
        g_A[tid] = (float)exp(-dt * sp);
    }
    if (tid < NPAD) {
        float v;
        if (tid < 512)       v = bb[tid];
        else if (tid < 520)  v = bdiag[tid - 512];
        else if (tid < 576)  v = boff[tid - 520];
        else if (tid < 584)  v = balpha[tid - 576];
        else                 v = 0.0f;
        g_bpack[tid] = v;
    }
}

// W_d[r][c] = sum_n V[n,r] * a_n^d * U[n,c], d=0..7  (runs after misc_kernel)
__global__ void wtab_kernel(const float* __restrict__ Uw, const float* __restrict__ Vw) {
    int i = threadIdx.x;
    if (i >= 512) return;
    int d = i >> 6, r = (i >> 3) & 7, c = i & 7;
    float s = 0.0f;
    for (int n = 0; n < NS; n++) {
        float a = g_A[n];
        float p = 1.0f;
        for (int t = 0; t < d; t++) p *= a;
        s += Vw[n * 8 + r] * p * Uw[n * 8 + c];
    }
    g_W8[i] = s;
}

// ---------------- activations for one T-segment ----------------
// grid = 32 blocks; row0 = (bx>>2)*2048 + seg*256 + (bx&3)*64
__global__ void __launch_bounds__(256) act_kernel(int seg) {
    __shared__ float s[64 * 72];
    const int row0 = (blockIdx.x >> 2) * TT + seg * TSEG + (blockIdx.x & 3) * 64;
    const int tid = threadIdx.x;
    for (int i = tid; i < 64 * 72; i += 256) {
        int r = i / 72, c = i - r * 72;
        s[i] = g_P[(size_t)(row0 + r) * NPAD + 512 + c];
    }
    __syncthreads();
    if (tid < 64) {
        const int row = row0 + tid;
        const float* v = &s[tid * 72];
        float dg[8];
#pragma unroll
        for (int i = 0; i < 8; i++) dg[i] = 1.0f / (1.0f + expf(-v[i]));
        float Cm[64];
        int m = 0;
#pragma unroll
        for (int i = 0; i < 8; i++) {
#pragma unroll
            for (int j = 0; j < 8; j++) {
                if (i == j) {
                    Cm[i * 8 + j] = dg[i];
                } else {
                    float x = v[8 + m];
                    float sp = (x > 15.0f) ? x : log1pf(expf(x));
                    Cm[i * 8 + j] = -sp;
                    m++;
                }
            }
        }
#pragma unroll
        for (int q = 0; q < 64; q++) g_C[(size_t)row * 64 + q] = Cm[q];
        float a[8], mx = v[64];
#pragma unroll
        for (int i = 1; i < 8; i++) mx = fmaxf(mx, v[64 + i]);
        float sum = 0.0f;
#pragma unroll
        for (int i = 0; i < 8; i++) { a[i] = expf(v[64 + i] - mx); sum += a[i]; }
        float inv = 1.0f / sum;
#pragma unroll
        for (int k = 0; k < 8; k++) {
            float al = a[k] * inv;
            g_alpha[(size_t)row * 8 + k] = al;
            __nv_bfloat16 h = __float2bfloat16_rn(al);
            g_hwh[(size_t)row * KHW + 512 + k] = h;
            g_hwl[(size_t)row * KHW + 512 + k] = __float2bfloat16_rn(al - __bfloat162float(h));
        }
    }
    const __nv_bfloat16 z = __float2bfloat16_rn(0.0f);
    for (int i = tid; i < 64 * 56; i += 256) {
        int r = i / 56, c = i - r * 56;
        g_hwh[(size_t)(row0 + r) * KHW + 520 + c] = z;
        g_hwl[(size_t)(row0 + r) * KHW + 520 + c] = z;
    }
}

// ---------------- chunked scan over one T-segment (32 chunks of 8 steps) ----------------
#define SCAN_SMEM (15616 * 4)
__global__ void __launch_bounds__(512, 1) scan_kernel(const float* __restrict__ Uw,
                                                      const float* __restrict__ Vw, int seg) {
    extern __shared__ float sm[];
    float* bxs  = sm;             // 8192
    float* fbuf = sm + 8192;      // 4096
    float* hst  = sm + 12288;     // 512
    float* cst  = sm + 12800;     // 1024
    float* ast  = sm + 13824;     // 128
    float* wt   = sm + 13952;     // 512
    float* red  = sm + 14464;     // 1024
    float* pf   = sm + 15488;     // 64
    float* mb   = sm + 15552;     // 64

    const int b = blockIdx.x;
    const int i = threadIdx.x;
    const int wid = i >> 5, lane = i & 31;
    const uint32_t sbase = smem_u32(sm);
    const int cbeg = seg * CH_PER_SEG, cend = cbeg + CH_PER_SEG;

    // init
    hst[i] = (seg == 0) ? 0.0f : g_hcarry[b * NS + i];
    wt[i] = g_W8[i];
    const int k = i & 7, g8 = i >> 3;
    float Vv[8], Urow[8];
#pragma unroll
    for (int q = 0; q < 8; q++) Vv[q] = Vw[(g8 * 8 + q) * 8 + k];
#pragma unroll
    for (int q = 0; q < 8; q++) Urow[q] = Uw[i * 8 + q];
    const float an = g_A[i];
    float wreg[8];
    if (seg == 0) {
#pragma unroll
        for (int q = 0; q < 8; q++) wreg[q] = 0.0f;
    } else {
#pragma unroll
        for (int q = 0; q < 8; q++) wreg[q] = g_wcarry[b * 8 + q];
    }

    const float* bxg = g_P + (size_t)b * TT * NPAD;
    const float* cg  = g_C + (size_t)b * TT * 64;
    const float* ag  = g_alpha + (size_t)b * TT * 8;
    const size_t t0 = (size_t)cbeg * 8;

    // prefill stage for first chunk (cbeg even -> buf 0)
    for (int idx = i; idx < 1024; idx += 512) {
        int t = idx >> 7, sg = idx & 127;
        cp16(sbase + (uint32_t)(t * 512 + sg * 4) * 4, bxg + (t0 + t) * NPAD + sg * 4);
    }
    for (int idx = i; idx < 128; idx += 512) {
        int t = idx >> 4, sg = idx & 15;
        cp16(sbase + (uint32_t)(12800 + t * 64 + sg * 4) * 4, cg + (t0 + t) * 64 + sg * 4);
    }
    if (i < 16) {
        int t = i >> 1, sg = i & 1;
        cp16(sbase + (uint32_t)(13824 + t * 8 + sg * 4) * 4, ag + (t0 + t) * 8 + sg * 4);
    }
    asm volatile("cp.async.commit_group;");
    asm volatile("cp.async.wait_group 0;");
    __syncthreads();

    float ff[8];
    for (int c = cbeg; c < cend; ++c) {
        const int buf = c & 1;
        // ---- Phase A: thread-local f recurrence ----
        float fp = hst[i];
#pragma unroll
        for (int j = 0; j < 8; j++) {
            fp = fmaf(an, fp, bxs[buf * 4096 + j * 512 + i]);
            ff[j] = fp;
            fbuf[j * 512 + i] = fp;
        }
        __syncthreads();

        // ---- Phase B: PF_j = V^T f_j ----
        float pv[8];
        {
            const float* fb = fbuf + g8 * 8;
#pragma unroll
            for (int j = 0; j < 8; j++) {
                float4 f0 = *(const float4*)(fb + j * 512);
                float4 f1 = *(const float4*)(fb + j * 512 + 4);
                pv[j] = dot8v(f0, f1, Vv);
            }
        }
#pragma unroll
        for (int j = 0; j < 8; j++) {
            pv[j] += __shfl_xor_sync(0xffffffffu, pv[j], 8);
            pv[j] += __shfl_xor_sync(0xffffffffu, pv[j], 16);
        }
        if (lane < 8) {
#pragma unroll
            for (int j = 0; j < 8; j++) red[(j * 8 + lane) * 16 + wid] = pv[j];
        }
        __syncthreads();
        if (i < 64) {
            const float* rb = red + i * 16;
            float4 r0 = *(const float4*)rb,       r1 = *(const float4*)(rb + 4);
            float4 r2 = *(const float4*)(rb + 8), r3 = *(const float4*)(rb + 12);
            pf[i] = ((r0.x + r0.y) + (r0.z + r0.w)) + ((r1.x + r1.y) + (r1.z + r1.w))
                  + ((r2.x + r2.y) + (r2.z + r2.w)) + ((r3.x + r3.y) + (r3.z + r3.w));
        } else if (i >= 128 && c + 1 < cend) {
            // stage next chunk
            const int nb = buf ^ 1;
            const size_t tb = (size_t)(c + 1) * 8;
            const int tt = i - 128;
            for (int idx = tt; idx < 1024; idx += 384) {
                int t = idx >> 7, sg = idx & 127;
                cp16(sbase + (uint32_t)(nb * 4096 + t * 512 + sg * 4) * 4,
                     bxg + (tb + t) * NPAD + sg * 4);
            }
            for (int idx = tt; idx < 128; idx += 384) {
                int t = idx >> 4, sg = idx & 15;
                cp16(sbase + (uint32_t)(12800 + nb * 512 + t * 64 + sg * 4) * 4,
                     cg + (tb + t) * 64 + sg * 4);
            }
            if (tt < 16) {
                int t = tt >> 1, sg = tt & 1;
                cp16(sbase + (uint32_t)(13824 + nb * 64 + t * 8 + sg * 4) * 4,
                     ag + (tb + t) * 8 + sg * 4);
            }
            asm volatile("cp.async.commit_group;");
        }
        __syncthreads();

        // ---- Phase C: serial 8-dim chain (warp 0) ----
        if (wid == 0) {
            const int r = lane & 7, dup = lane >> 3;
            const int j1 = dup, j2 = dup + 4;
            float PFr[8];
#pragma unroll
            for (int s = 0; s < 8; s++) PFr[s] = pf[s * 8 + r];
            float accA = 0.0f, accB = 0.0f;
            const float* cb = cst + buf * 512;
#pragma unroll
            for (int s = 0; s < 8; s++) {
                float4 c0 = *(const float4*)(cb + s * 64 + r * 8);
                float4 c1 = *(const float4*)(cb + s * 64 + r * 8 + 4);
                float mr = dot8v(c0, c1, wreg);
                float mf[8];
#pragma unroll
                for (int q = 0; q < 8; q++) mf[q] = __shfl_sync(0xffffffffu, mr, q + (dup << 3));
                if (j1 >= s) {
                    const float* wr = wt + ((j1 - s) * 8 + r) * 8;
                    accA += dot8v(*(const float4*)wr, *(const float4*)(wr + 4), mf);
                }
                if (j2 >= s) {
                    const float* wr = wt + ((j2 - s) * 8 + r) * 8;
                    accB += dot8v(*(const float4*)wr, *(const float4*)(wr + 4), mf);
                }
                float wv = (j1 == s) ? (PFr[s] + accA) : ((j2 == s) ? (PFr[s] + accB) : 0.0f);
#pragma unroll
                for (int q = 0; q < 8; q++) wreg[q] = __shfl_sync(0xffffffffu, wv, q + ((s & 3) << 3));
                if (dup == 0) mb[s * 8 + r] = mr;
            }
        } else {
            asm volatile("cp.async.wait_group 0;");
        }
        __syncthreads();

        // ---- Phase D: reconstruct h + emit hw ----
        {
            float g = 0.0f;
            const size_t row0 = (size_t)b * TT + (size_t)c * 8;
            __nv_bfloat16* oh = g_hwh + row0 * KHW + i;
            __nv_bfloat16* ol = g_hwl + row0 * KHW + i;
            const float* as_ = ast + buf * 64;
            const int ab = i >> 6;
            float hlast = 0.0f;
#pragma unroll
            for (int j = 0; j < 8; j++) {
                float4 m0 = *(const float4*)(mb + j * 8);
                float4 m1 = *(const float4*)(mb + j * 8 + 4);
                float um = dot8v(m0, m1, Urow);
                g = fmaf(an, g, um);
                float h = ff[j] + g;
                float wv = h * as_[j * 8 + ab];
                __nv_bfloat16 hi = __float2bfloat16_rn(wv);
                oh[(size_t)j * KHW] = hi;
                ol[(size_t)j * KHW] = __float2bfloat16_rn(wv - __bfloat162float(hi));
                hlast = h;
            }
            hst[i] = hlast;
        }
        __syncthreads();
    }

    // write carries for next segment
    g_hcarry[b * NS + i] = hst[i];
    if (wid == 0 && lane == 0) {
#pragma unroll
        for (int q = 0; q < 8; q++) g_wcarry[b * 8 + q] = wreg[q];
    }
}

// ---------------- launch: 8-segment software pipeline across 3 streams ----------------
extern "C" void kernel_launch(void* const* d_in, const int* in_sizes, int n_in,
                              void* d_out, int out_size) {
    const float* x      = (const float*)d_in[0];
    const float* Wb     = (const float*)d_in[1];
    const float* bb     = (const float*)d_in[2];
    const float* Wdiag  = (const float*)d_in[3];
    const float* bdiag  = (const float*)d_in[4];
    const float* Woff   = (const float*)d_in[5];
    const float* boff   = (const float*)d_in[6];
    const float* Walpha = (const float*)d_in[7];
    const float* balpha = (const float*)d_in[8];
    const float* Wc     = (const float*)d_in[9];
    const float* bc     = (const float*)d_in[10];
    const float* ll     = (const float*)d_in[11];
    const float* U      = (const float*)d_in[12];
    const float* V      = (const float*)d_in[13];
    float* out = (float*)d_out;

    float *pP, *pbpack;
    __nv_bfloat16 *pxh, *pxl, *pWh, *pWl, *phwh, *phwl, *pW2h, *pW2l;
    cudaGetSymbolAddress((void**)&pP,     g_P);
    cudaGetSymbolAddress((void**)&pbpack, g_bpack);
    cudaGetSymbolAddress((void**)&pxh,    g_xh);
    cudaGetSymbolAddress((void**)&pxl,    g_xl);
    cudaGetSymbolAddress((void**)&pWh,    g_Wh);
    cudaGetSymbolAddress((void**)&pWl,    g_Wl);
    cudaGetSymbolAddress((void**)&phwh,   g_hwh);
    cudaGetSymbolAddress((void**)&phwl,   g_hwl);
    cudaGetSymbolAddress((void**)&pW2h,   g_W2h);
    cudaGetSymbolAddress((void**)&pW2l,   g_W2l);

    cudaFuncSetAttribute(gemm_bf16x3_mma, cudaFuncAttributeMaxDynamicSharedMemorySize, GSMEM);
    cudaFuncSetAttribute(scan_kernel, cudaFuncAttributeMaxDynamicSharedMemorySize, SCAN_SMEM);

    static cudaStream_t sB = nullptr, sC = nullptr;
    static cudaEvent_t evA[NSEG], evS[NSEG], evEnd = nullptr;
    static int streams_ok = -1;
    if (streams_ok < 0) {
        bool ok = (cudaStreamCreateWithFlags(&sB, cudaStreamNonBlocking) == cudaSuccess) &&
                  (cudaStreamCreateWithFlags(&sC, cudaStreamNonBlocking) == cudaSuccess);
        for (int s = 0; s < NSEG && ok; s++) {
            ok = (cudaEventCreateWithFlags(&evA[s], cudaEventDisableTiming) == cudaSuccess) &&
                 (cudaEventCreateWithFlags(&evS[s], cudaEventDisableTiming) == cudaSuccess);
        }
        ok = ok && (cudaEventCreateWithFlags(&evEnd, cudaEventDisableTiming) == cudaSuccess);
        streams_ok = ok ? 1 : 0;
    }

    const int conv_blocks = (BB * CONV_F4_PER_BATCH + 255) / 256;

    if (streams_ok == 1) {
        // head: pack2b on GEMM2's stream; everything else on stream 0
        pack2b_kernel<<<(KHW * DM + 255) / 256, 256, 0, sC>>>(Wc, bc);
        pack1b_kernel<<<(DM * NPAD + 255) / 256, 256>>>(Wb, Wdiag, Woff, Walpha);
        misc_kernel<<<1, 1024>>>(bb, bdiag, boff, balpha, ll);
        wtab_kernel<<<1, 512>>>(U, V);

        // producer chain on stream 0: conv seg + GEMM1 seg + act seg
        for (int s = 0; s < NSEG; s++) {
            conv_x_kernel<<<conv_blocks, 256>>>((const float4*)x, (uint2*)pxh, (uint2*)pxl, s);
            gemm_bf16x3_mma<<<dim3(NPAD / 128, 16), 256, GSMEM>>>(pxh, pxl, pWh, pWl,
                                                                  pbpack, pP, DM, NPAD, s);
            act_kernel<<<32, 256>>>(s);
            cudaEventRecord(evA[s], 0);
        }
        // scan chain on stream B
        for (int s = 0; s < NSEG; s++) {
            cudaStreamWaitEvent(sB, evA[s], 0);
            scan_kernel<<<BB, 512, SCAN_SMEM, sB>>>(U, V, s);
            cudaEventRecord(evS[s], sB);
        }
        // GEMM2 chain on stream C
        for (int s = 0; s < NSEG; s++) {
            cudaStreamWaitEvent(sC, evS[s], 0);
            gemm_bf16x3_mma<<<dim3(DM / 128, 16), 256, GSMEM, sC>>>(phwh, phwl, pW2h, pW2l,
                                                                    nullptr, out, KHW, DM, s);
        }
        cudaEventRecord(evEnd, sC);
        cudaStreamWaitEvent(0, evEnd, 0);
    } else {
        // sequential fallback on stream 0
        pack2b_kernel<<<(KHW * DM + 255) / 256, 256>>>(Wc, bc);
        pack1b_kernel<<<(DM * NPAD + 255) / 256, 256>>>(Wb, Wdiag, Woff, Walpha);
        misc_kernel<<<1, 1024>>>(bb, bdiag, boff, balpha, ll);
        wtab_kernel<<<1, 512>>>(U, V);
        for (int s = 0; s < NSEG; s++) {
            conv_x_kernel<<<conv_blocks, 256>>>((const float4*)x, (uint2*)pxh, (uint2*)pxl, s);
            gemm_bf16x3_mma<<<dim3(NPAD / 128, 16), 256, GSMEM>>>(pxh, pxl, pWh, pWl,
                                                                  pbpack, pP, DM, NPAD, s);
            act_kernel<<<32, 256>>>(s);
        }
        for (int s = 0; s < NSEG; s++) scan_kernel<<<BB, 512, SCAN_SMEM>>>(U, V, s);
        for (int s = 0; s < NSEG; s++)
            gemm_bf16x3_mma<<<dim3(DM / 128, 16), 256, GSMEM>>>(phwh, phwl, pW2h, pW2l,
                                                                nullptr, out, KHW, DM, s);
    }
}

// round 12
// speedup vs baseline: 2.6825x; 1.1185x over previous
#include <cuda_runtime.h>
#include <cuda_bf16.h>
#include <cstdint>
#include <math.h>

#define BB 8
#define TT 2048
#define DM 1024
#define NS 512
#define NPAD 640
#define NHW 520
#define KHW 576                 // padded K for GEMM2 (18 x 32)
#define ROWS (BB*TT)            // 16384
#define NCH 256                 // chunks of 8 steps
#define NSEG 8
#define CH_PER_SEG (NCH / NSEG) // 32
#define TSEG (TT / NSEG)        // 256 rows per batch per segment

// ---------------- scratch (static device globals; no dynamic alloc) ----------------
__device__ float g_P[ROWS * NPAD];              // GEMM1 output fp32
__device__ float g_C[ROWS * 64];                // C matrices (b,t,8,8)
__device__ float g_alpha[ROWS * 8];
__device__ float g_bpack[NPAD];                 // packed biases
__device__ float g_A[NS];
__device__ float g_W8[512];                     // W_d = V^T diag(a^d) U, d=0..7, [d][r][c]
__device__ float g_hcarry[BB * NS];             // h carry between scan segments
__device__ float g_wcarry[BB * 8];              // w carry between scan segments
__device__ __nv_bfloat16 g_xh[ROWS * DM];       // x split hi/lo, [M][K]
__device__ __nv_bfloat16 g_xl[ROWS * DM];
__device__ __nv_bfloat16 g_Wh[DM * NPAD];       // Wpack [K=1024][N=640] hi/lo
__device__ __nv_bfloat16 g_Wl[DM * NPAD];
__device__ __nv_bfloat16 g_hwh[ROWS * KHW];     // [h*alpha | alpha | 0pad] hi, bf16
__device__ __nv_bfloat16 g_hwl[ROWS * KHW];     // lo residual
__device__ __nv_bfloat16 g_W2h[KHW * DM];       // W2 [K=576][N=1024] hi/lo
__device__ __nv_bfloat16 g_W2l[KHW * DM];

// ---------------- helpers ----------------
__device__ __forceinline__ uint32_t smem_u32(const void* p) {
    uint32_t a;
    asm("{ .reg .u64 t; cvta.to.shared.u64 t, %1; cvt.u32.u64 %0, t; }" : "=r"(a) : "l"(p));
    return a;
}
__device__ __forceinline__ void cp16(uint32_t dst, const void* src) {
    asm volatile("cp.async.cg.shared.global [%0], [%1], 16;" :: "r"(dst), "l"(src));
}
__device__ __forceinline__ void ldsm4(uint32_t* r, uint32_t addr) {
    asm volatile("ldmatrix.sync.aligned.m8n8.x4.shared.b16 {%0,%1,%2,%3}, [%4];"
                 : "=r"(r[0]), "=r"(r[1]), "=r"(r[2]), "=r"(r[3]) : "r"(addr));
}
__device__ __forceinline__ void ldsm4t(uint32_t* r, uint32_t addr) {
    asm volatile("ldmatrix.sync.aligned.m8n8.x4.trans.shared.b16 {%0,%1,%2,%3}, [%4];"
                 : "=r"(r[0]), "=r"(r[1]), "=r"(r[2]), "=r"(r[3]) : "r"(addr));
}
__device__ __forceinline__ void mma16816(float* d, const uint32_t* a, const uint32_t* b) {
    asm volatile(
        "mma.sync.aligned.m16n8k16.row.col.f32.bf16.bf16.f32 "
        "{%0,%1,%2,%3}, {%4,%5,%6,%7}, {%8,%9}, {%0,%1,%2,%3};\n"
        : "+f"(d[0]), "+f"(d[1]), "+f"(d[2]), "+f"(d[3])
        : "r"(a[0]), "r"(a[1]), "r"(a[2]), "r"(a[3]), "r"(b[0]), "r"(b[1]));
}
__device__ __forceinline__ uint32_t bf16x2_pack(float a, float b) {
    __nv_bfloat162 p = __nv_bfloat162(__float2bfloat16_rn(a), __float2bfloat16_rn(b));
    return *(uint32_t*)&p;
}
__device__ __forceinline__ float dot8v(float4 a0, float4 a1, const float* m) {
    float t0 = fmaf(a0.y, m[1], a0.x * m[0]);
    float t1 = fmaf(a0.w, m[3], a0.z * m[2]);
    float t2 = fmaf(a1.y, m[5], a1.x * m[4]);
    float t3 = fmaf(a1.w, m[7], a1.z * m[6]);
    return (t0 + t1) + (t2 + t3);
}

// smem stage layout (bytes): Ah | Al | Bh | Bl, padded strides for conflict-free ldmatrix
#define ASTR 40
#define BSTR 136
#define A_BYTES (128 * ASTR * 2)
#define B_BYTES (32 * BSTR * 2)
#define OFF_AH 0
#define OFF_AL A_BYTES
#define OFF_BH (2 * A_BYTES)
#define OFF_BL (2 * A_BYTES + B_BYTES)
#define STG (2 * A_BYTES + 2 * B_BYTES)
#define GSMEM (3 * STG)

// ---------------- bf16x3 mma.sync GEMM over one T-segment ----------------
__global__ void __launch_bounds__(256, 1)
gemm_bf16x3_mma(const __nv_bfloat16* __restrict__ Ah, const __nv_bfloat16* __restrict__ Al,
                const __nv_bfloat16* __restrict__ Bh, const __nv_bfloat16* __restrict__ Bl,
                const float* __restrict__ bias, float* __restrict__ D, int K, int N, int seg)
{
    extern __shared__ char smem[];
    const uint32_t sbase = smem_u32(smem);
    const int tid = threadIdx.x;
    const int lane = tid & 31, w = tid >> 5;
    const int wm = w & 1, wn = w >> 1;
    const int m0 = (blockIdx.y >> 1) * TT + seg * TSEG + (blockIdx.y & 1) * 128;
    const int n0 = blockIdx.x * 128;
    const int NC = K >> 5;

    float acc[4][4][4];
#pragma unroll
    for (int i = 0; i < 4; i++)
#pragma unroll
        for (int j = 0; j < 4; j++)
#pragma unroll
            for (int q = 0; q < 4; q++) acc[i][j][q] = 0.0f;

    const int ar = tid >> 2, as = tid & 3;
    const int br = tid >> 4, bs = tid & 15;

    auto load_stage = [&](int s, int c) {
        const uint32_t st = sbase + s * STG;
        const long kc = (long)c * 32;
        cp16(st + OFF_AH + ar * 80 + as * 16,        Ah + (long)(m0 + ar) * K + kc + as * 8);
        cp16(st + OFF_AH + (ar + 64) * 80 + as * 16, Ah + (long)(m0 + ar + 64) * K + kc + as * 8);
        cp16(st + OFF_AL + ar * 80 + as * 16,        Al + (long)(m0 + ar) * K + kc + as * 8);
        cp16(st + OFF_AL + (ar + 64) * 80 + as * 16, Al + (long)(m0 + ar + 64) * K + kc + as * 8);
        cp16(st + OFF_BH + br * 272 + bs * 16,        Bh + (kc + br) * (long)N + n0 + bs * 8);
        cp16(st + OFF_BH + (br + 16) * 272 + bs * 16, Bh + (kc + br + 16) * (long)N + n0 + bs * 8);
        cp16(st + OFF_BL + br * 272 + bs * 16,        Bl + (kc + br) * (long)N + n0 + bs * 8);
        cp16(st + OFF_BL + (br + 16) * 272 + bs * 16, Bl + (kc + br + 16) * (long)N + n0 + bs * 8);
        asm volatile("cp.async.commit_group;");
    };

    const int pre = (NC < 3) ? NC : 3;
    for (int s = 0; s < pre; s++) load_stage(s, s);

    const uint32_t a_off = (uint32_t)(((wm * 64 + (lane & 15)) * ASTR + ((lane >> 4) << 3)) * 2);
    const uint32_t b_off = (uint32_t)((((lane & 15)) * BSTR + wn * 32 + ((lane >> 4) << 3)) * 2);

    int s = 0;
    for (int kt = 0; kt < NC; ++kt) {
        const int pend = ((NC - kt) < 3 ? (NC - kt) : 3);
        if (pend == 3)      asm volatile("cp.async.wait_group 2;");
        else if (pend == 2) asm volatile("cp.async.wait_group 1;");
        else                asm volatile("cp.async.wait_group 0;");
        __syncthreads();

        const uint32_t st = sbase + s * STG;
        const uint32_t ah_b = st + OFF_AH + a_off;
        const uint32_t al_b = st + OFF_AL + a_off;
        const uint32_t bh_b = st + OFF_BH + b_off;
        const uint32_t bl_b = st + OFF_BL + b_off;

#pragma unroll
        for (int kk = 0; kk < 2; ++kk) {
            uint32_t af[4][4], lf[4][4], bf[2][4], gf[2][4];
#pragma unroll
            for (int mt = 0; mt < 4; mt++) {
                ldsm4(af[mt], ah_b + (mt * 16 * ASTR + kk * 16) * 2);
                ldsm4(lf[mt], al_b + (mt * 16 * ASTR + kk * 16) * 2);
            }
#pragma unroll
            for (int np = 0; np < 2; np++) {
                ldsm4t(bf[np], bh_b + (kk * 16 * BSTR + np * 16) * 2);
                ldsm4t(gf[np], bl_b + (kk * 16 * BSTR + np * 16) * 2);
            }
#pragma unroll
            for (int mt = 0; mt < 4; mt++) {
#pragma unroll
                for (int nt = 0; nt < 4; nt++) {
                    const uint32_t* bp = &bf[nt >> 1][(nt & 1) * 2];
                    const uint32_t* lp = &gf[nt >> 1][(nt & 1) * 2];
                    mma16816(acc[mt][nt], af[mt], bp);
                    mma16816(acc[mt][nt], lf[mt], bp);
                    mma16816(acc[mt][nt], af[mt], lp);
                }
            }
        }
        __syncthreads();
        const int cn = kt + 3;
        if (cn < NC) load_stage(s, cn);
        if (++s == 3) s = 0;
    }

    const int rb = m0 + wm * 64 + (lane >> 2);
    const int cb = n0 + wn * 32 + (lane & 3) * 2;
#pragma unroll
    for (int mt = 0; mt < 4; mt++) {
#pragma unroll
        for (int nt = 0; nt < 4; nt++) {
            const int r = rb + mt * 16;
            const int c = cb + nt * 8;
            float b0 = 0.0f, b1 = 0.0f;
            if (bias) { b0 = bias[c]; b1 = bias[c + 1]; }
            float2 o0 = make_float2(acc[mt][nt][0] + b0, acc[mt][nt][1] + b1);
            float2 o1 = make_float2(acc[mt][nt][2] + b0, acc[mt][nt][3] + b1);
            *(float2*)(D + (size_t)r * N + c) = o0;
            *(float2*)(D + (size_t)(r + 8) * N + c) = o1;
        }
    }
}

// ---------------- conversion / packing kernels ----------------
#define CONV_F4_PER_BATCH (TSEG * DM / 4)       // 65536
__global__ void conv_x_kernel(const float4* __restrict__ src, uint2* __restrict__ dh,
                              uint2* __restrict__ dl, int seg) {
    int i = blockIdx.x * blockDim.x + threadIdx.x;
    if (i >= BB * CONV_F4_PER_BATCH) return;
    int b = i / CONV_F4_PER_BATCH;
    int rem = i - b * CONV_F4_PER_BATCH;
    size_t gi = (size_t)b * (TT * DM / 4) + (size_t)seg * CONV_F4_PER_BATCH + rem;
    float4 v = src[gi];
    float hx = __bfloat162float(__float2bfloat16_rn(v.x));
    float hy = __bfloat162float(__float2bfloat16_rn(v.y));
    float hz = __bfloat162float(__float2bfloat16_rn(v.z));
    float hw = __bfloat162float(__float2bfloat16_rn(v.w));
    uint2 oh, ol;
    oh.x = bf16x2_pack(v.x, v.y); oh.y = bf16x2_pack(v.z, v.w);
    ol.x = bf16x2_pack(v.x - hx, v.y - hy); ol.y = bf16x2_pack(v.z - hz, v.w - hw);
    dh[gi] = oh; dl[gi] = ol;
}

__global__ void pack1b_kernel(const float* __restrict__ Wb, const float* __restrict__ Wdiag,
                              const float* __restrict__ Woff, const float* __restrict__ Walpha) {
    int idx = blockIdx.x * blockDim.x + threadIdx.x;
    if (idx >= DM * NPAD) return;
    int r = idx / NPAD, c = idx - r * NPAD;
    float v;
    if (c < 512)       v = Wb[r * NS + c];
    else if (c < 520)  v = Wdiag[r * 8 + (c - 512)];
    else if (c < 576)  v = Woff[r * 56 + (c - 520)];
    else if (c < 584)  v = Walpha[r * 8 + (c - 576)];
    else               v = 0.0f;
    __nv_bfloat16 h = __float2bfloat16_rn(v);
    g_Wh[idx] = h;
    g_Wl[idx] = __float2bfloat16_rn(v - __bfloat162float(h));
}

__global__ void pack2b_kernel(const float* __restrict__ Wc, const float* __restrict__ bc) {
    int idx = blockIdx.x * blockDim.x + threadIdx.x;
    if (idx >= KHW * DM) return;
    int k = idx >> 10, n = idx & 1023;
    float v;
    if (k < 512)      v = Wc[idx];
    else if (k < 520) v = bc[(size_t)(k - 512) * DM + n];
    else              v = 0.0f;
    __nv_bfloat16 h = __float2bfloat16_rn(v);
    g_W2h[idx] = h;
    g_W2l[idx] = __float2bfloat16_rn(v - __bfloat162float(h));
}

__global__ void misc_kernel(const float* __restrict__ bb, const float* __restrict__ bdiag,
                            const float* __restrict__ boff, const float* __restrict__ balpha,
                            const float* __restrict__ log_lambda) {
    int tid = threadIdx.x;
    if (tid < NS) {
        int k = tid >> 6;
        double dt = 1e-3 * exp((double)k * log(1000.0) / 7.0);
        double ll = (double)log_lambda[tid];
        double sp = log1p(exp(ll));
        g_A[tid] = (float)exp(-dt * sp);
    }
    if (tid < NPAD) {
        float v;
        if (tid < 512)       v = bb[tid];
        else if (tid < 520)  v = bdiag[tid - 512];
        else if (tid < 576)  v = boff[tid - 520];
        else if (tid < 584)  v = balpha[tid - 576];
        else                 v = 0.0f;
        g_bpack[tid] = v;
    }
}

// W_d[r][c] = sum_n V[n,r] * a_n^d * U[n,c]; one block per output, 128-thread reduce.
__global__ void __launch_bounds__(128) wtab_kernel(const float* __restrict__ Uw,
                                                   const float* __restrict__ Vw) {
    __shared__ float warpsum[4];
    const int o = blockIdx.x;               // 0..511
    const int d = o >> 6, r = (o >> 3) & 7, c = o & 7;
    const int t = threadIdx.x;
    float s = 0.0f;
#pragma unroll
    for (int q = 0; q < 4; q++) {
        int n = t + q * 128;
        float a = g_A[n];
        float p = 1.0f;
        for (int e = 0; e < d; e++) p *= a;
        s += Vw[n * 8 + r] * p * Uw[n * 8 + c];
    }
    s += __shfl_xor_sync(0xffffffffu, s, 16);
    s += __shfl_xor_sync(0xffffffffu, s, 8);
    s += __shfl_xor_sync(0xffffffffu, s, 4);
    s += __shfl_xor_sync(0xffffffffu, s, 2);
    s += __shfl_xor_sync(0xffffffffu, s, 1);
    if ((t & 31) == 0) warpsum[t >> 5] = s;
    __syncthreads();
    if (t == 0)
        g_W8[o] = (warpsum[0] + warpsum[1]) + (warpsum[2] + warpsum[3]);
}

// ---------------- activations for one T-segment ----------------
__global__ void __launch_bounds__(256) act_kernel(int seg) {
    __shared__ float s[64 * 72];
    const int row0 = (blockIdx.x >> 2) * TT + seg * TSEG + (blockIdx.x & 3) * 64;
    const int tid = threadIdx.x;
    for (int i = tid; i < 64 * 72; i += 256) {
        int r = i / 72, c = i - r * 72;
        s[i] = g_P[(size_t)(row0 + r) * NPAD + 512 + c];
    }
    __syncthreads();
    if (tid < 64) {
        const int row = row0 + tid;
        const float* v = &s[tid * 72];
        float dg[8];
#pragma unroll
        for (int i = 0; i < 8; i++) dg[i] = 1.0f / (1.0f + expf(-v[i]));
        float Cm[64];
        int m = 0;
#pragma unroll
        for (int i = 0; i < 8; i++) {
#pragma unroll
            for (int j = 0; j < 8; j++) {
                if (i == j) {
                    Cm[i * 8 + j] = dg[i];
                } else {
                    float x = v[8 + m];
                    float sp = (x > 15.0f) ? x : log1pf(expf(x));
                    Cm[i * 8 + j] = -sp;
                    m++;
                }
            }
        }
#pragma unroll
        for (int q = 0; q < 64; q++) g_C[(size_t)row * 64 + q] = Cm[q];
        float a[8], mx = v[64];
#pragma unroll
        for (int i = 1; i < 8; i++) mx = fmaxf(mx, v[64 + i]);
        float sum = 0.0f;
#pragma unroll
        for (int i = 0; i < 8; i++) { a[i] = expf(v[64 + i] - mx); sum += a[i]; }
        float inv = 1.0f / sum;
#pragma unroll
        for (int k = 0; k < 8; k++) {
            float al = a[k] * inv;
            g_alpha[(size_t)row * 8 + k] = al;
            __nv_bfloat16 h = __float2bfloat16_rn(al);
            g_hwh[(size_t)row * KHW + 512 + k] = h;
            g_hwl[(size_t)row * KHW + 512 + k] = __float2bfloat16_rn(al - __bfloat162float(h));
        }
    }
    const __nv_bfloat16 z = __float2bfloat16_rn(0.0f);
    for (int i = tid; i < 64 * 56; i += 256) {
        int r = i / 56, c = i - r * 56;
        g_hwh[(size_t)(row0 + r) * KHW + 520 + c] = z;
        g_hwl[(size_t)(row0 + r) * KHW + 520 + c] = z;
    }
}

// ---------------- chunked scan over one T-segment (32 chunks of 8 steps) ----------------
#define SCAN_SMEM (15616 * 4)
__global__ void __launch_bounds__(512, 1) scan_kernel(const float* __restrict__ Uw,
                                                      const float* __restrict__ Vw, int seg) {
    extern __shared__ float sm[];
    float* bxs  = sm;             // 8192
    float* fbuf = sm + 8192;      // 4096
    float* hst  = sm + 12288;     // 512
    float* cst  = sm + 12800;     // 1024
    float* ast  = sm + 13824;     // 128
    float* wt   = sm + 13952;     // 512
    float* red  = sm + 14464;     // 1024
    float* pf   = sm + 15488;     // 64
    float* mb   = sm + 15552;     // 64

    const int b = blockIdx.x;
    const int i = threadIdx.x;
    const int wid = i >> 5, lane = i & 31;
    const uint32_t sbase = smem_u32(sm);
    const int cbeg = seg * CH_PER_SEG, cend = cbeg + CH_PER_SEG;

    // init
    hst[i] = (seg == 0) ? 0.0f : g_hcarry[b * NS + i];
    wt[i] = g_W8[i];
    const int k = i & 7, g8 = i >> 3;
    float Vv[8], Urow[8];
#pragma unroll
    for (int q = 0; q < 8; q++) Vv[q] = Vw[(g8 * 8 + q) * 8 + k];
#pragma unroll
    for (int q = 0; q < 8; q++) Urow[q] = Uw[i * 8 + q];
    const float an = g_A[i];
    float wreg[8];
    if (seg == 0) {
#pragma unroll
        for (int q = 0; q < 8; q++) wreg[q] = 0.0f;
    } else {
#pragma unroll
        for (int q = 0; q < 8; q++) wreg[q] = g_wcarry[b * 8 + q];
    }

    const float* bxg = g_P + (size_t)b * TT * NPAD;
    const float* cg  = g_C + (size_t)b * TT * 64;
    const float* ag  = g_alpha + (size_t)b * TT * 8;
    const size_t t0 = (size_t)cbeg * 8;

    // prefill stage for first chunk (cbeg even -> buf 0)
    for (int idx = i; idx < 1024; idx += 512) {
        int t = idx >> 7, sg = idx & 127;
        cp16(sbase + (uint32_t)(t * 512 + sg * 4) * 4, bxg + (t0 + t) * NPAD + sg * 4);
    }
    for (int idx = i; idx < 128; idx += 512) {
        int t = idx >> 4, sg = idx & 15;
        cp16(sbase + (uint32_t)(12800 + t * 64 + sg * 4) * 4, cg + (t0 + t) * 64 + sg * 4);
    }
    if (i < 16) {
        int t = i >> 1, sg = i & 1;
        cp16(sbase + (uint32_t)(13824 + t * 8 + sg * 4) * 4, ag + (t0 + t) * 8 + sg * 4);
    }
    asm volatile("cp.async.commit_group;");
    asm volatile("cp.async.wait_group 0;");
    __syncthreads();

    float ff[8];
    for (int c = cbeg; c < cend; ++c) {
        const int buf = c & 1;
        // ---- Phase A: thread-local f recurrence ----
        float fp = hst[i];
#pragma unroll
        for (int j = 0; j < 8; j++) {
            fp = fmaf(an, fp, bxs[buf * 4096 + j * 512 + i]);
            ff[j] = fp;
            fbuf[j * 512 + i] = fp;
        }
        __syncthreads();

        // ---- Phase B: PF_j = V^T f_j ----
        float pv[8];
        {
            const float* fb = fbuf + g8 * 8;
#pragma unroll
            for (int j = 0; j < 8; j++) {
                float4 f0 = *(const float4*)(fb + j * 512);
                float4 f1 = *(const float4*)(fb + j * 512 + 4);
                pv[j] = dot8v(f0, f1, Vv);
            }
        }
#pragma unroll
        for (int j = 0; j < 8; j++) {
            pv[j] += __shfl_xor_sync(0xffffffffu, pv[j], 8);
            pv[j] += __shfl_xor_sync(0xffffffffu, pv[j], 16);
        }
        if (lane < 8) {
#pragma unroll
            for (int j = 0; j < 8; j++) red[(j * 8 + lane) * 16 + wid] = pv[j];
        }
        __syncthreads();
        if (i < 64) {
            const float* rb = red + i * 16;
            float4 r0 = *(const float4*)rb,       r1 = *(const float4*)(rb + 4);
            float4 r2 = *(const float4*)(rb + 8), r3 = *(const float4*)(rb + 12);
            pf[i] = ((r0.x + r0.y) + (r0.z + r0.w)) + ((r1.x + r1.y) + (r1.z + r1.w))
                  + ((r2.x + r2.y) + (r2.z + r2.w)) + ((r3.x + r3.y) + (r3.z + r3.w));
        } else if (i >= 128 && c + 1 < cend) {
            // stage next chunk
            const int nb = buf ^ 1;
            const size_t tb = (size_t)(c + 1) * 8;
            const int tt = i - 128;
            for (int idx = tt; idx < 1024; idx += 384) {
                int t = idx >> 7, sg = idx & 127;
                cp16(sbase + (uint32_t)(nb * 4096 + t * 512 + sg * 4) * 4,
                     bxg + (tb + t) * NPAD + sg * 4);
            }
            for (int idx = tt; idx < 128; idx += 384) {
                int t = idx >> 4, sg = idx & 15;
                cp16(sbase + (uint32_t)(12800 + nb * 512 + t * 64 + sg * 4) * 4,
                     cg + (tb + t) * 64 + sg * 4);
            }
            if (tt < 16) {
                int t = tt >> 1, sg = tt & 1;
                cp16(sbase + (uint32_t)(13824 + nb * 64 + t * 8 + sg * 4) * 4,
                     ag + (tb + t) * 8 + sg * 4);
            }
            asm volatile("cp.async.commit_group;");
        }
        __syncthreads();

        // ---- Phase C: serial 8-dim chain (warp 0) ----
        if (wid == 0) {
            const int r = lane & 7, dup = lane >> 3;
            const int j1 = dup, j2 = dup + 4;
            float PFr[8];
#pragma unroll
            for (int s = 0; s < 8; s++) PFr[s] = pf[s * 8 + r];
            float accA = 0.0f, accB = 0.0f;
            const float* cb = cst + buf * 512;
#pragma unroll
            for (int s = 0; s < 8; s++) {
                float4 c0 = *(const float4*)(cb + s * 64 + r * 8);
                float4 c1 = *(const float4*)(cb + s * 64 + r * 8 + 4);
                float mr = dot8v(c0, c1, wreg);
                float mf[8];
#pragma unroll
                for (int q = 0; q < 8; q++) mf[q] = __shfl_sync(0xffffffffu, mr, q + (dup << 3));
                if (j1 >= s) {
                    const float* wr = wt + ((j1 - s) * 8 + r) * 8;
                    accA += dot8v(*(const float4*)wr, *(const float4*)(wr + 4), mf);
                }
                if (j2 >= s) {
                    const float* wr = wt + ((j2 - s) * 8 + r) * 8;
                    accB += dot8v(*(const float4*)wr, *(const float4*)(wr + 4), mf);
                }
                float wv = (j1 == s) ? (PFr[s] + accA) : ((j2 == s) ? (PFr[s] + accB) : 0.0f);
#pragma unroll
                for (int q = 0; q < 8; q++) wreg[q] = __shfl_sync(0xffffffffu, wv, q + ((s & 3) << 3));
                if (dup == 0) mb[s * 8 + r] = mr;
            }
        } else {
            asm volatile("cp.async.wait_group 0;");
        }
        __syncthreads();

        // ---- Phase D: reconstruct h + emit hw ----
        {
            float g = 0.0f;
            const size_t row0 = (size_t)b * TT + (size_t)c * 8;
            __nv_bfloat16* oh = g_hwh + row0 * KHW + i;
            __nv_bfloat16* ol = g_hwl + row0 * KHW + i;
            const float* as_ = ast + buf * 64;
            const int ab = i >> 6;
            float hlast = 0.0f;
#pragma unroll
            for (int j = 0; j < 8; j++) {
                float4 m0 = *(const float4*)(mb + j * 8);
                float4 m1 = *(const float4*)(mb + j * 8 + 4);
                float um = dot8v(m0, m1, Urow);
                g = fmaf(an, g, um);
                float h = ff[j] + g;
                float wv = h * as_[j * 8 + ab];
                __nv_bfloat16 hi = __float2bfloat16_rn(wv);
                oh[(size_t)j * KHW] = hi;
                ol[(size_t)j * KHW] = __float2bfloat16_rn(wv - __bfloat162float(hi));
                hlast = h;
            }
            hst[i] = hlast;
        }
        __syncthreads();
    }

    // write carries for next segment
    g_hcarry[b * NS + i] = hst[i];
    if (wid == 0 && lane == 0) {
#pragma unroll
        for (int q = 0; q < 8; q++) g_wcarry[b * 8 + q] = wreg[q];
    }
}

// ---------------- launch: 8-segment software pipeline across 3 streams ----------------
extern "C" void kernel_launch(void* const* d_in, const int* in_sizes, int n_in,
                              void* d_out, int out_size) {
    const float* x      = (const float*)d_in[0];
    const float* Wb     = (const float*)d_in[1];
    const float* bb     = (const float*)d_in[2];
    const float* Wdiag  = (const float*)d_in[3];
    const float* bdiag  = (const float*)d_in[4];
    const float* Woff   = (const float*)d_in[5];
    const float* boff   = (const float*)d_in[6];
    const float* Walpha = (const float*)d_in[7];
    const float* balpha = (const float*)d_in[8];
    const float* Wc     = (const float*)d_in[9];
    const float* bc     = (const float*)d_in[10];
    const float* ll     = (const float*)d_in[11];
    const float* U      = (const float*)d_in[12];
    const float* V      = (const float*)d_in[13];
    float* out = (float*)d_out;

    float *pP, *pbpack;
    __nv_bfloat16 *pxh, *pxl, *pWh, *pWl, *phwh, *phwl, *pW2h, *pW2l;
    cudaGetSymbolAddress((void**)&pP,     g_P);
    cudaGetSymbolAddress((void**)&pbpack, g_bpack);
    cudaGetSymbolAddress((void**)&pxh,    g_xh);
    cudaGetSymbolAddress((void**)&pxl,    g_xl);
    cudaGetSymbolAddress((void**)&pWh,    g_Wh);
    cudaGetSymbolAddress((void**)&pWl,    g_Wl);
    cudaGetSymbolAddress((void**)&phwh,   g_hwh);
    cudaGetSymbolAddress((void**)&phwl,   g_hwl);
    cudaGetSymbolAddress((void**)&pW2h,   g_W2h);
    cudaGetSymbolAddress((void**)&pW2l,   g_W2l);

    cudaFuncSetAttribute(gemm_bf16x3_mma, cudaFuncAttributeMaxDynamicSharedMemorySize, GSMEM);
    cudaFuncSetAttribute(scan_kernel, cudaFuncAttributeMaxDynamicSharedMemorySize, SCAN_SMEM);

    static cudaStream_t sB = nullptr, sC = nullptr;
    static cudaEvent_t evA[NSEG], evS[NSEG], evM = nullptr, evEnd = nullptr;
    static int streams_ok = -1;
    if (streams_ok < 0) {
        bool ok = (cudaStreamCreateWithFlags(&sB, cudaStreamNonBlocking) == cudaSuccess) &&
                  (cudaStreamCreateWithFlags(&sC, cudaStreamNonBlocking) == cudaSuccess);
        for (int s = 0; s < NSEG && ok; s++) {
            ok = (cudaEventCreateWithFlags(&evA[s], cudaEventDisableTiming) == cudaSuccess) &&
                 (cudaEventCreateWithFlags(&evS[s], cudaEventDisableTiming) == cudaSuccess);
        }
        ok = ok && (cudaEventCreateWithFlags(&evM, cudaEventDisableTiming) == cudaSuccess);
        ok = ok && (cudaEventCreateWithFlags(&evEnd, cudaEventDisableTiming) == cudaSuccess);
        streams_ok = ok ? 1 : 0;
    }

    const int conv_blocks = (BB * CONV_F4_PER_BATCH + 255) / 256;

    if (streams_ok == 1) {
        // head: pack2b on GEMM2's stream; pack1b+misc on stream 0; wtab on scan stream
        pack2b_kernel<<<(KHW * DM + 255) / 256, 256, 0, sC>>>(Wc, bc);
        pack1b_kernel<<<(DM * NPAD + 255) / 256, 256>>>(Wb, Wdiag, Woff, Walpha);
        misc_kernel<<<1, 1024>>>(bb, bdiag, boff, balpha, ll);
        cudaEventRecord(evM, 0);
        cudaStreamWaitEvent(sB, evM, 0);
        wtab_kernel<<<512, 128, 0, sB>>>(U, V);   // off the GEMM1 critical path

        // producer chain on stream 0: conv seg + GEMM1 seg + act seg
        for (int s = 0; s < NSEG; s++) {
            conv_x_kernel<<<conv_blocks, 256>>>((const float4*)x, (uint2*)pxh, (uint2*)pxl, s);
            gemm_bf16x3_mma<<<dim3(NPAD / 128, 16), 256, GSMEM>>>(pxh, pxl, pWh, pWl,
                                                                  pbpack, pP, DM, NPAD, s);
            act_kernel<<<32, 256>>>(s);
            cudaEventRecord(evA[s], 0);
        }
        // scan chain on stream B (wtab already ordered before the first scan)
        for (int s = 0; s < NSEG; s++) {
            cudaStreamWaitEvent(sB, evA[s], 0);
            scan_kernel<<<BB, 512, SCAN_SMEM, sB>>>(U, V, s);
            cudaEventRecord(evS[s], sB);
        }
        // GEMM2 chain on stream C
        for (int s = 0; s < NSEG; s++) {
            cudaStreamWaitEvent(sC, evS[s], 0);
            gemm_bf16x3_mma<<<dim3(DM / 128, 16), 256, GSMEM, sC>>>(phwh, phwl, pW2h, pW2l,
                                                                    nullptr, out, KHW, DM, s);
        }
        cudaEventRecord(evEnd, sC);
        cudaStreamWaitEvent(0, evEnd, 0);
    } else {
        // sequential fallback on stream 0
        pack2b_kernel<<<(KHW * DM + 255) / 256, 256>>>(Wc, bc);
        pack1b_kernel<<<(DM * NPAD + 255) / 256, 256>>>(Wb, Wdiag, Woff, Walpha);
        misc_kernel<<<1, 1024>>>(bb, bdiag, boff, balpha, ll);
        wtab_kernel<<<512, 128>>>(U, V);
        for (int s = 0; s < NSEG; s++) {
            conv_x_kernel<<<conv_blocks, 256>>>((const float4*)x, (uint2*)pxh, (uint2*)pxl, s);
            gemm_bf16x3_mma<<<dim3(NPAD / 128, 16), 256, GSMEM>>>(pxh, pxl, pWh, pWl,
                                                                  pbpack, pP, DM, NPAD, s);
            act_kernel<<<32, 256>>>(s);
        }
        for (int s = 0; s < NSEG; s++) scan_kernel<<<BB, 512, SCAN_SMEM>>>(U, V, s);
        for (int s = 0; s < NSEG; s++)
            gemm_bf16x3_mma<<<dim3(DM / 128, 16), 256, GSMEM>>>(phwh, phwl, pW2h, pW2l,
                                                                nullptr, out, KHW, DM, s);
    }
}

// round 15
// speedup vs baseline: 3.0267x; 1.1283x over previous
#include <cuda_runtime.h>
#include <cuda_bf16.h>
#include <cstdint>
#include <math.h>

#define BB 8
#define TT 2048
#define DM 1024
#define NS 512
#define NPAD 640
#define NHW 520
#define KHW 576                 // padded K for GEMM2 (18 x 32)
#define ROWS (BB*TT)            // 16384
#define NCH 256                 // chunks of 8 steps
#define NSEG 8
#define CH_PER_SEG (NCH / NSEG) // 32
#define TSEG (TT / NSEG)        // 256 rows per batch per segment

// ---------------- scratch (static device globals; no dynamic alloc) ----------------
__device__ float g_P[ROWS * NPAD];              // GEMM1 output fp32
__device__ float g_C[ROWS * 64];                // C matrices (b,t,8,8)
__device__ float g_alpha[ROWS * 8];
__device__ float g_bpack[NPAD];                 // packed biases
__device__ float g_A[NS];
__device__ float g_W8[512];                     // W_d = V^T diag(a^d) U, d=0..7, [d][r][c]
__device__ float g_hcarry[BB * NS];             // h carry between scan segments
__device__ float g_wcarry[BB * 8];              // w carry between scan segments
__device__ __nv_bfloat16 g_xh[ROWS * DM];       // x split hi/lo, [M][K]
__device__ __nv_bfloat16 g_xl[ROWS * DM];
__device__ __nv_bfloat16 g_Wh[DM * NPAD];       // Wpack [K=1024][N=640] hi/lo
__device__ __nv_bfloat16 g_Wl[DM * NPAD];
__device__ __nv_bfloat16 g_hwh[ROWS * KHW];     // [h*alpha | alpha | 0pad] hi, bf16
__device__ __nv_bfloat16 g_hwl[ROWS * KHW];     // lo residual
__device__ __nv_bfloat16 g_W2h[KHW * DM];       // W2 [K=576][N=1024] hi/lo
__device__ __nv_bfloat16 g_W2l[KHW * DM];

// ---------------- helpers ----------------
__device__ __forceinline__ uint32_t smem_u32(const void* p) {
    uint32_t a;
    asm("{ .reg .u64 t; cvta.to.shared.u64 t, %1; cvt.u32.u64 %0, t; }" : "=r"(a) : "l"(p));
    return a;
}
__device__ __forceinline__ void cp16(uint32_t dst, const void* src) {
    asm volatile("cp.async.cg.shared.global [%0], [%1], 16;" :: "r"(dst), "l"(src));
}
__device__ __forceinline__ void ldsm4(uint32_t* r, uint32_t addr) {
    asm volatile("ldmatrix.sync.aligned.m8n8.x4.shared.b16 {%0,%1,%2,%3}, [%4];"
                 : "=r"(r[0]), "=r"(r[1]), "=r"(r[2]), "=r"(r[3]) : "r"(addr));
}
__device__ __forceinline__ void ldsm4t(uint32_t* r, uint32_t addr) {
    asm volatile("ldmatrix.sync.aligned.m8n8.x4.trans.shared.b16 {%0,%1,%2,%3}, [%4];"
                 : "=r"(r[0]), "=r"(r[1]), "=r"(r[2]), "=r"(r[3]) : "r"(addr));
}
__device__ __forceinline__ void mma16816(float* d, const uint32_t* a, const uint32_t* b) {
    asm volatile(
        "mma.sync.aligned.m16n8k16.row.col.f32.bf16.bf16.f32 "
        "{%0,%1,%2,%3}, {%4,%5,%6,%7}, {%8,%9}, {%0,%1,%2,%3};\n"
        : "+f"(d[0]), "+f"(d[1]), "+f"(d[2]), "+f"(d[3])
        : "r"(a[0]), "r"(a[1]), "r"(a[2]), "r"(a[3]), "r"(b[0]), "r"(b[1]));
}
__device__ __forceinline__ uint32_t bf16x2_pack(float a, float b) {
    __nv_bfloat162 p = __nv_bfloat162(__float2bfloat16_rn(a), __float2bfloat16_rn(b));
    return *(uint32_t*)&p;
}
__device__ __forceinline__ float dot8v(float4 a0, float4 a1, const float* m) {
    float t0 = fmaf(a0.y, m[1], a0.x * m[0]);
    float t1 = fmaf(a0.w, m[3], a0.z * m[2]);
    float t2 = fmaf(a1.y, m[5], a1.x * m[4]);
    float t3 = fmaf(a1.w, m[7], a1.z * m[6]);
    return (t0 + t1) + (t2 + t3);
}

// smem stage layout (bytes): Ah | Al | Bh | Bl, padded strides for conflict-free ldmatrix
#define ASTR 40
#define BSTR 136
#define A_BYTES (128 * ASTR * 2)
#define B_BYTES (32 * BSTR * 2)
#define OFF_AH 0
#define OFF_AL A_BYTES
#define OFF_BH (2 * A_BYTES)
#define OFF_BL (2 * A_BYTES + B_BYTES)
#define STG (2 * A_BYTES + 2 * B_BYTES)
#define GSMEM (3 * STG)

// ---------------- bf16x3 mma.sync GEMM over one T-segment ----------------
__global__ void __launch_bounds__(256, 1)
gemm_bf16x3_mma(const __nv_bfloat16* __restrict__ Ah, const __nv_bfloat16* __restrict__ Al,
                const __nv_bfloat16* __restrict__ Bh, const __nv_bfloat16* __restrict__ Bl,
                const float* __restrict__ bias, float* __restrict__ D, int K, int N, int seg)
{
    extern __shared__ char smem[];
    const uint32_t sbase = smem_u32(smem);
    const int tid = threadIdx.x;
    const int lane = tid & 31, w = tid >> 5;
    const int wm = w & 1, wn = w >> 1;
    const int m0 = (blockIdx.y >> 1) * TT + seg * TSEG + (blockIdx.y & 1) * 128;
    const int n0 = blockIdx.x * 128;
    const int NC = K >> 5;

    float acc[4][4][4];
#pragma unroll
    for (int i = 0; i < 4; i++)
#pragma unroll
        for (int j = 0; j < 4; j++)
#pragma unroll
            for (int q = 0; q < 4; q++) acc[i][j][q] = 0.0f;

    const int ar = tid >> 2, as = tid & 3;
    const int br = tid >> 4, bs = tid & 15;

    auto load_stage = [&](int s, int c) {
        const uint32_t st = sbase + s * STG;
        const long kc = (long)c * 32;
        cp16(st + OFF_AH + ar * 80 + as * 16,        Ah + (long)(m0 + ar) * K + kc + as * 8);
        cp16(st + OFF_AH + (ar + 64) * 80 + as * 16, Ah + (long)(m0 + ar + 64) * K + kc + as * 8);
        cp16(st + OFF_AL + ar * 80 + as * 16,        Al + (long)(m0 + ar) * K + kc + as * 8);
        cp16(st + OFF_AL + (ar + 64) * 80 + as * 16, Al + (long)(m0 + ar + 64) * K + kc + as * 8);
        cp16(st + OFF_BH + br * 272 + bs * 16,        Bh + (kc + br) * (long)N + n0 + bs * 8);
        cp16(st + OFF_BH + (br + 16) * 272 + bs * 16, Bh + (kc + br + 16) * (long)N + n0 + bs * 8);
        cp16(st + OFF_BL + br * 272 + bs * 16,        Bl + (kc + br) * (long)N + n0 + bs * 8);
        cp16(st + OFF_BL + (br + 16) * 272 + bs * 16, Bl + (kc + br + 16) * (long)N + n0 + bs * 8);
        asm volatile("cp.async.commit_group;");
    };

    const int pre = (NC < 3) ? NC : 3;
    for (int s = 0; s < pre; s++) load_stage(s, s);

    const uint32_t a_off = (uint32_t)(((wm * 64 + (lane & 15)) * ASTR + ((lane >> 4) << 3)) * 2);
    const uint32_t b_off = (uint32_t)((((lane & 15)) * BSTR + wn * 32 + ((lane >> 4) << 3)) * 2);

    int s = 0;
    for (int kt = 0; kt < NC; ++kt) {
        const int pend = ((NC - kt) < 3 ? (NC - kt) : 3);
        if (pend == 3)      asm volatile("cp.async.wait_group 2;");
        else if (pend == 2) asm volatile("cp.async.wait_group 1;");
        else                asm volatile("cp.async.wait_group 0;");
        __syncthreads();

        const uint32_t st = sbase + s * STG;
        const uint32_t ah_b = st + OFF_AH + a_off;
        const uint32_t al_b = st + OFF_AL + a_off;
        const uint32_t bh_b = st + OFF_BH + b_off;
        const uint32_t bl_b = st + OFF_BL + b_off;

#pragma unroll
        for (int kk = 0; kk < 2; ++kk) {
            uint32_t af[4][4], lf[4][4], bf[2][4], gf[2][4];
#pragma unroll
            for (int mt = 0; mt < 4; mt++) {
                ldsm4(af[mt], ah_b + (mt * 16 * ASTR + kk * 16) * 2);
                ldsm4(lf[mt], al_b + (mt * 16 * ASTR + kk * 16) * 2);
            }
#pragma unroll
            for (int np = 0; np < 2; np++) {
                ldsm4t(bf[np], bh_b + (kk * 16 * BSTR + np * 16) * 2);
                ldsm4t(gf[np], bl_b + (kk * 16 * BSTR + np * 16) * 2);
            }
#pragma unroll
            for (int mt = 0; mt < 4; mt++) {
#pragma unroll
                for (int nt = 0; nt < 4; nt++) {
                    const uint32_t* bp = &bf[nt >> 1][(nt & 1) * 2];
                    const uint32_t* lp = &gf[nt >> 1][(nt & 1) * 2];
                    mma16816(acc[mt][nt], af[mt], bp);
                    mma16816(acc[mt][nt], lf[mt], bp);
                    mma16816(acc[mt][nt], af[mt], lp);
                }
            }
        }
        __syncthreads();
        const int cn = kt + 3;
        if (cn < NC) load_stage(s, cn);
        if (++s == 3) s = 0;
    }

    const int rb = m0 + wm * 64 + (lane >> 2);
    const int cb = n0 + wn * 32 + (lane & 3) * 2;
#pragma unroll
    for (int mt = 0; mt < 4; mt++) {
#pragma unroll
        for (int nt = 0; nt < 4; nt++) {
            const int r = rb + mt * 16;
            const int c = cb + nt * 8;
            float b0 = 0.0f, b1 = 0.0f;
            if (bias) { b0 = bias[c]; b1 = bias[c + 1]; }
            float2 o0 = make_float2(acc[mt][nt][0] + b0, acc[mt][nt][1] + b1);
            float2 o1 = make_float2(acc[mt][nt][2] + b0, acc[mt][nt][3] + b1);
            *(float2*)(D + (size_t)r * N + c) = o0;
            *(float2*)(D + (size_t)(r + 8) * N + c) = o1;
        }
    }
}

// ---------------- conversion / packing kernels ----------------
#define CONV_F4_PER_BATCH (TSEG * DM / 4)       // 65536
__global__ void conv_x_kernel(const float4* __restrict__ src, uint2* __restrict__ dh,
                              uint2* __restrict__ dl, int seg) {
    int i = blockIdx.x * blockDim.x + threadIdx.x;
    if (i >= BB * CONV_F4_PER_BATCH) return;
    int b = i / CONV_F4_PER_BATCH;
    int rem = i - b * CONV_F4_PER_BATCH;
    size_t gi = (size_t)b * (TT * DM / 4) + (size_t)seg * CONV_F4_PER_BATCH + rem;
    float4 v = src[gi];
    float hx = __bfloat162float(__float2bfloat16_rn(v.x));
    float hy = __bfloat162float(__float2bfloat16_rn(v.y));
    float hz = __bfloat162float(__float2bfloat16_rn(v.z));
    float hw = __bfloat162float(__float2bfloat16_rn(v.w));
    uint2 oh, ol;
    oh.x = bf16x2_pack(v.x, v.y); oh.y = bf16x2_pack(v.z, v.w);
    ol.x = bf16x2_pack(v.x - hx, v.y - hy); ol.y = bf16x2_pack(v.z - hz, v.w - hw);
    dh[gi] = oh; dl[gi] = ol;
}

__global__ void pack1b_kernel(const float* __restrict__ Wb, const float* __restrict__ Wdiag,
                              const float* __restrict__ Woff, const float* __restrict__ Walpha) {
    int idx = blockIdx.x * blockDim.x + threadIdx.x;
    if (idx >= DM * NPAD) return;
    int r = idx / NPAD, c = idx - r * NPAD;
    float v;
    if (c < 512)       v = Wb[r * NS + c];
    else if (c < 520)  v = Wdiag[r * 8 + (c - 512)];
    else if (c < 576)  v = Woff[r * 56 + (c - 520)];
    else if (c < 584)  v = Walpha[r * 8 + (c - 576)];
    else               v = 0.0f;
    __nv_bfloat16 h = __float2bfloat16_rn(v);
    g_Wh[idx] = h;
    g_Wl[idx] = __float2bfloat16_rn(v - __bfloat162float(h));
}

__global__ void pack2b_kernel(const float* __restrict__ Wc, const float* __restrict__ bc) {
    int idx = blockIdx.x * blockDim.x + threadIdx.x;
    if (idx >= KHW * DM) return;
    int k = idx >> 10, n = idx & 1023;
    float v;
    if (k < 512)      v = Wc[idx];
    else if (k < 520) v = bc[(size_t)(k - 512) * DM + n];
    else              v = 0.0f;
    __nv_bfloat16 h = __float2bfloat16_rn(v);
    g_W2h[idx] = h;
    g_W2l[idx] = __float2bfloat16_rn(v - __bfloat162float(h));
}

__global__ void misc_kernel(const float* __restrict__ bb, const float* __restrict__ bdiag,
                            const float* __restrict__ boff, const float* __restrict__ balpha,
                            const float* __restrict__ log_lambda) {
    int tid = threadIdx.x;
    if (tid < NS) {
        int k = tid >> 6;
        double dt = 1e-3 * exp((double)k * log(1000.0) / 7.0);
        double ll = (double)log_lambda[tid];
        double sp = log1p(exp(ll));
        g_A[tid] = (float)exp(-dt * sp);
    }
    if (tid < NPAD) {
        float v;
        if (tid < 512)       v = bb[tid];
        else if (tid < 520)  v = bdiag[tid - 512];
        else if (tid < 576)  v = boff[tid - 520];
        else if (tid < 584)  v = balpha[tid - 576];
        else                 v = 0.0f;
        g_bpack[tid] = v;
    }
}

// W_d[r][c] = sum_n V[n,r] * a_n^d * U[n,c]; one block per output, 128-thread reduce.
__global__ void __launch_bounds__(128) wtab_kernel(const float* __restrict__ Uw,
                                                   const float* __restrict__ Vw) {
    __shared__ float warpsum[4];
    const int o = blockIdx.x;               // 0..511
    const int d = o >> 6, r = (o >> 3) & 7, c = o & 7;
    const int t = threadIdx.x;
    float s = 0.0f;
#pragma unroll
    for (int q = 0; q < 4; q++) {
        int n = t + q * 128;
        float a = g_A[n];
        float p = 1.0f;
        for (int e = 0; e < d; e++) p *= a;
        s += Vw[n * 8 + r] * p * Uw[n * 8 + c];
    }
    s += __shfl_xor_sync(0xffffffffu, s, 16);
    s += __shfl_xor_sync(0xffffffffu, s, 8);
    s += __shfl_xor_sync(0xffffffffu, s, 4);
    s += __shfl_xor_sync(0xffffffffu, s, 2);
    s += __shfl_xor_sync(0xffffffffu, s, 1);
    if ((t & 31) == 0) warpsum[t >> 5] = s;
    __syncthreads();
    if (t == 0)
        g_W8[o] = (warpsum[0] + warpsum[1]) + (warpsum[2] + warpsum[3]);
}

// ---------------- activations for one T-segment ----------------
__global__ void __launch_bounds__(256) act_kernel(int seg) {
    __shared__ float s[64 * 72];
    const int row0 = (blockIdx.x >> 2) * TT + seg * TSEG + (blockIdx.x & 3) * 64;
    const int tid = threadIdx.x;
    for (int i = tid; i < 64 * 72; i += 256) {
        int r = i / 72, c = i - r * 72;
        s[i] = g_P[(size_t)(row0 + r) * NPAD + 512 + c];
    }
    __syncthreads();
    if (tid < 64) {
        const int row = row0 + tid;
        const float* v = &s[tid * 72];
        float dg[8];
#pragma unroll
        for (int i = 0; i < 8; i++) dg[i] = 1.0f / (1.0f + expf(-v[i]));
        float Cm[64];
        int m = 0;
#pragma unroll
        for (int i = 0; i < 8; i++) {
#pragma unroll
            for (int j = 0; j < 8; j++) {
                if (i == j) {
                    Cm[i * 8 + j] = dg[i];
                } else {
                    float x = v[8 + m];
                    float sp = (x > 15.0f) ? x : log1pf(expf(x));
                    Cm[i * 8 + j] = -sp;
                    m++;
                }
            }
        }
#pragma unroll
        for (int q = 0; q < 64; q++) g_C[(size_t)row * 64 + q] = Cm[q];
        float a[8], mx = v[64];
#pragma unroll
        for (int i = 1; i < 8; i++) mx = fmaxf(mx, v[64 + i]);
        float sum = 0.0f;
#pragma unroll
        for (int i = 0; i < 8; i++) { a[i] = expf(v[64 + i] - mx); sum += a[i]; }
        float inv = 1.0f / sum;
#pragma unroll
        for (int k = 0; k < 8; k++) {
            float al = a[k] * inv;
            g_alpha[(size_t)row * 8 + k] = al;
            __nv_bfloat16 h = __float2bfloat16_rn(al);
            g_hwh[(size_t)row * KHW + 512 + k] = h;
            g_hwl[(size_t)row * KHW + 512 + k] = __float2bfloat16_rn(al - __bfloat162float(h));
        }
    }
    const __nv_bfloat16 z = __float2bfloat16_rn(0.0f);
    for (int i = tid; i < 64 * 56; i += 256) {
        int r = i / 56, c = i - r * 56;
        g_hwh[(size_t)(row0 + r) * KHW + 520 + c] = z;
        g_hwl[(size_t)(row0 + r) * KHW + 520 + c] = z;
    }
}

// ---------------- chunked scan over one T-segment ----------------
// Triple-buffered inputs (prefetch 2 chunks ahead), 2 full barriers per chunk,
// warp0-private pf computation (conflict-free red layout [wid][o]), register h carry,
// register-preloaded C rows in the serial chain, double-buffered mb.
#define SCAN_SMEM (19840 * 4)
__global__ void __launch_bounds__(512, 1) scan_kernel(const float* __restrict__ Uw,
                                                      const float* __restrict__ Vw, int seg) {
    extern __shared__ float sm[];
    float* bxs  = sm;
    float* fbuf = sm + 12288;
    float* cst  = sm + 16384;
    float* ast  = sm + 17920;
    float* wt   = sm + 18112;
    float* red  = sm + 18624;
    float* pf   = sm + 19648;
    float* mb   = sm + 19712;

    const int b = blockIdx.x;
    const int i = threadIdx.x;
    const int wid = i >> 5, lane = i & 31;
    const uint32_t sbase = smem_u32(sm);
    const int cbeg = seg * CH_PER_SEG;

    float hreg = (seg == 0) ? 0.0f : g_hcarry[b * NS + i];
    wt[i] = g_W8[i];
    const int k = i & 7, g8 = i >> 3;
    float Vv[8], Urow[8];
#pragma unroll
    for (int q = 0; q < 8; q++) Vv[q] = Vw[(g8 * 8 + q) * 8 + k];
#pragma unroll
    for (int q = 0; q < 8; q++) Urow[q] = Uw[i * 8 + q];
    const float an = g_A[i];
    float wreg[8];
    if (seg == 0) {
#pragma unroll
        for (int q = 0; q < 8; q++) wreg[q] = 0.0f;
    } else {
#pragma unroll
        for (int q = 0; q < 8; q++) wreg[q] = g_wcarry[b * 8 + q];
    }

    const float* bxg = g_P + (size_t)b * TT * NPAD;
    const float* cg  = g_C + (size_t)b * TT * 64;
    const float* ag  = g_alpha + (size_t)b * TT * 8;
    const size_t t0 = (size_t)cbeg * 8;

    // prefill chunks 0 and 1 (buffers 0,1)
    for (int g = 0; g < 2; g++) {
        const size_t tb = t0 + (size_t)g * 8;
        for (int idx = i; idx < 1024; idx += 512) {
            int t = idx >> 7, sg = idx & 127;
            cp16(sbase + (uint32_t)(g * 4096 + t * 512 + sg * 4) * 4, bxg + (tb + t) * NPAD + sg * 4);
        }
        for (int idx = i; idx < 128; idx += 512) {
            int t = idx >> 4, sg = idx & 15;
            cp16(sbase + (uint32_t)(16384 + g * 512 + t * 64 + sg * 4) * 4, cg + (tb + t) * 64 + sg * 4);
        }
        if (i < 16) {
            int t = i >> 1, sg = i & 1;
            cp16(sbase + (uint32_t)(17920 + g * 64 + t * 8 + sg * 4) * 4, ag + (tb + t) * 8 + sg * 4);
        }
        asm volatile("cp.async.commit_group;");
    }
    asm volatile("cp.async.wait_group 0;");
    __syncthreads();

    float ff[8];
    for (int cc = 0; cc < CH_PER_SEG; ++cc) {
        const int buf = cc % 3;
        // ---- Phase A: thread-local f recurrence ----
        float fp = hreg;
#pragma unroll
        for (int j = 0; j < 8; j++) {
            fp = fmaf(an, fp, bxs[buf * 4096 + j * 512 + i]);
            ff[j] = fp;
            fbuf[j * 512 + i] = fp;
        }
        __syncwarp();           // fbuf exchange is within-warp only

        // ---- Phase B: PF partials, warp combine, red[wid][o] ----
        float pv[8];
        {
            const float* fb = fbuf + g8 * 8;
#pragma unroll
            for (int j = 0; j < 8; j++) {
                float4 f0 = *(const float4*)(fb + j * 512);
                float4 f1 = *(const float4*)(fb + j * 512 + 4);
                pv[j] = dot8v(f0, f1, Vv);
            }
        }
#pragma unroll
        for (int j = 0; j < 8; j++) {
            pv[j] += __shfl_xor_sync(0xffffffffu, pv[j], 8);
            pv[j] += __shfl_xor_sync(0xffffffffu, pv[j], 16);
        }
        if (lane < 8) {
#pragma unroll
            for (int j = 0; j < 8; j++) red[wid * 64 + j * 8 + lane] = pv[j];
        }
        __syncthreads();        // barrier 1

        // prefetch chunk cc+2 (threads >=128 only)
        bool issued = false;
        if (i >= 128 && cc + 2 < CH_PER_SEG) {
            const int nb = (cc + 2) % 3;
            const size_t tb = t0 + (size_t)(cc + 2) * 8;
            const int tt = i - 128;
            for (int idx = tt; idx < 1024; idx += 384) {
                int t = idx >> 7, sg = idx & 127;
                cp16(sbase + (uint32_t)(nb * 4096 + t * 512 + sg * 4) * 4,
                     bxg + (tb + t) * NPAD + sg * 4);
            }
            for (int idx = tt; idx < 128; idx += 384) {
                int t = idx >> 4, sg = idx & 15;
                cp16(sbase + (uint32_t)(16384 + nb * 512 + t * 64 + sg * 4) * 4,
                     cg + (tb + t) * 64 + sg * 4);
            }
            if (tt < 16) {
                int t = tt >> 1, sg = tt & 1;
                cp16(sbase + (uint32_t)(17920 + nb * 64 + t * 8 + sg * 4) * 4,
                     ag + (tb + t) * 8 + sg * 4);
            }
            asm volatile("cp.async.commit_group;");
            issued = true;
        }

        // ---- Phase C: warp0 computes pf then runs the serial 8-dim chain ----
        if (wid == 0) {
#pragma unroll
            for (int q = 0; q < 2; q++) {
                const int o = lane + q * 32;
                float s0 = 0.0f, s1 = 0.0f, s2 = 0.0f, s3 = 0.0f;
#pragma unroll
                for (int w4 = 0; w4 < 4; w4++) {
                    s0 += red[(w4 * 4 + 0) * 64 + o];
                    s1 += red[(w4 * 4 + 1) * 64 + o];
                    s2 += red[(w4 * 4 + 2) * 64 + o];
                    s3 += red[(w4 * 4 + 3) * 64 + o];
                }
                pf[o] = (s0 + s1) + (s2 + s3);
            }
            __syncwarp();

            const int r = lane & 7, dup = lane >> 3;
            const int j1 = dup, j2 = dup + 4;
            float PFr[8];
#pragma unroll
            for (int s = 0; s < 8; s++) PFr[s] = pf[s * 8 + r];
            const float* cb = cst + buf * 512;
            float4 c0 = *(const float4*)(cb + r * 8);
            float4 c1 = *(const float4*)(cb + r * 8 + 4);
            float accA = 0.0f, accB = 0.0f;
            float* mbw = mb + (cc & 1) * 64;
#pragma unroll
            for (int s = 0; s < 8; s++) {
                float4 n0, n1;
                if (s < 7) {
                    n0 = *(const float4*)(cb + (s + 1) * 64 + r * 8);
                    n1 = *(const float4*)(cb + (s + 1) * 64 + r * 8 + 4);
                }
                float mr = dot8v(c0, c1, wreg);
                float mf[8];
#pragma unroll
                for (int q = 0; q < 8; q++) mf[q] = __shfl_sync(0xffffffffu, mr, q + (dup << 3));
                if (j1 >= s) {
                    const float* wr = wt + (j1 - s) * 64 + r * 8;
                    accA += dot8v(*(const float4*)wr, *(const float4*)(wr + 4), mf);
                }
                if (j2 >= s) {
                    const float* wr = wt + (j2 - s) * 64 + r * 8;
                    accB += dot8v(*(const float4*)wr, *(const float4*)(wr + 4), mf);
                }
                float wv = (j1 == s) ? (PFr[s] + accA) : ((j2 == s) ? (PFr[s] + accB) : 0.0f);
#pragma unroll
                for (int q = 0; q < 8; q++) wreg[q] = __shfl_sync(0xffffffffu, wv, q + ((s & 3) << 3));
                if (dup == 0) mbw[s * 8 + r] = mr;
                c0 = n0; c1 = n1;
            }
        } else if (i >= 128) {
            if (issued) asm volatile("cp.async.wait_group 1;");
            else        asm volatile("cp.async.wait_group 0;");
        }
        __syncthreads();        // barrier 2

        // ---- Phase D: reconstruct h + emit hw (no trailing barrier) ----
        {
            float g = 0.0f;
            const size_t row0 = (size_t)b * TT + (size_t)(cbeg + cc) * 8;
            __nv_bfloat16* oh = g_hwh + row0 * KHW + i;
            __nv_bfloat16* ol = g_hwl + row0 * KHW + i;
            const float* mbr = mb + (cc & 1) * 64;
            const float* as_ = ast + buf * 64;
            const int ab = i >> 6;
#pragma unroll
            for (int j = 0; j < 8; j++) {
                float4 m0 = *(const float4*)(mbr + j * 8);
                float4 m1 = *(const float4*)(mbr + j * 8 + 4);
                float um = dot8v(m0, m1, Urow);
                g = fmaf(an, g, um);
                float h = ff[j] + g;
                float wv = h * as_[j * 8 + ab];
                __nv_bfloat16 hi = __float2bfloat16_rn(wv);
                oh[(size_t)j * KHW] = hi;
                ol[(size_t)j * KHW] = __float2bfloat16_rn(wv - __bfloat162float(hi));
                if (j == 7) hreg = h;
            }
        }
    }

    // write carries for next segment
    g_hcarry[b * NS + i] = hreg;
    if (wid == 0 && lane == 0) {
#pragma unroll
        for (int q = 0; q < 8; q++) g_wcarry[b * 8 + q] = wreg[q];
    }
}

// ---------------- launch: 8-segment pipeline, 3 streams (R12 topology) ----------------
extern "C" void kernel_launch(void* const* d_in, const int* in_sizes, int n_in,
                              void* d_out, int out_size) {
    const float* x      = (const float*)d_in[0];
    const float* Wb     = (const float*)d_in[1];
    const float* bb     = (const float*)d_in[2];
    const float* Wdiag  = (const float*)d_in[3];
    const float* bdiag  = (const float*)d_in[4];
    const float* Woff   = (const float*)d_in[5];
    const float* boff   = (const float*)d_in[6];
    const float* Walpha = (const float*)d_in[7];
    const float* balpha = (const float*)d_in[8];
    const float* Wc     = (const float*)d_in[9];
    const float* bc     = (const float*)d_in[10];
    const float* ll     = (const float*)d_in[11];
    const float* U      = (const float*)d_in[12];
    const float* V      = (const float*)d_in[13];
    float* out = (float*)d_out;

    float *pP, *pbpack;
    __nv_bfloat16 *pxh, *pxl, *pWh, *pWl, *phwh, *phwl, *pW2h, *pW2l;
    cudaGetSymbolAddress((void**)&pP,     g_P);
    cudaGetSymbolAddress((void**)&pbpack, g_bpack);
    cudaGetSymbolAddress((void**)&pxh,    g_xh);
    cudaGetSymbolAddress((void**)&pxl,    g_xl);
    cudaGetSymbolAddress((void**)&pWh,    g_Wh);
    cudaGetSymbolAddress((void**)&pWl,    g_Wl);
    cudaGetSymbolAddress((void**)&phwh,   g_hwh);
    cudaGetSymbolAddress((void**)&phwl,   g_hwl);
    cudaGetSymbolAddress((void**)&pW2h,   g_W2h);
    cudaGetSymbolAddress((void**)&pW2l,   g_W2l);

    cudaFuncSetAttribute(gemm_bf16x3_mma, cudaFuncAttributeMaxDynamicSharedMemorySize, GSMEM);
    cudaFuncSetAttribute(scan_kernel, cudaFuncAttributeMaxDynamicSharedMemorySize, SCAN_SMEM);

    static cudaStream_t sB = nullptr, sC = nullptr;
    static cudaEvent_t evA[NSEG], evS[NSEG], evM = nullptr, evEnd = nullptr;
    static int streams_ok = -1;
    if (streams_ok < 0) {
        bool ok = (cudaStreamCreateWithFlags(&sB, cudaStreamNonBlocking) == cudaSuccess) &&
                  (cudaStreamCreateWithFlags(&sC, cudaStreamNonBlocking) == cudaSuccess);
        for (int s = 0; s < NSEG && ok; s++) {
            ok = (cudaEventCreateWithFlags(&evA[s], cudaEventDisableTiming) == cudaSuccess) &&
                 (cudaEventCreateWithFlags(&evS[s], cudaEventDisableTiming) == cudaSuccess);
        }
        ok = ok && (cudaEventCreateWithFlags(&evM, cudaEventDisableTiming) == cudaSuccess);
        ok = ok && (cudaEventCreateWithFlags(&evEnd, cudaEventDisableTiming) == cudaSuccess);
        streams_ok = ok ? 1 : 0;
    }

    const int conv_blocks = (BB * CONV_F4_PER_BATCH + 255) / 256;

    if (streams_ok == 1) {
        // head: pack2b on GEMM2's stream; pack1b+misc on stream 0; wtab on scan stream
        pack2b_kernel<<<(KHW * DM + 255) / 256, 256, 0, sC>>>(Wc, bc);
        pack1b_kernel<<<(DM * NPAD + 255) / 256, 256>>>(Wb, Wdiag, Woff, Walpha);
        misc_kernel<<<1, 1024>>>(bb, bdiag, boff, balpha, ll);
        cudaEventRecord(evM, 0);
        cudaStreamWaitEvent(sB, evM, 0);
        wtab_kernel<<<512, 128, 0, sB>>>(U, V);   // off the GEMM1 critical path

        // producer chain on stream 0: conv seg + GEMM1 seg + act seg
        for (int s = 0; s < NSEG; s++) {
            conv_x_kernel<<<conv_blocks, 256>>>((const float4*)x, (uint2*)pxh, (uint2*)pxl, s);
            gemm_bf16x3_mma<<<dim3(NPAD / 128, 16), 256, GSMEM>>>(pxh, pxl, pWh, pWl,
                                                                  pbpack, pP, DM, NPAD, s);
            act_kernel<<<32, 256>>>(s);
            cudaEventRecord(evA[s], 0);
        }
        // scan chain on stream B
        for (int s = 0; s < NSEG; s++) {
            cudaStreamWaitEvent(sB, evA[s], 0);
            scan_kernel<<<BB, 512, SCAN_SMEM, sB>>>(U, V, s);
            cudaEventRecord(evS[s], sB);
        }
        // GEMM2 chain on stream C
        for (int s = 0; s < NSEG; s++) {
            cudaStreamWaitEvent(sC, evS[s], 0);
            gemm_bf16x3_mma<<<dim3(DM / 128, 16), 256, GSMEM, sC>>>(phwh, phwl, pW2h, pW2l,
                                                                    nullptr, out, KHW, DM, s);
        }
        cudaEventRecord(evEnd, sC);
        cudaStreamWaitEvent(0, evEnd, 0);
    } else {
        // sequential fallback on stream 0
        pack2b_kernel<<<(KHW * DM + 255) / 256, 256>>>(Wc, bc);
        pack1b_kernel<<<(DM * NPAD + 255) / 256, 256>>>(Wb, Wdiag, Woff, Walpha);
        misc_kernel<<<1, 1024>>>(bb, bdiag, boff, balpha, ll);
        wtab_kernel<<<512, 128>>>(U, V);
        for (int s = 0; s < NSEG; s++) {
            conv_x_kernel<<<conv_blocks, 256>>>((const float4*)x, (uint2*)pxh, (uint2*)pxl, s);
            gemm_bf16x3_mma<<<dim3(NPAD / 128, 16), 256, GSMEM>>>(pxh, pxl, pWh, pWl,
                                                                  pbpack, pP, DM, NPAD, s);
            act_kernel<<<32, 256>>>(s);
        }
        for (int s = 0; s < NSEG; s++) scan_kernel<<<BB, 512, SCAN_SMEM>>>(U, V, s);
        for (int s = 0; s < NSEG; s++)
            gemm_bf16x3_mma<<<dim3(DM / 128, 16), 256, GSMEM>>>(phwh, phwl, pW2h, pW2l,
                                                                nullptr, out, KHW, DM, s);
    }
}